// round 9
// baseline (speedup 1.0000x reference)
#include <cuda_runtime.h>
#include <cuda_bf16.h>

static const int NN = 200000;
static const int NE = 3200000;
static const int NG = 400;
static const int NB = (NN + 1023) / 1024;  // 196 scan blocks

// Scratch (device globals; no runtime allocation allowed)
__device__ int   g_degi[NN];
__device__ int   g_off[NN + 1];
__device__ int   g_cursor[NN];
__device__ int   g_csr[NE];
__device__ int   g_bsum[256];
__device__ float g_bufB[(size_t)NN * 48];
__device__ float g_z[(size_t)NN * 48];      // projected neighbor features
__device__ float g_s[(size_t)NN * 48];      // self-projection + bias
__device__ float g_agg[(size_t)NN * 32];    // layer-0 raw-feature aggregate
__device__ float g_cnt[NG];

// ---------------------------------------------------------------------------
__global__ void k_degree(const int* __restrict__ dst) {
    int i = blockIdx.x * blockDim.x + threadIdx.x;
    if (i >= NE / 4) return;
    int4 d = reinterpret_cast<const int4*>(dst)[i];
    atomicAdd(&g_degi[d.x], 1);
    atomicAdd(&g_degi[d.y], 1);
    atomicAdd(&g_degi[d.z], 1);
    atomicAdd(&g_degi[d.w], 1);
}

// ---- parallel exclusive scan of g_degi -> g_off ----
__global__ void k_scan1() {
    __shared__ int sh[1024];
    int t = threadIdx.x;
    int j = blockIdx.x * 1024 + t;
    sh[t] = (j < NN) ? g_degi[j] : 0;
    __syncthreads();
    for (int d = 512; d > 0; d >>= 1) {
        if (t < d) sh[t] += sh[t + d];
        __syncthreads();
    }
    if (t == 0) g_bsum[blockIdx.x] = sh[0];
}

__global__ void k_scan2() {
    __shared__ int sh[256];
    int t = threadIdx.x;
    int v = (t < NB) ? g_bsum[t] : 0;
    sh[t] = v;
    __syncthreads();
    for (int d = 1; d < 256; d <<= 1) {
        int x = (t >= d) ? sh[t - d] : 0;
        __syncthreads();
        sh[t] += x;
        __syncthreads();
    }
    g_bsum[t] = sh[t] - v;  // exclusive
}

__global__ void k_scan3() {
    __shared__ int sh[1024];
    int t = threadIdx.x;
    int j = blockIdx.x * 1024 + t;
    int v = (j < NN) ? g_degi[j] : 0;
    sh[t] = v;
    __syncthreads();
    for (int d = 1; d < 1024; d <<= 1) {
        int x = (t >= d) ? sh[t - d] : 0;
        __syncthreads();
        sh[t] += x;
        __syncthreads();
    }
    int excl = sh[t] - v + g_bsum[blockIdx.x];
    if (j < NN) {
        g_off[j] = excl;
        g_cursor[j] = excl;
    }
    if (j == NN - 1) g_off[NN] = excl + v;
}

__global__ void k_build(const int* __restrict__ src, const int* __restrict__ dst) {
    int i = blockIdx.x * blockDim.x + threadIdx.x;
    if (i >= NE / 2) return;
    int2 s2 = reinterpret_cast<const int2*>(src)[i];
    int2 d2 = reinterpret_cast<const int2*>(dst)[i];
    int p0 = atomicAdd(&g_cursor[d2.x], 1);
    g_csr[p0] = s2.x;
    int p1 = atomicAdd(&g_cursor[d2.y], 1);
    g_csr[p1] = s2.y;
}

// ---------------------------------------------------------------------------
// plain gather (layer 0): agg[v] = sum feat[nbr] / max(deg,1). Warp per node.
template <int DIM, int SLOTS>
__global__ void k_gather4(const float* __restrict__ z, float* __restrict__ agg) {
    constexpr int F4L = 32 / SLOTS;
    constexpr int NF4 = DIM / 4;
    int gt = blockIdx.x * blockDim.x + threadIdx.x;
    int v = gt >> 5;
    if (v >= NN) return;
    int lane = gt & 31;
    int slot = lane / F4L;
    int f4 = lane % F4L;
    bool act = (f4 < NF4);

    int beg = g_off[v];
    int end = g_off[v + 1];
    float4 acc = make_float4(0.f, 0.f, 0.f, 0.f);

    int e = beg;
    for (; e + 4 * SLOTS <= end; e += 4 * SLOTS) {
        int s0 = g_csr[e + slot];
        int s1 = g_csr[e + SLOTS + slot];
        int s2 = g_csr[e + 2 * SLOTS + slot];
        int s3 = g_csr[e + 3 * SLOTS + slot];
        if (act) {
            float4 t0 = __ldg(reinterpret_cast<const float4*>(z + (size_t)s0 * DIM) + f4);
            float4 t1 = __ldg(reinterpret_cast<const float4*>(z + (size_t)s1 * DIM) + f4);
            float4 t2 = __ldg(reinterpret_cast<const float4*>(z + (size_t)s2 * DIM) + f4);
            float4 t3 = __ldg(reinterpret_cast<const float4*>(z + (size_t)s3 * DIM) + f4);
            acc.x += (t0.x + t1.x) + (t2.x + t3.x);
            acc.y += (t0.y + t1.y) + (t2.y + t3.y);
            acc.z += (t0.z + t1.z) + (t2.z + t3.z);
            acc.w += (t0.w + t1.w) + (t2.w + t3.w);
        }
    }
    for (; e < end; e += SLOTS) {
        int myE = e + slot;
        if (myE < end && act) {
            int s0 = g_csr[myE];
            float4 t0 = __ldg(reinterpret_cast<const float4*>(z + (size_t)s0 * DIM) + f4);
            acc.x += t0.x; acc.y += t0.y; acc.z += t0.z; acc.w += t0.w;
        }
    }
#pragma unroll
    for (int m = F4L; m < 32; m <<= 1) {
        acc.x += __shfl_xor_sync(0xFFFFFFFFu, acc.x, m);
        acc.y += __shfl_xor_sync(0xFFFFFFFFu, acc.y, m);
        acc.z += __shfl_xor_sync(0xFFFFFFFFu, acc.z, m);
        acc.w += __shfl_xor_sync(0xFFFFFFFFu, acc.w, m);
    }
    float inv = 1.0f / fmaxf((float)(end - beg), 1.0f);
    if (slot == 0 && act) {
        float4 o = make_float4(acc.x * inv, acc.y * inv, acc.z * inv, acc.w * inv);
        reinterpret_cast<float4*>(agg + (size_t)v * DIM)[f4] = o;
    }
}

// ---------------------------------------------------------------------------
// Fused layer-0 projection + layer-1 z/s projection (all node-local math):
//   h0 = relu( feat@Ws0 + agg@Wn0 + b0 )   (kept in smem, never hits DRAM)
//   z1 = h0@Wn1 ; s1 = h0@Ws1 + b1
// Block = 64 nodes. Phase 1: (oq in 0..31) x (nodegroup in 0..7), NV=8.
// Phase 2: 64 nodes x 12 oq = 768 items over 3 iterations.
__global__ void __launch_bounds__(256) k_sage0zs(
    const float* __restrict__ feat, const float* __restrict__ agg,
    const float* __restrict__ Ws0, const float* __restrict__ Wn0,
    const float* __restrict__ b0,
    const float* __restrict__ Wn1, const float* __restrict__ Ws1,
    const float* __restrict__ b1,
    float* __restrict__ z, float* __restrict__ s) {
    __shared__ float smH[64 * 136];  // 136-float row pitch: 16B-aligned, bank-shifted
    int nbase = blockIdx.x * 64;
    int t = threadIdx.x;

    // ---- phase 1: h0 rows into smem ----
    {
        int oq = t & 31;   // float4 column group of 128-dim output
        int ngrp = t >> 5; // 0..7, nodes ngrp*8 .. ngrp*8+7
        float4 b4 = __ldg(reinterpret_cast<const float4*>(b0) + oq);
        float4 acc[8];
#pragma unroll
        for (int i = 0; i < 8; i++) acc[i] = b4;

#pragma unroll
        for (int k = 0; k < 32; k += 4) {
            float4 ws0 = __ldg(reinterpret_cast<const float4*>(Ws0 + (size_t)(k + 0) * 128) + oq);
            float4 ws1 = __ldg(reinterpret_cast<const float4*>(Ws0 + (size_t)(k + 1) * 128) + oq);
            float4 ws2 = __ldg(reinterpret_cast<const float4*>(Ws0 + (size_t)(k + 2) * 128) + oq);
            float4 ws3 = __ldg(reinterpret_cast<const float4*>(Ws0 + (size_t)(k + 3) * 128) + oq);
            float4 wn0 = __ldg(reinterpret_cast<const float4*>(Wn0 + (size_t)(k + 0) * 128) + oq);
            float4 wn1 = __ldg(reinterpret_cast<const float4*>(Wn0 + (size_t)(k + 1) * 128) + oq);
            float4 wn2 = __ldg(reinterpret_cast<const float4*>(Wn0 + (size_t)(k + 2) * 128) + oq);
            float4 wn3 = __ldg(reinterpret_cast<const float4*>(Wn0 + (size_t)(k + 3) * 128) + oq);
#pragma unroll
            for (int i = 0; i < 8; i++) {
                int node = min(nbase + ngrp * 8 + i, NN - 1);
                float4 hv = __ldg(reinterpret_cast<const float4*>(feat + (size_t)node * 32) + (k >> 2));
                float4 av = __ldg(reinterpret_cast<const float4*>(agg + (size_t)node * 32) + (k >> 2));
                acc[i].x = fmaf(hv.x, ws0.x, fmaf(hv.y, ws1.x, fmaf(hv.z, ws2.x, fmaf(hv.w, ws3.x, acc[i].x))));
                acc[i].y = fmaf(hv.x, ws0.y, fmaf(hv.y, ws1.y, fmaf(hv.z, ws2.y, fmaf(hv.w, ws3.y, acc[i].y))));
                acc[i].z = fmaf(hv.x, ws0.z, fmaf(hv.y, ws1.z, fmaf(hv.z, ws2.z, fmaf(hv.w, ws3.z, acc[i].z))));
                acc[i].w = fmaf(hv.x, ws0.w, fmaf(hv.y, ws1.w, fmaf(hv.z, ws2.w, fmaf(hv.w, ws3.w, acc[i].w))));
                acc[i].x = fmaf(av.x, wn0.x, fmaf(av.y, wn1.x, fmaf(av.z, wn2.x, fmaf(av.w, wn3.x, acc[i].x))));
                acc[i].y = fmaf(av.x, wn0.y, fmaf(av.y, wn1.y, fmaf(av.z, wn2.y, fmaf(av.w, wn3.y, acc[i].y))));
                acc[i].z = fmaf(av.x, wn0.z, fmaf(av.y, wn1.z, fmaf(av.z, wn2.z, fmaf(av.w, wn3.z, acc[i].z))));
                acc[i].w = fmaf(av.x, wn0.w, fmaf(av.y, wn1.w, fmaf(av.z, wn2.w, fmaf(av.w, wn3.w, acc[i].w))));
            }
        }
#pragma unroll
        for (int i = 0; i < 8; i++) {
            int nl = ngrp * 8 + i;
            float4 r = make_float4(fmaxf(acc[i].x, 0.f), fmaxf(acc[i].y, 0.f),
                                   fmaxf(acc[i].z, 0.f), fmaxf(acc[i].w, 0.f));
            *reinterpret_cast<float4*>(&smH[nl * 136 + oq * 4]) = r;
        }
    }
    __syncthreads();

    // ---- phase 2: z1/s1 from smem h0 rows ----
#pragma unroll
    for (int it = 0; it < 3; it++) {
        int i = t + it * 256;
        int oq = i % 12;
        int nl = i / 12;  // 0..63
        int node = nbase + nl;
        float4 b4 = __ldg(reinterpret_cast<const float4*>(b1) + oq);
        float4 az = make_float4(0.f, 0.f, 0.f, 0.f);
        float4 as = b4;
#pragma unroll
        for (int k = 0; k < 128; k += 4) {
            float4 n0w = __ldg(reinterpret_cast<const float4*>(Wn1 + (size_t)(k + 0) * 48) + oq);
            float4 n1w = __ldg(reinterpret_cast<const float4*>(Wn1 + (size_t)(k + 1) * 48) + oq);
            float4 n2w = __ldg(reinterpret_cast<const float4*>(Wn1 + (size_t)(k + 2) * 48) + oq);
            float4 n3w = __ldg(reinterpret_cast<const float4*>(Wn1 + (size_t)(k + 3) * 48) + oq);
            float4 s0w = __ldg(reinterpret_cast<const float4*>(Ws1 + (size_t)(k + 0) * 48) + oq);
            float4 s1w = __ldg(reinterpret_cast<const float4*>(Ws1 + (size_t)(k + 1) * 48) + oq);
            float4 s2w = __ldg(reinterpret_cast<const float4*>(Ws1 + (size_t)(k + 2) * 48) + oq);
            float4 s3w = __ldg(reinterpret_cast<const float4*>(Ws1 + (size_t)(k + 3) * 48) + oq);
            float4 hv = *reinterpret_cast<const float4*>(&smH[nl * 136 + k]);
            az.x = fmaf(hv.x, n0w.x, fmaf(hv.y, n1w.x, fmaf(hv.z, n2w.x, fmaf(hv.w, n3w.x, az.x))));
            az.y = fmaf(hv.x, n0w.y, fmaf(hv.y, n1w.y, fmaf(hv.z, n2w.y, fmaf(hv.w, n3w.y, az.y))));
            az.z = fmaf(hv.x, n0w.z, fmaf(hv.y, n1w.z, fmaf(hv.z, n2w.z, fmaf(hv.w, n3w.z, az.z))));
            az.w = fmaf(hv.x, n0w.w, fmaf(hv.y, n1w.w, fmaf(hv.z, n2w.w, fmaf(hv.w, n3w.w, az.w))));
            as.x = fmaf(hv.x, s0w.x, fmaf(hv.y, s1w.x, fmaf(hv.z, s2w.x, fmaf(hv.w, s3w.x, as.x))));
            as.y = fmaf(hv.x, s0w.y, fmaf(hv.y, s1w.y, fmaf(hv.z, s2w.y, fmaf(hv.w, s3w.y, as.y))));
            as.z = fmaf(hv.x, s0w.z, fmaf(hv.y, s1w.z, fmaf(hv.z, s2w.z, fmaf(hv.w, s3w.z, as.z))));
            as.w = fmaf(hv.x, s0w.w, fmaf(hv.y, s1w.w, fmaf(hv.z, s2w.w, fmaf(hv.w, s3w.w, as.w))));
        }
        if (node < NN) {
            reinterpret_cast<float4*>(z + (size_t)node * 48)[oq] = az;
            reinterpret_cast<float4*>(s + (size_t)node * 48)[oq] = as;
        }
    }
}

// ---------------------------------------------------------------------------
// fused gather (layers 1,2): out[v] = act( s[v] + sum z[nbr]/max(deg,1) )
template <int DIM, int SLOTS, bool RELU>
__global__ void k_gatherF(const float* __restrict__ z, const float* __restrict__ s,
                          float* __restrict__ out) {
    constexpr int F4L = 32 / SLOTS;
    constexpr int NF4 = DIM / 4;
    int gt = blockIdx.x * blockDim.x + threadIdx.x;
    int v = gt >> 5;
    if (v >= NN) return;
    int lane = gt & 31;
    int slot = lane / F4L;
    int f4 = lane % F4L;
    bool act = (f4 < NF4);

    int beg = g_off[v];
    int end = g_off[v + 1];
    float4 acc = make_float4(0.f, 0.f, 0.f, 0.f);

    int e = beg;
    for (; e + 4 * SLOTS <= end; e += 4 * SLOTS) {
        int s0 = g_csr[e + slot];
        int s1 = g_csr[e + SLOTS + slot];
        int s2 = g_csr[e + 2 * SLOTS + slot];
        int s3 = g_csr[e + 3 * SLOTS + slot];
        if (act) {
            float4 t0 = __ldg(reinterpret_cast<const float4*>(z + (size_t)s0 * DIM) + f4);
            float4 t1 = __ldg(reinterpret_cast<const float4*>(z + (size_t)s1 * DIM) + f4);
            float4 t2 = __ldg(reinterpret_cast<const float4*>(z + (size_t)s2 * DIM) + f4);
            float4 t3 = __ldg(reinterpret_cast<const float4*>(z + (size_t)s3 * DIM) + f4);
            acc.x += (t0.x + t1.x) + (t2.x + t3.x);
            acc.y += (t0.y + t1.y) + (t2.y + t3.y);
            acc.z += (t0.z + t1.z) + (t2.z + t3.z);
            acc.w += (t0.w + t1.w) + (t2.w + t3.w);
        }
    }
    for (; e < end; e += SLOTS) {
        int myE = e + slot;
        if (myE < end && act) {
            int s0 = g_csr[myE];
            float4 t0 = __ldg(reinterpret_cast<const float4*>(z + (size_t)s0 * DIM) + f4);
            acc.x += t0.x; acc.y += t0.y; acc.z += t0.z; acc.w += t0.w;
        }
    }
#pragma unroll
    for (int m = F4L; m < 32; m <<= 1) {
        acc.x += __shfl_xor_sync(0xFFFFFFFFu, acc.x, m);
        acc.y += __shfl_xor_sync(0xFFFFFFFFu, acc.y, m);
        acc.z += __shfl_xor_sync(0xFFFFFFFFu, acc.z, m);
        acc.w += __shfl_xor_sync(0xFFFFFFFFu, acc.w, m);
    }
    float inv = 1.0f / fmaxf((float)(end - beg), 1.0f);
    if (slot == 0 && act) {
        float4 sv = __ldg(reinterpret_cast<const float4*>(s + (size_t)v * DIM) + f4);
        float4 o = make_float4(sv.x + acc.x * inv, sv.y + acc.y * inv,
                               sv.z + acc.z * inv, sv.w + acc.w * inv);
        if (RELU) {
            o.x = fmaxf(o.x, 0.f); o.y = fmaxf(o.y, 0.f);
            o.z = fmaxf(o.z, 0.f); o.w = fmaxf(o.w, 0.f);
        }
        reinterpret_cast<float4*>(out + (size_t)v * DIM)[f4] = o;
    }
}

// fused scalar gather for DIM=5 (layer 3, no relu)
__global__ void k_gatherF5(const float* __restrict__ z, const float* __restrict__ s,
                           float* __restrict__ out) {
    constexpr int DIM = 5;
    int gt = blockIdx.x * blockDim.x + threadIdx.x;
    int v = gt >> 5;
    if (v >= NN) return;
    int lane = gt & 31;
    int slot = lane >> 3;
    int f = lane & 7;
    bool act = (f < DIM);

    int beg = g_off[v];
    int end = g_off[v + 1];
    float acc = 0.0f;
    int e = beg;
    for (; e + 8 <= end; e += 8) {
        int s0 = g_csr[e + slot];
        int s1 = g_csr[e + 4 + slot];
        if (act) acc += z[(size_t)s0 * DIM + f] + z[(size_t)s1 * DIM + f];
    }
    for (; e < end; e += 4) {
        int myE = e + slot;
        if (myE < end && act) acc += z[(size_t)g_csr[myE] * DIM + f];
    }
#pragma unroll
    for (int m = 8; m < 32; m <<= 1) acc += __shfl_xor_sync(0xFFFFFFFFu, acc, m);
    float inv = 1.0f / fmaxf((float)(end - beg), 1.0f);
    if (slot == 0 && act)
        out[(size_t)v * DIM + f] = s[(size_t)v * DIM + f] + acc * inv;
}

// ---------------------------------------------------------------------------
// Combined z/s projection: z = h@Wn ; s = h@Ws + b. Thread -> float4 x NV nodes.
template <int DIN, int DOUT, int NV>
__global__ void k_zs(const float* __restrict__ h, const float* __restrict__ Wn,
                     const float* __restrict__ Ws, const float* __restrict__ bias,
                     float* __restrict__ z, float* __restrict__ s) {
    constexpr int OG = DOUT / 4;
    long long t = (long long)blockIdx.x * blockDim.x + threadIdx.x;
    int oq = (int)(t % OG);
    long long ng = t / OG;
    int n0 = (int)(ng * NV);
    if (n0 >= NN) return;

    float4 b4 = __ldg(reinterpret_cast<const float4*>(bias) + oq);
    float4 az[NV], as[NV];
#pragma unroll
    for (int i = 0; i < NV; i++) {
        az[i] = make_float4(0.f, 0.f, 0.f, 0.f);
        as[i] = b4;
    }

#pragma unroll
    for (int k = 0; k < DIN; k += 4) {
        float4 n0w = __ldg(reinterpret_cast<const float4*>(Wn + (size_t)(k + 0) * DOUT) + oq);
        float4 n1w = __ldg(reinterpret_cast<const float4*>(Wn + (size_t)(k + 1) * DOUT) + oq);
        float4 n2w = __ldg(reinterpret_cast<const float4*>(Wn + (size_t)(k + 2) * DOUT) + oq);
        float4 n3w = __ldg(reinterpret_cast<const float4*>(Wn + (size_t)(k + 3) * DOUT) + oq);
        float4 s0w = __ldg(reinterpret_cast<const float4*>(Ws + (size_t)(k + 0) * DOUT) + oq);
        float4 s1w = __ldg(reinterpret_cast<const float4*>(Ws + (size_t)(k + 1) * DOUT) + oq);
        float4 s2w = __ldg(reinterpret_cast<const float4*>(Ws + (size_t)(k + 2) * DOUT) + oq);
        float4 s3w = __ldg(reinterpret_cast<const float4*>(Ws + (size_t)(k + 3) * DOUT) + oq);
#pragma unroll
        for (int i = 0; i < NV; i++) {
            int node = min(n0 + i, NN - 1);
            float4 hv = __ldg(reinterpret_cast<const float4*>(h + (size_t)node * DIN) + (k >> 2));
            az[i].x = fmaf(hv.x, n0w.x, fmaf(hv.y, n1w.x, fmaf(hv.z, n2w.x, fmaf(hv.w, n3w.x, az[i].x))));
            az[i].y = fmaf(hv.x, n0w.y, fmaf(hv.y, n1w.y, fmaf(hv.z, n2w.y, fmaf(hv.w, n3w.y, az[i].y))));
            az[i].z = fmaf(hv.x, n0w.z, fmaf(hv.y, n1w.z, fmaf(hv.z, n2w.z, fmaf(hv.w, n3w.z, az[i].z))));
            az[i].w = fmaf(hv.x, n0w.w, fmaf(hv.y, n1w.w, fmaf(hv.z, n2w.w, fmaf(hv.w, n3w.w, az[i].w))));
            as[i].x = fmaf(hv.x, s0w.x, fmaf(hv.y, s1w.x, fmaf(hv.z, s2w.x, fmaf(hv.w, s3w.x, as[i].x))));
            as[i].y = fmaf(hv.x, s0w.y, fmaf(hv.y, s1w.y, fmaf(hv.z, s2w.y, fmaf(hv.w, s3w.y, as[i].y))));
            as[i].z = fmaf(hv.x, s0w.z, fmaf(hv.y, s1w.z, fmaf(hv.z, s2w.z, fmaf(hv.w, s3w.z, as[i].z))));
            as[i].w = fmaf(hv.x, s0w.w, fmaf(hv.y, s1w.w, fmaf(hv.z, s2w.w, fmaf(hv.w, s3w.w, as[i].w))));
        }
    }

#pragma unroll
    for (int i = 0; i < NV; i++) {
        if (n0 + i < NN) {
            reinterpret_cast<float4*>(z + (size_t)(n0 + i) * DOUT)[oq] = az[i];
            reinterpret_cast<float4*>(s + (size_t)(n0 + i) * DOUT)[oq] = as[i];
        }
    }
}

// scalar combined z/s for DOUT=5 (layer 3)
template <int DIN, int DOUT>
__global__ void k_zsS(const float* __restrict__ h, const float* __restrict__ Wn,
                      const float* __restrict__ Ws, const float* __restrict__ bias,
                      float* __restrict__ z, float* __restrict__ s) {
    long long idx = (long long)blockIdx.x * blockDim.x + threadIdx.x;
    if (idx >= (long long)NN * DOUT) return;
    int v = (int)(idx / DOUT);
    int o = (int)(idx % DOUT);
    const float* hrow = h + (size_t)v * DIN;
    float accz = 0.0f;
    float accs = bias[o];
#pragma unroll
    for (int k = 0; k < DIN; k++) {
        float hv = hrow[k];
        accz = fmaf(hv, Wn[k * DOUT + o], accz);
        accs = fmaf(hv, Ws[k * DOUT + o], accs);
    }
    z[idx] = accz;
    s[idx] = accs;
}

// ---------------------------------------------------------------------------
// warp-aggregated readout (gid sorted -> warps mostly single-graph)
__global__ void k_readout(const float* __restrict__ h, const int* __restrict__ gid,
                          float* __restrict__ out) {
    int v = blockIdx.x * blockDim.x + threadIdx.x;
    bool ok = (v < NN);
    int g = ok ? gid[v] : -1;
    float c = ok ? 1.0f : 0.0f;
    float f0 = 0, f1 = 0, f2 = 0, f3 = 0, f4 = 0;
    if (ok) {
        const float* hr = h + (size_t)v * 5;
        f0 = hr[0]; f1 = hr[1]; f2 = hr[2]; f3 = hr[3]; f4 = hr[4];
    }
    int g0 = __shfl_sync(0xFFFFFFFFu, ok ? g : __shfl_sync(0xFFFFFFFFu, g, 0), 0);
    bool uniform = __all_sync(0xFFFFFFFFu, !ok || g == g0);
    if (uniform) {
#pragma unroll
        for (int m = 16; m > 0; m >>= 1) {
            c  += __shfl_xor_sync(0xFFFFFFFFu, c, m);
            f0 += __shfl_xor_sync(0xFFFFFFFFu, f0, m);
            f1 += __shfl_xor_sync(0xFFFFFFFFu, f1, m);
            f2 += __shfl_xor_sync(0xFFFFFFFFu, f2, m);
            f3 += __shfl_xor_sync(0xFFFFFFFFu, f3, m);
            f4 += __shfl_xor_sync(0xFFFFFFFFu, f4, m);
        }
        if ((threadIdx.x & 31) == 0 && c > 0.0f) {
            atomicAdd(&g_cnt[g0], c);
            atomicAdd(&out[g0 * 5 + 0], f0);
            atomicAdd(&out[g0 * 5 + 1], f1);
            atomicAdd(&out[g0 * 5 + 2], f2);
            atomicAdd(&out[g0 * 5 + 3], f3);
            atomicAdd(&out[g0 * 5 + 4], f4);
        }
    } else if (ok) {
        atomicAdd(&g_cnt[g], 1.0f);
        atomicAdd(&out[g * 5 + 0], f0);
        atomicAdd(&out[g * 5 + 1], f1);
        atomicAdd(&out[g * 5 + 2], f2);
        atomicAdd(&out[g * 5 + 3], f3);
        atomicAdd(&out[g * 5 + 4], f4);
    }
}

__global__ void k_final(float* __restrict__ out) {
    int i = blockIdx.x * blockDim.x + threadIdx.x;
    if (i < NG * 5) out[i] /= fmaxf(g_cnt[i / 5], 1.0f);
}

// ---------------------------------------------------------------------------
static inline int blks(long long n, int t) { return (int)((n + t - 1) / t); }

extern "C" void kernel_launch(void* const* d_in, const int* in_sizes, int n_in,
                              void* d_out, int out_size) {
    const float* feat = (const float*)d_in[0];
    const int* src = (const int*)d_in[1];
    const int* dst = (const int*)d_in[2];
    const int* gid = (const int*)d_in[3];
    const float* Ws0 = (const float*)d_in[4];
    const float* Wn0 = (const float*)d_in[5];
    const float* b0  = (const float*)d_in[6];
    const float* Ws1 = (const float*)d_in[7];
    const float* Wn1 = (const float*)d_in[8];
    const float* b1  = (const float*)d_in[9];
    const float* Ws2 = (const float*)d_in[10];
    const float* Wn2 = (const float*)d_in[11];
    const float* b2  = (const float*)d_in[12];
    const float* Ws3 = (const float*)d_in[13];
    const float* Wn3 = (const float*)d_in[14];
    const float* b3  = (const float*)d_in[15];
    float* out = (float*)d_out;

    float *bufB, *z, *s, *agg, *cnt;
    int *degi;
    cudaGetSymbolAddress((void**)&bufB, g_bufB);
    cudaGetSymbolAddress((void**)&z, g_z);
    cudaGetSymbolAddress((void**)&s, g_s);
    cudaGetSymbolAddress((void**)&agg, g_agg);
    cudaGetSymbolAddress((void**)&cnt, g_cnt);
    cudaGetSymbolAddress((void**)&degi, g_degi);

    const int T = 256;

    // ---- CSR build ----
    cudaMemsetAsync(degi, 0, NN * sizeof(int));
    k_degree<<<blks(NE / 4, T), T>>>(dst);
    k_scan1<<<NB, 1024>>>();
    k_scan2<<<1, 256>>>();
    k_scan3<<<NB, 1024>>>();
    k_build<<<blks(NE / 2, T), T>>>(src, dst);

    // ---- layer 0 + layer-1 projections (fused, h0 never leaves smem) ----
    k_gather4<32, 4><<<blks((long long)NN * 32, T), T>>>(feat, agg);
    k_sage0zs<<<(NN + 63) / 64, 256>>>(feat, agg, Ws0, Wn0, b0, Wn1, Ws1, b1, z, s);

    // ---- layer 1 gather/epilogue: 128 -> 48, relu ----
    k_gatherF<48, 2, true><<<blks((long long)NN * 32, T), T>>>(z, s, bufB);

    // ---- layer 2: 48 -> 28, relu ----
    {
        long long th = (long long)((NN + 3) / 4) * 7;
        k_zs<48, 28, 4><<<blks(th, T), T>>>(bufB, Wn2, Ws2, b2, z, s);
    }
    k_gatherF<28, 4, true><<<blks((long long)NN * 32, T), T>>>(z, s, bufB);

    // ---- layer 3: 28 -> 5, linear ----
    k_zsS<28, 5><<<blks((long long)NN * 5, T), T>>>(bufB, Wn3, Ws3, b3, z, s);
    k_gatherF5<<<blks((long long)NN * 32, T), T>>>(z, s, bufB);

    // ---- readout ----
    cudaMemsetAsync(out, 0, NG * 5 * sizeof(float));
    cudaMemsetAsync(cnt, 0, NG * sizeof(float));
    k_readout<<<blks(NN, T), T>>>(bufB, gid, out);
    k_final<<<blks(NG * 5, T), T>>>(out);
}

// round 10
// speedup vs baseline: 1.3509x; 1.3509x over previous
#include <cuda_runtime.h>
#include <cuda_bf16.h>

static const int NN = 200000;
static const int NE = 3200000;
static const int NG = 400;
static const int NB = (NN + 1023) / 1024;  // 196 scan blocks

// Scratch (device globals; no runtime allocation allowed)
__device__ int   g_degi[NN];
__device__ int   g_off[NN + 1];
__device__ int   g_cursor[NN];
__device__ int   g_csr[NE];
__device__ int   g_bsum[256];
__device__ float g_bufA[(size_t)NN * 128];  // layer outputs (max 128)
__device__ float g_bufB[(size_t)NN * 48];
__device__ float g_z[(size_t)NN * 48];      // projected neighbor features
__device__ float g_s[(size_t)NN * 48];      // self-projection + bias
__device__ float g_agg[(size_t)NN * 32];    // layer-0 raw-feature aggregate
__device__ float g_cnt[NG];

// ---------------------------------------------------------------------------
__global__ void k_degree(const int* __restrict__ dst) {
    int i = blockIdx.x * blockDim.x + threadIdx.x;
    if (i >= NE / 4) return;
    int4 d = reinterpret_cast<const int4*>(dst)[i];
    atomicAdd(&g_degi[d.x], 1);
    atomicAdd(&g_degi[d.y], 1);
    atomicAdd(&g_degi[d.z], 1);
    atomicAdd(&g_degi[d.w], 1);
}

// ---- parallel exclusive scan of g_degi -> g_off ----
__global__ void k_scan1() {
    __shared__ int sh[1024];
    int t = threadIdx.x;
    int j = blockIdx.x * 1024 + t;
    sh[t] = (j < NN) ? g_degi[j] : 0;
    __syncthreads();
    for (int d = 512; d > 0; d >>= 1) {
        if (t < d) sh[t] += sh[t + d];
        __syncthreads();
    }
    if (t == 0) g_bsum[blockIdx.x] = sh[0];
}

__global__ void k_scan2() {
    __shared__ int sh[256];
    int t = threadIdx.x;
    int v = (t < NB) ? g_bsum[t] : 0;
    sh[t] = v;
    __syncthreads();
    for (int d = 1; d < 256; d <<= 1) {
        int x = (t >= d) ? sh[t - d] : 0;
        __syncthreads();
        sh[t] += x;
        __syncthreads();
    }
    g_bsum[t] = sh[t] - v;  // exclusive
}

__global__ void k_scan3() {
    __shared__ int sh[1024];
    int t = threadIdx.x;
    int j = blockIdx.x * 1024 + t;
    int v = (j < NN) ? g_degi[j] : 0;
    sh[t] = v;
    __syncthreads();
    for (int d = 1; d < 1024; d <<= 1) {
        int x = (t >= d) ? sh[t - d] : 0;
        __syncthreads();
        sh[t] += x;
        __syncthreads();
    }
    int excl = sh[t] - v + g_bsum[blockIdx.x];
    if (j < NN) {
        g_off[j] = excl;
        g_cursor[j] = excl;
    }
    if (j == NN - 1) g_off[NN] = excl + v;
}

__global__ void k_build(const int* __restrict__ src, const int* __restrict__ dst) {
    int i = blockIdx.x * blockDim.x + threadIdx.x;
    if (i >= NE / 2) return;
    int2 s2 = reinterpret_cast<const int2*>(src)[i];
    int2 d2 = reinterpret_cast<const int2*>(dst)[i];
    int p0 = atomicAdd(&g_cursor[d2.x], 1);
    g_csr[p0] = s2.x;
    int p1 = atomicAdd(&g_cursor[d2.y], 1);
    g_csr[p1] = s2.y;
}

// ---------------------------------------------------------------------------
// plain gather (layer 0): agg[v] = sum feat[nbr] / max(deg,1). Warp per node.
template <int DIM, int SLOTS>
__global__ void k_gather4(const float* __restrict__ z, float* __restrict__ agg) {
    constexpr int F4L = 32 / SLOTS;
    constexpr int NF4 = DIM / 4;
    int gt = blockIdx.x * blockDim.x + threadIdx.x;
    int v = gt >> 5;
    if (v >= NN) return;
    int lane = gt & 31;
    int slot = lane / F4L;
    int f4 = lane % F4L;
    bool act = (f4 < NF4);

    int beg = g_off[v];
    int end = g_off[v + 1];
    float4 acc = make_float4(0.f, 0.f, 0.f, 0.f);

    int e = beg;
    for (; e + 4 * SLOTS <= end; e += 4 * SLOTS) {
        int s0 = g_csr[e + slot];
        int s1 = g_csr[e + SLOTS + slot];
        int s2 = g_csr[e + 2 * SLOTS + slot];
        int s3 = g_csr[e + 3 * SLOTS + slot];
        if (act) {
            float4 t0 = __ldg(reinterpret_cast<const float4*>(z + (size_t)s0 * DIM) + f4);
            float4 t1 = __ldg(reinterpret_cast<const float4*>(z + (size_t)s1 * DIM) + f4);
            float4 t2 = __ldg(reinterpret_cast<const float4*>(z + (size_t)s2 * DIM) + f4);
            float4 t3 = __ldg(reinterpret_cast<const float4*>(z + (size_t)s3 * DIM) + f4);
            acc.x += (t0.x + t1.x) + (t2.x + t3.x);
            acc.y += (t0.y + t1.y) + (t2.y + t3.y);
            acc.z += (t0.z + t1.z) + (t2.z + t3.z);
            acc.w += (t0.w + t1.w) + (t2.w + t3.w);
        }
    }
    for (; e < end; e += SLOTS) {
        int myE = e + slot;
        if (myE < end && act) {
            int s0 = g_csr[myE];
            float4 t0 = __ldg(reinterpret_cast<const float4*>(z + (size_t)s0 * DIM) + f4);
            acc.x += t0.x; acc.y += t0.y; acc.z += t0.z; acc.w += t0.w;
        }
    }
#pragma unroll
    for (int m = F4L; m < 32; m <<= 1) {
        acc.x += __shfl_xor_sync(0xFFFFFFFFu, acc.x, m);
        acc.y += __shfl_xor_sync(0xFFFFFFFFu, acc.y, m);
        acc.z += __shfl_xor_sync(0xFFFFFFFFu, acc.z, m);
        acc.w += __shfl_xor_sync(0xFFFFFFFFu, acc.w, m);
    }
    float inv = 1.0f / fmaxf((float)(end - beg), 1.0f);
    if (slot == 0 && act) {
        float4 o = make_float4(acc.x * inv, acc.y * inv, acc.z * inv, acc.w * inv);
        reinterpret_cast<float4*>(agg + (size_t)v * DIM)[f4] = o;
    }
}

// fused gather (layers 1,2): out[v] = act( s[v] + sum z[nbr]/max(deg,1) )
template <int DIM, int SLOTS, bool RELU>
__global__ void k_gatherF(const float* __restrict__ z, const float* __restrict__ s,
                          float* __restrict__ out) {
    constexpr int F4L = 32 / SLOTS;
    constexpr int NF4 = DIM / 4;
    int gt = blockIdx.x * blockDim.x + threadIdx.x;
    int v = gt >> 5;
    if (v >= NN) return;
    int lane = gt & 31;
    int slot = lane / F4L;
    int f4 = lane % F4L;
    bool act = (f4 < NF4);

    int beg = g_off[v];
    int end = g_off[v + 1];
    float4 acc = make_float4(0.f, 0.f, 0.f, 0.f);

    int e = beg;
    for (; e + 4 * SLOTS <= end; e += 4 * SLOTS) {
        int s0 = g_csr[e + slot];
        int s1 = g_csr[e + SLOTS + slot];
        int s2 = g_csr[e + 2 * SLOTS + slot];
        int s3 = g_csr[e + 3 * SLOTS + slot];
        if (act) {
            float4 t0 = __ldg(reinterpret_cast<const float4*>(z + (size_t)s0 * DIM) + f4);
            float4 t1 = __ldg(reinterpret_cast<const float4*>(z + (size_t)s1 * DIM) + f4);
            float4 t2 = __ldg(reinterpret_cast<const float4*>(z + (size_t)s2 * DIM) + f4);
            float4 t3 = __ldg(reinterpret_cast<const float4*>(z + (size_t)s3 * DIM) + f4);
            acc.x += (t0.x + t1.x) + (t2.x + t3.x);
            acc.y += (t0.y + t1.y) + (t2.y + t3.y);
            acc.z += (t0.z + t1.z) + (t2.z + t3.z);
            acc.w += (t0.w + t1.w) + (t2.w + t3.w);
        }
    }
    for (; e < end; e += SLOTS) {
        int myE = e + slot;
        if (myE < end && act) {
            int s0 = g_csr[myE];
            float4 t0 = __ldg(reinterpret_cast<const float4*>(z + (size_t)s0 * DIM) + f4);
            acc.x += t0.x; acc.y += t0.y; acc.z += t0.z; acc.w += t0.w;
        }
    }
#pragma unroll
    for (int m = F4L; m < 32; m <<= 1) {
        acc.x += __shfl_xor_sync(0xFFFFFFFFu, acc.x, m);
        acc.y += __shfl_xor_sync(0xFFFFFFFFu, acc.y, m);
        acc.z += __shfl_xor_sync(0xFFFFFFFFu, acc.z, m);
        acc.w += __shfl_xor_sync(0xFFFFFFFFu, acc.w, m);
    }
    float inv = 1.0f / fmaxf((float)(end - beg), 1.0f);
    if (slot == 0 && act) {
        float4 sv = __ldg(reinterpret_cast<const float4*>(s + (size_t)v * DIM) + f4);
        float4 o = make_float4(sv.x + acc.x * inv, sv.y + acc.y * inv,
                               sv.z + acc.z * inv, sv.w + acc.w * inv);
        if (RELU) {
            o.x = fmaxf(o.x, 0.f); o.y = fmaxf(o.y, 0.f);
            o.z = fmaxf(o.z, 0.f); o.w = fmaxf(o.w, 0.f);
        }
        reinterpret_cast<float4*>(out + (size_t)v * DIM)[f4] = o;
    }
}

// fused scalar gather for DIM=5 (layer 3, no relu)
__global__ void k_gatherF5(const float* __restrict__ z, const float* __restrict__ s,
                           float* __restrict__ out) {
    constexpr int DIM = 5;
    int gt = blockIdx.x * blockDim.x + threadIdx.x;
    int v = gt >> 5;
    if (v >= NN) return;
    int lane = gt & 31;
    int slot = lane >> 3;
    int f = lane & 7;
    bool act = (f < DIM);

    int beg = g_off[v];
    int end = g_off[v + 1];
    float acc = 0.0f;
    int e = beg;
    for (; e + 8 <= end; e += 8) {
        int s0 = g_csr[e + slot];
        int s1 = g_csr[e + 4 + slot];
        if (act) acc += z[(size_t)s0 * DIM + f] + z[(size_t)s1 * DIM + f];
    }
    for (; e < end; e += 4) {
        int myE = e + slot;
        if (myE < end && act) acc += z[(size_t)g_csr[myE] * DIM + f];
    }
#pragma unroll
    for (int m = 8; m < 32; m <<= 1) acc += __shfl_xor_sync(0xFFFFFFFFu, acc, m);
    float inv = 1.0f / fmaxf((float)(end - beg), 1.0f);
    if (slot == 0 && act)
        out[(size_t)v * DIM + f] = s[(size_t)v * DIM + f] + acc * inv;
}

// ---------------------------------------------------------------------------
// Combined z/s projection: z = h@Wn ; s = h@Ws + b. Thread -> float4 x NV nodes.
template <int DIN, int DOUT, int NV>
__global__ void k_zs(const float* __restrict__ h, const float* __restrict__ Wn,
                     const float* __restrict__ Ws, const float* __restrict__ bias,
                     float* __restrict__ z, float* __restrict__ s) {
    constexpr int OG = DOUT / 4;
    long long t = (long long)blockIdx.x * blockDim.x + threadIdx.x;
    int oq = (int)(t % OG);
    long long ng = t / OG;
    int n0 = (int)(ng * NV);
    if (n0 >= NN) return;

    float4 b4 = __ldg(reinterpret_cast<const float4*>(bias) + oq);
    float4 az[NV], as[NV];
#pragma unroll
    for (int i = 0; i < NV; i++) {
        az[i] = make_float4(0.f, 0.f, 0.f, 0.f);
        as[i] = b4;
    }

#pragma unroll
    for (int k = 0; k < DIN; k += 4) {
        float4 n0w = __ldg(reinterpret_cast<const float4*>(Wn + (size_t)(k + 0) * DOUT) + oq);
        float4 n1w = __ldg(reinterpret_cast<const float4*>(Wn + (size_t)(k + 1) * DOUT) + oq);
        float4 n2w = __ldg(reinterpret_cast<const float4*>(Wn + (size_t)(k + 2) * DOUT) + oq);
        float4 n3w = __ldg(reinterpret_cast<const float4*>(Wn + (size_t)(k + 3) * DOUT) + oq);
        float4 s0w = __ldg(reinterpret_cast<const float4*>(Ws + (size_t)(k + 0) * DOUT) + oq);
        float4 s1w = __ldg(reinterpret_cast<const float4*>(Ws + (size_t)(k + 1) * DOUT) + oq);
        float4 s2w = __ldg(reinterpret_cast<const float4*>(Ws + (size_t)(k + 2) * DOUT) + oq);
        float4 s3w = __ldg(reinterpret_cast<const float4*>(Ws + (size_t)(k + 3) * DOUT) + oq);
#pragma unroll
        for (int i = 0; i < NV; i++) {
            int node = min(n0 + i, NN - 1);
            float4 hv = __ldg(reinterpret_cast<const float4*>(h + (size_t)node * DIN) + (k >> 2));
            az[i].x = fmaf(hv.x, n0w.x, fmaf(hv.y, n1w.x, fmaf(hv.z, n2w.x, fmaf(hv.w, n3w.x, az[i].x))));
            az[i].y = fmaf(hv.x, n0w.y, fmaf(hv.y, n1w.y, fmaf(hv.z, n2w.y, fmaf(hv.w, n3w.y, az[i].y))));
            az[i].z = fmaf(hv.x, n0w.z, fmaf(hv.y, n1w.z, fmaf(hv.z, n2w.z, fmaf(hv.w, n3w.z, az[i].z))));
            az[i].w = fmaf(hv.x, n0w.w, fmaf(hv.y, n1w.w, fmaf(hv.z, n2w.w, fmaf(hv.w, n3w.w, az[i].w))));
            as[i].x = fmaf(hv.x, s0w.x, fmaf(hv.y, s1w.x, fmaf(hv.z, s2w.x, fmaf(hv.w, s3w.x, as[i].x))));
            as[i].y = fmaf(hv.x, s0w.y, fmaf(hv.y, s1w.y, fmaf(hv.z, s2w.y, fmaf(hv.w, s3w.y, as[i].y))));
            as[i].z = fmaf(hv.x, s0w.z, fmaf(hv.y, s1w.z, fmaf(hv.z, s2w.z, fmaf(hv.w, s3w.z, as[i].z))));
            as[i].w = fmaf(hv.x, s0w.w, fmaf(hv.y, s1w.w, fmaf(hv.z, s2w.w, fmaf(hv.w, s3w.w, as[i].w))));
        }
    }

#pragma unroll
    for (int i = 0; i < NV; i++) {
        if (n0 + i < NN) {
            reinterpret_cast<float4*>(z + (size_t)(n0 + i) * DOUT)[oq] = az[i];
            reinterpret_cast<float4*>(s + (size_t)(n0 + i) * DOUT)[oq] = as[i];
        }
    }
}

// scalar combined z/s for DOUT=5 (layer 3)
template <int DIN, int DOUT>
__global__ void k_zsS(const float* __restrict__ h, const float* __restrict__ Wn,
                      const float* __restrict__ Ws, const float* __restrict__ bias,
                      float* __restrict__ z, float* __restrict__ s) {
    long long idx = (long long)blockIdx.x * blockDim.x + threadIdx.x;
    if (idx >= (long long)NN * DOUT) return;
    int v = (int)(idx / DOUT);
    int o = (int)(idx % DOUT);
    const float* hrow = h + (size_t)v * DIN;
    float accz = 0.0f;
    float accs = bias[o];
#pragma unroll
    for (int k = 0; k < DIN; k++) {
        float hv = hrow[k];
        accz = fmaf(hv, Wn[k * DOUT + o], accz);
        accs = fmaf(hv, Ws[k * DOUT + o], accs);
    }
    z[idx] = accz;
    s[idx] = accs;
}

// Fused layer-0: out = relu( feat@Ws + agg@Wn + b ), DIN=32, DOUT=128
template <int NV>
__global__ void k_sage0(const float* __restrict__ feat, const float* __restrict__ agg,
                        const float* __restrict__ Ws, const float* __restrict__ Wn,
                        const float* __restrict__ bias, float* __restrict__ out) {
    constexpr int DIN = 32, DOUT = 128, OG = 32;
    long long t = (long long)blockIdx.x * blockDim.x + threadIdx.x;
    int oq = (int)(t % OG);
    long long ng = t / OG;
    int n0 = (int)(ng * NV);
    if (n0 >= NN) return;

    float4 b4 = __ldg(reinterpret_cast<const float4*>(bias) + oq);
    float4 acc[NV];
#pragma unroll
    for (int i = 0; i < NV; i++) acc[i] = b4;

#pragma unroll
    for (int k = 0; k < DIN; k += 4) {
        float4 ws0 = __ldg(reinterpret_cast<const float4*>(Ws + (size_t)(k + 0) * DOUT) + oq);
        float4 ws1 = __ldg(reinterpret_cast<const float4*>(Ws + (size_t)(k + 1) * DOUT) + oq);
        float4 ws2 = __ldg(reinterpret_cast<const float4*>(Ws + (size_t)(k + 2) * DOUT) + oq);
        float4 ws3 = __ldg(reinterpret_cast<const float4*>(Ws + (size_t)(k + 3) * DOUT) + oq);
        float4 wn0 = __ldg(reinterpret_cast<const float4*>(Wn + (size_t)(k + 0) * DOUT) + oq);
        float4 wn1 = __ldg(reinterpret_cast<const float4*>(Wn + (size_t)(k + 1) * DOUT) + oq);
        float4 wn2 = __ldg(reinterpret_cast<const float4*>(Wn + (size_t)(k + 2) * DOUT) + oq);
        float4 wn3 = __ldg(reinterpret_cast<const float4*>(Wn + (size_t)(k + 3) * DOUT) + oq);
#pragma unroll
        for (int i = 0; i < NV; i++) {
            int node = min(n0 + i, NN - 1);
            float4 hv = __ldg(reinterpret_cast<const float4*>(feat + (size_t)node * DIN) + (k >> 2));
            float4 av = __ldg(reinterpret_cast<const float4*>(agg + (size_t)node * DIN) + (k >> 2));
            acc[i].x = fmaf(hv.x, ws0.x, fmaf(hv.y, ws1.x, fmaf(hv.z, ws2.x, fmaf(hv.w, ws3.x, acc[i].x))));
            acc[i].y = fmaf(hv.x, ws0.y, fmaf(hv.y, ws1.y, fmaf(hv.z, ws2.y, fmaf(hv.w, ws3.y, acc[i].y))));
            acc[i].z = fmaf(hv.x, ws0.z, fmaf(hv.y, ws1.z, fmaf(hv.z, ws2.z, fmaf(hv.w, ws3.z, acc[i].z))));
            acc[i].w = fmaf(hv.x, ws0.w, fmaf(hv.y, ws1.w, fmaf(hv.z, ws2.w, fmaf(hv.w, ws3.w, acc[i].w))));
            acc[i].x = fmaf(av.x, wn0.x, fmaf(av.y, wn1.x, fmaf(av.z, wn2.x, fmaf(av.w, wn3.x, acc[i].x))));
            acc[i].y = fmaf(av.x, wn0.y, fmaf(av.y, wn1.y, fmaf(av.z, wn2.y, fmaf(av.w, wn3.y, acc[i].y))));
            acc[i].z = fmaf(av.x, wn0.z, fmaf(av.y, wn1.z, fmaf(av.z, wn2.z, fmaf(av.w, wn3.z, acc[i].z))));
            acc[i].w = fmaf(av.x, wn0.w, fmaf(av.y, wn1.w, fmaf(av.z, wn2.w, fmaf(av.w, wn3.w, acc[i].w))));
        }
    }

#pragma unroll
    for (int i = 0; i < NV; i++) {
        if (n0 + i < NN) {
            float4 r = acc[i];
            r.x = fmaxf(r.x, 0.f); r.y = fmaxf(r.y, 0.f);
            r.z = fmaxf(r.z, 0.f); r.w = fmaxf(r.w, 0.f);
            reinterpret_cast<float4*>(out + (size_t)(n0 + i) * DOUT)[oq] = r;
        }
    }
}

// ---------------------------------------------------------------------------
// warp-aggregated readout (gid sorted -> warps mostly single-graph)
__global__ void k_readout(const float* __restrict__ h, const int* __restrict__ gid,
                          float* __restrict__ out) {
    int v = blockIdx.x * blockDim.x + threadIdx.x;
    bool ok = (v < NN);
    int g = ok ? gid[v] : -1;
    float c = ok ? 1.0f : 0.0f;
    float f0 = 0, f1 = 0, f2 = 0, f3 = 0, f4 = 0;
    if (ok) {
        const float* hr = h + (size_t)v * 5;
        f0 = hr[0]; f1 = hr[1]; f2 = hr[2]; f3 = hr[3]; f4 = hr[4];
    }
    int g0 = __shfl_sync(0xFFFFFFFFu, ok ? g : __shfl_sync(0xFFFFFFFFu, g, 0), 0);
    bool uniform = __all_sync(0xFFFFFFFFu, !ok || g == g0);
    if (uniform) {
#pragma unroll
        for (int m = 16; m > 0; m >>= 1) {
            c  += __shfl_xor_sync(0xFFFFFFFFu, c, m);
            f0 += __shfl_xor_sync(0xFFFFFFFFu, f0, m);
            f1 += __shfl_xor_sync(0xFFFFFFFFu, f1, m);
            f2 += __shfl_xor_sync(0xFFFFFFFFu, f2, m);
            f3 += __shfl_xor_sync(0xFFFFFFFFu, f3, m);
            f4 += __shfl_xor_sync(0xFFFFFFFFu, f4, m);
        }
        if ((threadIdx.x & 31) == 0 && c > 0.0f) {
            atomicAdd(&g_cnt[g0], c);
            atomicAdd(&out[g0 * 5 + 0], f0);
            atomicAdd(&out[g0 * 5 + 1], f1);
            atomicAdd(&out[g0 * 5 + 2], f2);
            atomicAdd(&out[g0 * 5 + 3], f3);
            atomicAdd(&out[g0 * 5 + 4], f4);
        }
    } else if (ok) {
        atomicAdd(&g_cnt[g], 1.0f);
        atomicAdd(&out[g * 5 + 0], f0);
        atomicAdd(&out[g * 5 + 1], f1);
        atomicAdd(&out[g * 5 + 2], f2);
        atomicAdd(&out[g * 5 + 3], f3);
        atomicAdd(&out[g * 5 + 4], f4);
    }
}

__global__ void k_final(float* __restrict__ out) {
    int i = blockIdx.x * blockDim.x + threadIdx.x;
    if (i < NG * 5) out[i] /= fmaxf(g_cnt[i / 5], 1.0f);
}

// ---------------------------------------------------------------------------
static inline int blks(long long n, int t) { return (int)((n + t - 1) / t); }

extern "C" void kernel_launch(void* const* d_in, const int* in_sizes, int n_in,
                              void* d_out, int out_size) {
    const float* feat = (const float*)d_in[0];
    const int* src = (const int*)d_in[1];
    const int* dst = (const int*)d_in[2];
    const int* gid = (const int*)d_in[3];
    const float* Ws0 = (const float*)d_in[4];
    const float* Wn0 = (const float*)d_in[5];
    const float* b0  = (const float*)d_in[6];
    const float* Ws1 = (const float*)d_in[7];
    const float* Wn1 = (const float*)d_in[8];
    const float* b1  = (const float*)d_in[9];
    const float* Ws2 = (const float*)d_in[10];
    const float* Wn2 = (const float*)d_in[11];
    const float* b2  = (const float*)d_in[12];
    const float* Ws3 = (const float*)d_in[13];
    const float* Wn3 = (const float*)d_in[14];
    const float* b3  = (const float*)d_in[15];
    float* out = (float*)d_out;

    float *bufA, *bufB, *z, *s, *agg, *cnt;
    int *degi;
    cudaGetSymbolAddress((void**)&bufA, g_bufA);
    cudaGetSymbolAddress((void**)&bufB, g_bufB);
    cudaGetSymbolAddress((void**)&z, g_z);
    cudaGetSymbolAddress((void**)&s, g_s);
    cudaGetSymbolAddress((void**)&agg, g_agg);
    cudaGetSymbolAddress((void**)&cnt, g_cnt);
    cudaGetSymbolAddress((void**)&degi, g_degi);

    const int T = 256;

    // ---- CSR build ----
    cudaMemsetAsync(degi, 0, NN * sizeof(int));
    k_degree<<<blks(NE / 4, T), T>>>(dst);
    k_scan1<<<NB, 1024>>>();
    k_scan2<<<1, 256>>>();
    k_scan3<<<NB, 1024>>>();
    k_build<<<blks(NE / 2, T), T>>>(src, dst);

    // ---- layer 0: 32 -> 128, relu ----
    k_gather4<32, 4><<<blks((long long)NN * 32, T), T>>>(feat, agg);
    {
        long long th = (long long)((NN + 3) / 4) * 32;
        k_sage0<4><<<blks(th, T), T>>>(feat, agg, Ws0, Wn0, b0, bufA);
    }

    // ---- layer 1: 128 -> 48, relu (combined zs + fused gather) ----
    {
        long long th = (long long)((NN + 3) / 4) * 12;
        k_zs<128, 48, 4><<<blks(th, T), T>>>(bufA, Wn1, Ws1, b1, z, s);
    }
    k_gatherF<48, 2, true><<<blks((long long)NN * 32, T), T>>>(z, s, bufB);

    // ---- layer 2: 48 -> 28, relu ----
    {
        long long th = (long long)((NN + 3) / 4) * 7;
        k_zs<48, 28, 4><<<blks(th, T), T>>>(bufB, Wn2, Ws2, b2, z, s);
    }
    k_gatherF<28, 4, true><<<blks((long long)NN * 32, T), T>>>(z, s, bufA);

    // ---- layer 3: 28 -> 5, linear ----
    k_zsS<28, 5><<<blks((long long)NN * 5, T), T>>>(bufA, Wn3, Ws3, b3, z, s);
    k_gatherF5<<<blks((long long)NN * 32, T), T>>>(z, s, bufB);

    // ---- readout ----
    cudaMemsetAsync(out, 0, NG * 5 * sizeof(float));
    cudaMemsetAsync(cnt, 0, NG * sizeof(float));
    k_readout<<<blks(NN, T), T>>>(bufB, gid, out);
    k_final<<<blks(NG * 5, T), T>>>(out);
}

// round 11
// speedup vs baseline: 1.3727x; 1.0162x over previous
#include <cuda_runtime.h>
#include <cuda_bf16.h>

static const int NN = 200000;
static const int NE = 3200000;
static const int NG = 400;
static const int NB = (NN + 1023) / 1024;  // 196 scan blocks

// Scratch (device globals; no runtime allocation allowed)
__device__ int   g_degi[NN];
__device__ int   g_off[NN + 1];
__device__ int   g_rank[NE];
__device__ int   g_csr[NE];
__device__ int   g_bsum[256];
__device__ float g_bufA[(size_t)NN * 128];  // layer outputs (max 128)
__device__ float g_bufB[(size_t)NN * 48];
__device__ float g_z[(size_t)NN * 48];      // projected neighbor features
__device__ float g_s[(size_t)NN * 48];      // self-projection + bias
__device__ float g_agg[(size_t)NN * 32];    // layer-0 raw-feature aggregate
__device__ float g_cnt[NG];

// ---------------------------------------------------------------------------
// degree + rank: one atomic pass records each edge's slot within its dst list
__global__ void k_degrank(const int* __restrict__ dst) {
    int e = blockIdx.x * blockDim.x + threadIdx.x;
    if (e < NE) g_rank[e] = atomicAdd(&g_degi[dst[e]], 1);
}

// ---- parallel exclusive scan of g_degi -> g_off ----
__global__ void k_scan1() {
    __shared__ int sh[1024];
    int t = threadIdx.x;
    int j = blockIdx.x * 1024 + t;
    sh[t] = (j < NN) ? g_degi[j] : 0;
    __syncthreads();
    for (int d = 512; d > 0; d >>= 1) {
        if (t < d) sh[t] += sh[t + d];
        __syncthreads();
    }
    if (t == 0) g_bsum[blockIdx.x] = sh[0];
}

__global__ void k_scan2() {
    __shared__ int sh[256];
    int t = threadIdx.x;
    int v = (t < NB) ? g_bsum[t] : 0;
    sh[t] = v;
    __syncthreads();
    for (int d = 1; d < 256; d <<= 1) {
        int x = (t >= d) ? sh[t - d] : 0;
        __syncthreads();
        sh[t] += x;
        __syncthreads();
    }
    g_bsum[t] = sh[t] - v;  // exclusive
}

__global__ void k_scan3() {
    __shared__ int sh[1024];
    int t = threadIdx.x;
    int j = blockIdx.x * 1024 + t;
    int v = (j < NN) ? g_degi[j] : 0;
    sh[t] = v;
    __syncthreads();
    for (int d = 1; d < 1024; d <<= 1) {
        int x = (t >= d) ? sh[t - d] : 0;
        __syncthreads();
        sh[t] += x;
        __syncthreads();
    }
    int excl = sh[t] - v + g_bsum[blockIdx.x];
    if (j < NN) g_off[j] = excl;
    if (j == NN - 1) g_off[NN] = excl + v;
}

// atomic-free CSR fill: csr[off[dst] + rank] = src
__global__ void k_build(const int* __restrict__ src, const int* __restrict__ dst) {
    int e = blockIdx.x * blockDim.x + threadIdx.x;
    if (e >= NE) return;
    int d = dst[e];
    g_csr[g_off[d] + g_rank[e]] = src[e];
}

// ---------------------------------------------------------------------------
// plain gather (layer 0): agg[v] = sum feat[nbr] / max(deg,1). Warp per node.
template <int DIM, int SLOTS>
__global__ void k_gather4(const float* __restrict__ z, float* __restrict__ agg) {
    constexpr int F4L = 32 / SLOTS;
    constexpr int NF4 = DIM / 4;
    int gt = blockIdx.x * blockDim.x + threadIdx.x;
    int v = gt >> 5;
    if (v >= NN) return;
    int lane = gt & 31;
    int slot = lane / F4L;
    int f4 = lane % F4L;
    bool act = (f4 < NF4);

    int beg = g_off[v];
    int end = g_off[v + 1];
    float4 acc = make_float4(0.f, 0.f, 0.f, 0.f);

    int e = beg;
    for (; e + 4 * SLOTS <= end; e += 4 * SLOTS) {
        int s0 = g_csr[e + slot];
        int s1 = g_csr[e + SLOTS + slot];
        int s2 = g_csr[e + 2 * SLOTS + slot];
        int s3 = g_csr[e + 3 * SLOTS + slot];
        if (act) {
            float4 t0 = __ldg(reinterpret_cast<const float4*>(z + (size_t)s0 * DIM) + f4);
            float4 t1 = __ldg(reinterpret_cast<const float4*>(z + (size_t)s1 * DIM) + f4);
            float4 t2 = __ldg(reinterpret_cast<const float4*>(z + (size_t)s2 * DIM) + f4);
            float4 t3 = __ldg(reinterpret_cast<const float4*>(z + (size_t)s3 * DIM) + f4);
            acc.x += (t0.x + t1.x) + (t2.x + t3.x);
            acc.y += (t0.y + t1.y) + (t2.y + t3.y);
            acc.z += (t0.z + t1.z) + (t2.z + t3.z);
            acc.w += (t0.w + t1.w) + (t2.w + t3.w);
        }
    }
    for (; e < end; e += SLOTS) {
        int myE = e + slot;
        if (myE < end && act) {
            int s0 = g_csr[myE];
            float4 t0 = __ldg(reinterpret_cast<const float4*>(z + (size_t)s0 * DIM) + f4);
            acc.x += t0.x; acc.y += t0.y; acc.z += t0.z; acc.w += t0.w;
        }
    }
#pragma unroll
    for (int m = F4L; m < 32; m <<= 1) {
        acc.x += __shfl_xor_sync(0xFFFFFFFFu, acc.x, m);
        acc.y += __shfl_xor_sync(0xFFFFFFFFu, acc.y, m);
        acc.z += __shfl_xor_sync(0xFFFFFFFFu, acc.z, m);
        acc.w += __shfl_xor_sync(0xFFFFFFFFu, acc.w, m);
    }
    float inv = 1.0f / fmaxf((float)(end - beg), 1.0f);
    if (slot == 0 && act) {
        float4 o = make_float4(acc.x * inv, acc.y * inv, acc.z * inv, acc.w * inv);
        reinterpret_cast<float4*>(agg + (size_t)v * DIM)[f4] = o;
    }
}

// fused gather (layers 1,2): out[v] = act( s[v] + sum z[nbr]/max(deg,1) )
template <int DIM, int SLOTS, bool RELU>
__global__ void k_gatherF(const float* __restrict__ z, const float* __restrict__ s,
                          float* __restrict__ out) {
    constexpr int F4L = 32 / SLOTS;
    constexpr int NF4 = DIM / 4;
    int gt = blockIdx.x * blockDim.x + threadIdx.x;
    int v = gt >> 5;
    if (v >= NN) return;
    int lane = gt & 31;
    int slot = lane / F4L;
    int f4 = lane % F4L;
    bool act = (f4 < NF4);

    int beg = g_off[v];
    int end = g_off[v + 1];
    float4 acc = make_float4(0.f, 0.f, 0.f, 0.f);

    int e = beg;
    for (; e + 4 * SLOTS <= end; e += 4 * SLOTS) {
        int s0 = g_csr[e + slot];
        int s1 = g_csr[e + SLOTS + slot];
        int s2 = g_csr[e + 2 * SLOTS + slot];
        int s3 = g_csr[e + 3 * SLOTS + slot];
        if (act) {
            float4 t0 = __ldg(reinterpret_cast<const float4*>(z + (size_t)s0 * DIM) + f4);
            float4 t1 = __ldg(reinterpret_cast<const float4*>(z + (size_t)s1 * DIM) + f4);
            float4 t2 = __ldg(reinterpret_cast<const float4*>(z + (size_t)s2 * DIM) + f4);
            float4 t3 = __ldg(reinterpret_cast<const float4*>(z + (size_t)s3 * DIM) + f4);
            acc.x += (t0.x + t1.x) + (t2.x + t3.x);
            acc.y += (t0.y + t1.y) + (t2.y + t3.y);
            acc.z += (t0.z + t1.z) + (t2.z + t3.z);
            acc.w += (t0.w + t1.w) + (t2.w + t3.w);
        }
    }
    for (; e < end; e += SLOTS) {
        int myE = e + slot;
        if (myE < end && act) {
            int s0 = g_csr[myE];
            float4 t0 = __ldg(reinterpret_cast<const float4*>(z + (size_t)s0 * DIM) + f4);
            acc.x += t0.x; acc.y += t0.y; acc.z += t0.z; acc.w += t0.w;
        }
    }
#pragma unroll
    for (int m = F4L; m < 32; m <<= 1) {
        acc.x += __shfl_xor_sync(0xFFFFFFFFu, acc.x, m);
        acc.y += __shfl_xor_sync(0xFFFFFFFFu, acc.y, m);
        acc.z += __shfl_xor_sync(0xFFFFFFFFu, acc.z, m);
        acc.w += __shfl_xor_sync(0xFFFFFFFFu, acc.w, m);
    }
    float inv = 1.0f / fmaxf((float)(end - beg), 1.0f);
    if (slot == 0 && act) {
        float4 sv = __ldg(reinterpret_cast<const float4*>(s + (size_t)v * DIM) + f4);
        float4 o = make_float4(sv.x + acc.x * inv, sv.y + acc.y * inv,
                               sv.z + acc.z * inv, sv.w + acc.w * inv);
        if (RELU) {
            o.x = fmaxf(o.x, 0.f); o.y = fmaxf(o.y, 0.f);
            o.z = fmaxf(o.z, 0.f); o.w = fmaxf(o.w, 0.f);
        }
        reinterpret_cast<float4*>(out + (size_t)v * DIM)[f4] = o;
    }
}

// fused scalar gather for DIM=5 (layer 3, no relu)
__global__ void k_gatherF5(const float* __restrict__ z, const float* __restrict__ s,
                           float* __restrict__ out) {
    constexpr int DIM = 5;
    int gt = blockIdx.x * blockDim.x + threadIdx.x;
    int v = gt >> 5;
    if (v >= NN) return;
    int lane = gt & 31;
    int slot = lane >> 3;
    int f = lane & 7;
    bool act = (f < DIM);

    int beg = g_off[v];
    int end = g_off[v + 1];
    float acc = 0.0f;
    int e = beg;
    for (; e + 8 <= end; e += 8) {
        int s0 = g_csr[e + slot];
        int s1 = g_csr[e + 4 + slot];
        if (act) acc += z[(size_t)s0 * DIM + f] + z[(size_t)s1 * DIM + f];
    }
    for (; e < end; e += 4) {
        int myE = e + slot;
        if (myE < end && act) acc += z[(size_t)g_csr[myE] * DIM + f];
    }
#pragma unroll
    for (int m = 8; m < 32; m <<= 1) acc += __shfl_xor_sync(0xFFFFFFFFu, acc, m);
    float inv = 1.0f / fmaxf((float)(end - beg), 1.0f);
    if (slot == 0 && act)
        out[(size_t)v * DIM + f] = s[(size_t)v * DIM + f] + acc * inv;
}

// ---------------------------------------------------------------------------
// Combined z/s projection: z = h@Wn ; s = h@Ws + b. Thread -> float4 x NV nodes.
template <int DIN, int DOUT, int NV>
__global__ void k_zs(const float* __restrict__ h, const float* __restrict__ Wn,
                     const float* __restrict__ Ws, const float* __restrict__ bias,
                     float* __restrict__ z, float* __restrict__ s) {
    constexpr int OG = DOUT / 4;
    long long t = (long long)blockIdx.x * blockDim.x + threadIdx.x;
    int oq = (int)(t % OG);
    long long ng = t / OG;
    int n0 = (int)(ng * NV);
    if (n0 >= NN) return;

    float4 b4 = __ldg(reinterpret_cast<const float4*>(bias) + oq);
    float4 az[NV], as[NV];
#pragma unroll
    for (int i = 0; i < NV; i++) {
        az[i] = make_float4(0.f, 0.f, 0.f, 0.f);
        as[i] = b4;
    }

#pragma unroll
    for (int k = 0; k < DIN; k += 4) {
        float4 n0w = __ldg(reinterpret_cast<const float4*>(Wn + (size_t)(k + 0) * DOUT) + oq);
        float4 n1w = __ldg(reinterpret_cast<const float4*>(Wn + (size_t)(k + 1) * DOUT) + oq);
        float4 n2w = __ldg(reinterpret_cast<const float4*>(Wn + (size_t)(k + 2) * DOUT) + oq);
        float4 n3w = __ldg(reinterpret_cast<const float4*>(Wn + (size_t)(k + 3) * DOUT) + oq);
        float4 s0w = __ldg(reinterpret_cast<const float4*>(Ws + (size_t)(k + 0) * DOUT) + oq);
        float4 s1w = __ldg(reinterpret_cast<const float4*>(Ws + (size_t)(k + 1) * DOUT) + oq);
        float4 s2w = __ldg(reinterpret_cast<const float4*>(Ws + (size_t)(k + 2) * DOUT) + oq);
        float4 s3w = __ldg(reinterpret_cast<const float4*>(Ws + (size_t)(k + 3) * DOUT) + oq);
#pragma unroll
        for (int i = 0; i < NV; i++) {
            int node = min(n0 + i, NN - 1);
            float4 hv = __ldg(reinterpret_cast<const float4*>(h + (size_t)node * DIN) + (k >> 2));
            az[i].x = fmaf(hv.x, n0w.x, fmaf(hv.y, n1w.x, fmaf(hv.z, n2w.x, fmaf(hv.w, n3w.x, az[i].x))));
            az[i].y = fmaf(hv.x, n0w.y, fmaf(hv.y, n1w.y, fmaf(hv.z, n2w.y, fmaf(hv.w, n3w.y, az[i].y))));
            az[i].z = fmaf(hv.x, n0w.z, fmaf(hv.y, n1w.z, fmaf(hv.z, n2w.z, fmaf(hv.w, n3w.z, az[i].z))));
            az[i].w = fmaf(hv.x, n0w.w, fmaf(hv.y, n1w.w, fmaf(hv.z, n2w.w, fmaf(hv.w, n3w.w, az[i].w))));
            as[i].x = fmaf(hv.x, s0w.x, fmaf(hv.y, s1w.x, fmaf(hv.z, s2w.x, fmaf(hv.w, s3w.x, as[i].x))));
            as[i].y = fmaf(hv.x, s0w.y, fmaf(hv.y, s1w.y, fmaf(hv.z, s2w.y, fmaf(hv.w, s3w.y, as[i].y))));
            as[i].z = fmaf(hv.x, s0w.z, fmaf(hv.y, s1w.z, fmaf(hv.z, s2w.z, fmaf(hv.w, s3w.z, as[i].z))));
            as[i].w = fmaf(hv.x, s0w.w, fmaf(hv.y, s1w.w, fmaf(hv.z, s2w.w, fmaf(hv.w, s3w.w, as[i].w))));
        }
    }

#pragma unroll
    for (int i = 0; i < NV; i++) {
        if (n0 + i < NN) {
            reinterpret_cast<float4*>(z + (size_t)(n0 + i) * DOUT)[oq] = az[i];
            reinterpret_cast<float4*>(s + (size_t)(n0 + i) * DOUT)[oq] = as[i];
        }
    }
}

// scalar combined z/s for DOUT=5 (layer 3)
template <int DIN, int DOUT>
__global__ void k_zsS(const float* __restrict__ h, const float* __restrict__ Wn,
                      const float* __restrict__ Ws, const float* __restrict__ bias,
                      float* __restrict__ z, float* __restrict__ s) {
    long long idx = (long long)blockIdx.x * blockDim.x + threadIdx.x;
    if (idx >= (long long)NN * DOUT) return;
    int v = (int)(idx / DOUT);
    int o = (int)(idx % DOUT);
    const float* hrow = h + (size_t)v * DIN;
    float accz = 0.0f;
    float accs = bias[o];
#pragma unroll
    for (int k = 0; k < DIN; k++) {
        float hv = hrow[k];
        accz = fmaf(hv, Wn[k * DOUT + o], accz);
        accs = fmaf(hv, Ws[k * DOUT + o], accs);
    }
    z[idx] = accz;
    s[idx] = accs;
}

// Fused layer-0: out = relu( feat@Ws + agg@Wn + b ), DIN=32, DOUT=128
template <int NV>
__global__ void k_sage0(const float* __restrict__ feat, const float* __restrict__ agg,
                        const float* __restrict__ Ws, const float* __restrict__ Wn,
                        const float* __restrict__ bias, float* __restrict__ out) {
    constexpr int DIN = 32, DOUT = 128, OG = 32;
    long long t = (long long)blockIdx.x * blockDim.x + threadIdx.x;
    int oq = (int)(t % OG);
    long long ng = t / OG;
    int n0 = (int)(ng * NV);
    if (n0 >= NN) return;

    float4 b4 = __ldg(reinterpret_cast<const float4*>(bias) + oq);
    float4 acc[NV];
#pragma unroll
    for (int i = 0; i < NV; i++) acc[i] = b4;

#pragma unroll
    for (int k = 0; k < DIN; k += 4) {
        float4 ws0 = __ldg(reinterpret_cast<const float4*>(Ws + (size_t)(k + 0) * DOUT) + oq);
        float4 ws1 = __ldg(reinterpret_cast<const float4*>(Ws + (size_t)(k + 1) * DOUT) + oq);
        float4 ws2 = __ldg(reinterpret_cast<const float4*>(Ws + (size_t)(k + 2) * DOUT) + oq);
        float4 ws3 = __ldg(reinterpret_cast<const float4*>(Ws + (size_t)(k + 3) * DOUT) + oq);
        float4 wn0 = __ldg(reinterpret_cast<const float4*>(Wn + (size_t)(k + 0) * DOUT) + oq);
        float4 wn1 = __ldg(reinterpret_cast<const float4*>(Wn + (size_t)(k + 1) * DOUT) + oq);
        float4 wn2 = __ldg(reinterpret_cast<const float4*>(Wn + (size_t)(k + 2) * DOUT) + oq);
        float4 wn3 = __ldg(reinterpret_cast<const float4*>(Wn + (size_t)(k + 3) * DOUT) + oq);
#pragma unroll
        for (int i = 0; i < NV; i++) {
            int node = min(n0 + i, NN - 1);
            float4 hv = __ldg(reinterpret_cast<const float4*>(feat + (size_t)node * DIN) + (k >> 2));
            float4 av = __ldg(reinterpret_cast<const float4*>(agg + (size_t)node * DIN) + (k >> 2));
            acc[i].x = fmaf(hv.x, ws0.x, fmaf(hv.y, ws1.x, fmaf(hv.z, ws2.x, fmaf(hv.w, ws3.x, acc[i].x))));
            acc[i].y = fmaf(hv.x, ws0.y, fmaf(hv.y, ws1.y, fmaf(hv.z, ws2.y, fmaf(hv.w, ws3.y, acc[i].y))));
            acc[i].z = fmaf(hv.x, ws0.z, fmaf(hv.y, ws1.z, fmaf(hv.z, ws2.z, fmaf(hv.w, ws3.z, acc[i].z))));
            acc[i].w = fmaf(hv.x, ws0.w, fmaf(hv.y, ws1.w, fmaf(hv.z, ws2.w, fmaf(hv.w, ws3.w, acc[i].w))));
            acc[i].x = fmaf(av.x, wn0.x, fmaf(av.y, wn1.x, fmaf(av.z, wn2.x, fmaf(av.w, wn3.x, acc[i].x))));
            acc[i].y = fmaf(av.x, wn0.y, fmaf(av.y, wn1.y, fmaf(av.z, wn2.y, fmaf(av.w, wn3.y, acc[i].y))));
            acc[i].z = fmaf(av.x, wn0.z, fmaf(av.y, wn1.z, fmaf(av.z, wn2.z, fmaf(av.w, wn3.z, acc[i].z))));
            acc[i].w = fmaf(av.x, wn0.w, fmaf(av.y, wn1.w, fmaf(av.z, wn2.w, fmaf(av.w, wn3.w, acc[i].w))));
        }
    }

#pragma unroll
    for (int i = 0; i < NV; i++) {
        if (n0 + i < NN) {
            float4 r = acc[i];
            r.x = fmaxf(r.x, 0.f); r.y = fmaxf(r.y, 0.f);
            r.z = fmaxf(r.z, 0.f); r.w = fmaxf(r.w, 0.f);
            reinterpret_cast<float4*>(out + (size_t)(n0 + i) * DOUT)[oq] = r;
        }
    }
}

// ---------------------------------------------------------------------------
// warp-aggregated readout (gid sorted -> warps mostly single-graph)
__global__ void k_readout(const float* __restrict__ h, const int* __restrict__ gid,
                          float* __restrict__ out) {
    int v = blockIdx.x * blockDim.x + threadIdx.x;
    bool ok = (v < NN);
    int g = ok ? gid[v] : -1;
    float c = ok ? 1.0f : 0.0f;
    float f0 = 0, f1 = 0, f2 = 0, f3 = 0, f4 = 0;
    if (ok) {
        const float* hr = h + (size_t)v * 5;
        f0 = hr[0]; f1 = hr[1]; f2 = hr[2]; f3 = hr[3]; f4 = hr[4];
    }
    int g0 = __shfl_sync(0xFFFFFFFFu, ok ? g : __shfl_sync(0xFFFFFFFFu, g, 0), 0);
    bool uniform = __all_sync(0xFFFFFFFFu, !ok || g == g0);
    if (uniform) {
#pragma unroll
        for (int m = 16; m > 0; m >>= 1) {
            c  += __shfl_xor_sync(0xFFFFFFFFu, c, m);
            f0 += __shfl_xor_sync(0xFFFFFFFFu, f0, m);
            f1 += __shfl_xor_sync(0xFFFFFFFFu, f1, m);
            f2 += __shfl_xor_sync(0xFFFFFFFFu, f2, m);
            f3 += __shfl_xor_sync(0xFFFFFFFFu, f3, m);
            f4 += __shfl_xor_sync(0xFFFFFFFFu, f4, m);
        }
        if ((threadIdx.x & 31) == 0 && c > 0.0f) {
            atomicAdd(&g_cnt[g0], c);
            atomicAdd(&out[g0 * 5 + 0], f0);
            atomicAdd(&out[g0 * 5 + 1], f1);
            atomicAdd(&out[g0 * 5 + 2], f2);
            atomicAdd(&out[g0 * 5 + 3], f3);
            atomicAdd(&out[g0 * 5 + 4], f4);
        }
    } else if (ok) {
        atomicAdd(&g_cnt[g], 1.0f);
        atomicAdd(&out[g * 5 + 0], f0);
        atomicAdd(&out[g * 5 + 1], f1);
        atomicAdd(&out[g * 5 + 2], f2);
        atomicAdd(&out[g * 5 + 3], f3);
        atomicAdd(&out[g * 5 + 4], f4);
    }
}

__global__ void k_final(float* __restrict__ out) {
    int i = blockIdx.x * blockDim.x + threadIdx.x;
    if (i < NG * 5) out[i] /= fmaxf(g_cnt[i / 5], 1.0f);
}

// ---------------------------------------------------------------------------
static inline int blks(long long n, int t) { return (int)((n + t - 1) / t); }

extern "C" void kernel_launch(void* const* d_in, const int* in_sizes, int n_in,
                              void* d_out, int out_size) {
    const float* feat = (const float*)d_in[0];
    const int* src = (const int*)d_in[1];
    const int* dst = (const int*)d_in[2];
    const int* gid = (const int*)d_in[3];
    const float* Ws0 = (const float*)d_in[4];
    const float* Wn0 = (const float*)d_in[5];
    const float* b0  = (const float*)d_in[6];
    const float* Ws1 = (const float*)d_in[7];
    const float* Wn1 = (const float*)d_in[8];
    const float* b1  = (const float*)d_in[9];
    const float* Ws2 = (const float*)d_in[10];
    const float* Wn2 = (const float*)d_in[11];
    const float* b2  = (const float*)d_in[12];
    const float* Ws3 = (const float*)d_in[13];
    const float* Wn3 = (const float*)d_in[14];
    const float* b3  = (const float*)d_in[15];
    float* out = (float*)d_out;

    float *bufA, *bufB, *z, *s, *agg, *cnt;
    int *degi;
    cudaGetSymbolAddress((void**)&bufA, g_bufA);
    cudaGetSymbolAddress((void**)&bufB, g_bufB);
    cudaGetSymbolAddress((void**)&z, g_z);
    cudaGetSymbolAddress((void**)&s, g_s);
    cudaGetSymbolAddress((void**)&agg, g_agg);
    cudaGetSymbolAddress((void**)&cnt, g_cnt);
    cudaGetSymbolAddress((void**)&degi, g_degi);

    const int T = 256;

    // ---- CSR build (single atomic pass + atomic-free fill) ----
    cudaMemsetAsync(degi, 0, NN * sizeof(int));
    k_degrank<<<blks(NE, T), T>>>(dst);
    k_scan1<<<NB, 1024>>>();
    k_scan2<<<1, 256>>>();
    k_scan3<<<NB, 1024>>>();
    k_build<<<blks(NE, T), T>>>(src, dst);

    // ---- layer 0: 32 -> 128, relu ----
    k_gather4<32, 4><<<blks((long long)NN * 32, T), T>>>(feat, agg);
    {
        long long th = (long long)((NN + 3) / 4) * 32;
        k_sage0<4><<<blks(th, T), T>>>(feat, agg, Ws0, Wn0, b0, bufA);
    }

    // ---- layer 1: 128 -> 48, relu (combined zs + fused gather) ----
    {
        long long th = (long long)((NN + 3) / 4) * 12;
        k_zs<128, 48, 4><<<blks(th, T), T>>>(bufA, Wn1, Ws1, b1, z, s);
    }
    k_gatherF<48, 2, true><<<blks((long long)NN * 32, T), T>>>(z, s, bufB);

    // ---- layer 2: 48 -> 28, relu ----
    {
        long long th = (long long)((NN + 3) / 4) * 7;
        k_zs<48, 28, 4><<<blks(th, T), T>>>(bufB, Wn2, Ws2, b2, z, s);
    }
    k_gatherF<28, 4, true><<<blks((long long)NN * 32, T), T>>>(z, s, bufA);

    // ---- layer 3: 28 -> 5, linear ----
    k_zsS<28, 5><<<blks((long long)NN * 5, T), T>>>(bufA, Wn3, Ws3, b3, z, s);
    k_gatherF5<<<blks((long long)NN * 32, T), T>>>(z, s, bufB);

    // ---- readout ----
    cudaMemsetAsync(out, 0, NG * 5 * sizeof(float));
    cudaMemsetAsync(cnt, 0, NG * sizeof(float));
    k_readout<<<blks(NN, T), T>>>(bufB, gid, out);
    k_final<<<blks(NG * 5, T), T>>>(out);
}

// round 12
// speedup vs baseline: 1.3812x; 1.0062x over previous
#include <cuda_runtime.h>
#include <cuda_bf16.h>
#include <cuda_fp16.h>

static const int NN = 200000;
static const int NE = 3200000;
static const int NG = 400;
static const int NB = (NN + 1023) / 1024;  // 196 scan blocks

// Scratch (device globals; no runtime allocation allowed)
__device__ int    g_degi[NN];
__device__ int    g_off[NN + 1];
__device__ int    g_rank[NE];
__device__ int    g_csr[NE];
__device__ int    g_bsum[256];
__device__ float  g_bufA[(size_t)NN * 128];  // layer outputs (max 128)
__device__ float  g_bufB[(size_t)NN * 48];
__device__ __half g_feath[(size_t)NN * 32];  // fp16 copy of feat (gather operand)
__device__ __half g_zh[(size_t)NN * 48];     // fp16 projected neighbor features
__device__ float  g_z[(size_t)NN * 48];      // fp32 z for layer 3 (dim 5)
__device__ float  g_s[(size_t)NN * 48];      // self-projection + bias
__device__ float  g_agg[(size_t)NN * 32];    // layer-0 aggregate (fp32)
__device__ float  g_cnt[NG];

// ---------------------------------------------------------------------------
// degree + rank: one atomic pass records each edge's slot within its dst list
__global__ void k_degrank(const int* __restrict__ dst) {
    int e = blockIdx.x * blockDim.x + threadIdx.x;
    if (e < NE) g_rank[e] = atomicAdd(&g_degi[dst[e]], 1);
}

// ---- parallel exclusive scan of g_degi -> g_off ----
__global__ void k_scan1() {
    __shared__ int sh[1024];
    int t = threadIdx.x;
    int j = blockIdx.x * 1024 + t;
    sh[t] = (j < NN) ? g_degi[j] : 0;
    __syncthreads();
    for (int d = 512; d > 0; d >>= 1) {
        if (t < d) sh[t] += sh[t + d];
        __syncthreads();
    }
    if (t == 0) g_bsum[blockIdx.x] = sh[0];
}

__global__ void k_scan2() {
    __shared__ int sh[256];
    int t = threadIdx.x;
    int v = (t < NB) ? g_bsum[t] : 0;
    sh[t] = v;
    __syncthreads();
    for (int d = 1; d < 256; d <<= 1) {
        int x = (t >= d) ? sh[t - d] : 0;
        __syncthreads();
        sh[t] += x;
        __syncthreads();
    }
    g_bsum[t] = sh[t] - v;  // exclusive
}

__global__ void k_scan3() {
    __shared__ int sh[1024];
    int t = threadIdx.x;
    int j = blockIdx.x * 1024 + t;
    int v = (j < NN) ? g_degi[j] : 0;
    sh[t] = v;
    __syncthreads();
    for (int d = 1; d < 1024; d <<= 1) {
        int x = (t >= d) ? sh[t - d] : 0;
        __syncthreads();
        sh[t] += x;
        __syncthreads();
    }
    int excl = sh[t] - v + g_bsum[blockIdx.x];
    if (j < NN) g_off[j] = excl;
    if (j == NN - 1) g_off[NN] = excl + v;
}

// atomic-free CSR fill: csr[off[dst] + rank] = src
__global__ void k_build(const int* __restrict__ src, const int* __restrict__ dst) {
    int e = blockIdx.x * blockDim.x + threadIdx.x;
    if (e >= NE) return;
    int d = dst[e];
    g_csr[g_off[d] + g_rank[e]] = src[e];
}

// feat fp32 -> fp16 copy (gather operand for layer 0)
__global__ void k_cvtfeat(const float* __restrict__ f, __half* __restrict__ fh) {
    int i = blockIdx.x * blockDim.x + threadIdx.x;
    if (i >= NN * 32 / 4) return;
    float4 v = reinterpret_cast<const float4*>(f)[i];
    __half2 a = __floats2half2_rn(v.x, v.y);
    __half2 b = __floats2half2_rn(v.z, v.w);
    reinterpret_cast<uint2*>(fh)[i] =
        make_uint2(*reinterpret_cast<unsigned*>(&a), *reinterpret_cast<unsigned*>(&b));
}

// ---------------------------------------------------------------------------
// fp16 gather, uint4 chunks (8 halfs): DIM divisible by 8. Warp per node.
// out[v] = [relu]( [s[v] +] sum zh[nbr]/max(deg,1) )
template <int DIM, int SLOTS, bool FUSE, bool RELU>
__global__ void k_gatherH(const __half* __restrict__ zh, const float* __restrict__ s,
                          float* __restrict__ out) {
    constexpr int NCH = DIM / 8;
    constexpr int F4L = 32 / SLOTS;
    int gt = blockIdx.x * blockDim.x + threadIdx.x;
    int v = gt >> 5;
    if (v >= NN) return;
    int lane = gt & 31;
    int slot = lane / F4L;
    int f4 = lane % F4L;
    bool act = (f4 < NCH);

    int beg = g_off[v];
    int end = g_off[v + 1];
    float4 a0 = make_float4(0.f, 0.f, 0.f, 0.f);
    float4 a1 = make_float4(0.f, 0.f, 0.f, 0.f);

    int e = beg;
    for (; e + 2 * SLOTS <= end; e += 2 * SLOTS) {
        int s0 = g_csr[e + slot];
        int s1 = g_csr[e + SLOTS + slot];
        if (act) {
            uint4 t0 = __ldg(reinterpret_cast<const uint4*>(zh + (size_t)s0 * DIM) + f4);
            uint4 t1 = __ldg(reinterpret_cast<const uint4*>(zh + (size_t)s1 * DIM) + f4);
            __half2 p0 = __hadd2(*reinterpret_cast<__half2*>(&t0.x), *reinterpret_cast<__half2*>(&t1.x));
            __half2 p1 = __hadd2(*reinterpret_cast<__half2*>(&t0.y), *reinterpret_cast<__half2*>(&t1.y));
            __half2 p2 = __hadd2(*reinterpret_cast<__half2*>(&t0.z), *reinterpret_cast<__half2*>(&t1.z));
            __half2 p3 = __hadd2(*reinterpret_cast<__half2*>(&t0.w), *reinterpret_cast<__half2*>(&t1.w));
            float2 f0 = __half22float2(p0), f1 = __half22float2(p1);
            float2 f2 = __half22float2(p2), f3 = __half22float2(p3);
            a0.x += f0.x; a0.y += f0.y; a0.z += f1.x; a0.w += f1.y;
            a1.x += f2.x; a1.y += f2.y; a1.z += f3.x; a1.w += f3.y;
        }
    }
    for (; e < end; e += SLOTS) {
        int myE = e + slot;
        if (myE < end && act) {
            uint4 t0 = __ldg(reinterpret_cast<const uint4*>(zh + (size_t)g_csr[myE] * DIM) + f4);
            float2 f0 = __half22float2(*reinterpret_cast<__half2*>(&t0.x));
            float2 f1 = __half22float2(*reinterpret_cast<__half2*>(&t0.y));
            float2 f2 = __half22float2(*reinterpret_cast<__half2*>(&t0.z));
            float2 f3 = __half22float2(*reinterpret_cast<__half2*>(&t0.w));
            a0.x += f0.x; a0.y += f0.y; a0.z += f1.x; a0.w += f1.y;
            a1.x += f2.x; a1.y += f2.y; a1.z += f3.x; a1.w += f3.y;
        }
    }
#pragma unroll
    for (int m = F4L; m < 32; m <<= 1) {
        a0.x += __shfl_xor_sync(0xFFFFFFFFu, a0.x, m);
        a0.y += __shfl_xor_sync(0xFFFFFFFFu, a0.y, m);
        a0.z += __shfl_xor_sync(0xFFFFFFFFu, a0.z, m);
        a0.w += __shfl_xor_sync(0xFFFFFFFFu, a0.w, m);
        a1.x += __shfl_xor_sync(0xFFFFFFFFu, a1.x, m);
        a1.y += __shfl_xor_sync(0xFFFFFFFFu, a1.y, m);
        a1.z += __shfl_xor_sync(0xFFFFFFFFu, a1.z, m);
        a1.w += __shfl_xor_sync(0xFFFFFFFFu, a1.w, m);
    }
    float inv = 1.0f / fmaxf((float)(end - beg), 1.0f);
    if (slot == 0 && act) {
        float4 r0 = make_float4(a0.x * inv, a0.y * inv, a0.z * inv, a0.w * inv);
        float4 r1 = make_float4(a1.x * inv, a1.y * inv, a1.z * inv, a1.w * inv);
        float* dst = out + (size_t)v * DIM + f4 * 8;
        if (FUSE) {
            const float* sp = s + (size_t)v * DIM + f4 * 8;
            float4 s0v = *reinterpret_cast<const float4*>(sp);
            float4 s1v = *reinterpret_cast<const float4*>(sp + 4);
            r0.x += s0v.x; r0.y += s0v.y; r0.z += s0v.z; r0.w += s0v.w;
            r1.x += s1v.x; r1.y += s1v.y; r1.z += s1v.z; r1.w += s1v.w;
        }
        if (RELU) {
            r0.x = fmaxf(r0.x, 0.f); r0.y = fmaxf(r0.y, 0.f);
            r0.z = fmaxf(r0.z, 0.f); r0.w = fmaxf(r0.w, 0.f);
            r1.x = fmaxf(r1.x, 0.f); r1.y = fmaxf(r1.y, 0.f);
            r1.z = fmaxf(r1.z, 0.f); r1.w = fmaxf(r1.w, 0.f);
        }
        *reinterpret_cast<float4*>(dst) = r0;
        *reinterpret_cast<float4*>(dst + 4) = r1;
    }
}

// fp16 gather, uint2 chunks (4 halfs): for DIM=28. Warp per node, fused epilogue.
template <int DIM, int SLOTS, bool RELU>
__global__ void k_gatherH2(const __half* __restrict__ zh, const float* __restrict__ s,
                           float* __restrict__ out) {
    constexpr int NCH = DIM / 4;
    constexpr int F4L = 32 / SLOTS;
    int gt = blockIdx.x * blockDim.x + threadIdx.x;
    int v = gt >> 5;
    if (v >= NN) return;
    int lane = gt & 31;
    int slot = lane / F4L;
    int f4 = lane % F4L;
    bool act = (f4 < NCH);

    int beg = g_off[v];
    int end = g_off[v + 1];
    float4 a0 = make_float4(0.f, 0.f, 0.f, 0.f);

    int e = beg;
    for (; e + 2 * SLOTS <= end; e += 2 * SLOTS) {
        int s0 = g_csr[e + slot];
        int s1 = g_csr[e + SLOTS + slot];
        if (act) {
            uint2 t0 = __ldg(reinterpret_cast<const uint2*>(zh + (size_t)s0 * DIM) + f4);
            uint2 t1 = __ldg(reinterpret_cast<const uint2*>(zh + (size_t)s1 * DIM) + f4);
            __half2 p0 = __hadd2(*reinterpret_cast<__half2*>(&t0.x), *reinterpret_cast<__half2*>(&t1.x));
            __half2 p1 = __hadd2(*reinterpret_cast<__half2*>(&t0.y), *reinterpret_cast<__half2*>(&t1.y));
            float2 f0 = __half22float2(p0), f1 = __half22float2(p1);
            a0.x += f0.x; a0.y += f0.y; a0.z += f1.x; a0.w += f1.y;
        }
    }
    for (; e < end; e += SLOTS) {
        int myE = e + slot;
        if (myE < end && act) {
            uint2 t0 = __ldg(reinterpret_cast<const uint2*>(zh + (size_t)g_csr[myE] * DIM) + f4);
            float2 f0 = __half22float2(*reinterpret_cast<__half2*>(&t0.x));
            float2 f1 = __half22float2(*reinterpret_cast<__half2*>(&t0.y));
            a0.x += f0.x; a0.y += f0.y; a0.z += f1.x; a0.w += f1.y;
        }
    }
#pragma unroll
    for (int m = F4L; m < 32; m <<= 1) {
        a0.x += __shfl_xor_sync(0xFFFFFFFFu, a0.x, m);
        a0.y += __shfl_xor_sync(0xFFFFFFFFu, a0.y, m);
        a0.z += __shfl_xor_sync(0xFFFFFFFFu, a0.z, m);
        a0.w += __shfl_xor_sync(0xFFFFFFFFu, a0.w, m);
    }
    float inv = 1.0f / fmaxf((float)(end - beg), 1.0f);
    if (slot == 0 && act) {
        const float* sp = s + (size_t)v * DIM + f4 * 4;
        float4 sv = *reinterpret_cast<const float4*>(sp);
        float4 r = make_float4(sv.x + a0.x * inv, sv.y + a0.y * inv,
                               sv.z + a0.z * inv, sv.w + a0.w * inv);
        if (RELU) {
            r.x = fmaxf(r.x, 0.f); r.y = fmaxf(r.y, 0.f);
            r.z = fmaxf(r.z, 0.f); r.w = fmaxf(r.w, 0.f);
        }
        *reinterpret_cast<float4*>(out + (size_t)v * DIM + f4 * 4) = r;
    }
}

// fused scalar gather for DIM=5 (layer 3, fp32 z, no relu)
__global__ void k_gatherF5(const float* __restrict__ z, const float* __restrict__ s,
                           float* __restrict__ out) {
    constexpr int DIM = 5;
    int gt = blockIdx.x * blockDim.x + threadIdx.x;
    int v = gt >> 5;
    if (v >= NN) return;
    int lane = gt & 31;
    int slot = lane >> 3;
    int f = lane & 7;
    bool act = (f < DIM);

    int beg = g_off[v];
    int end = g_off[v + 1];
    float acc = 0.0f;
    int e = beg;
    for (; e + 8 <= end; e += 8) {
        int s0 = g_csr[e + slot];
        int s1 = g_csr[e + 4 + slot];
        if (act) acc += z[(size_t)s0 * DIM + f] + z[(size_t)s1 * DIM + f];
    }
    for (; e < end; e += 4) {
        int myE = e + slot;
        if (myE < end && act) acc += z[(size_t)g_csr[myE] * DIM + f];
    }
#pragma unroll
    for (int m = 8; m < 32; m <<= 1) acc += __shfl_xor_sync(0xFFFFFFFFu, acc, m);
    float inv = 1.0f / fmaxf((float)(end - beg), 1.0f);
    if (slot == 0 && act)
        out[(size_t)v * DIM + f] = s[(size_t)v * DIM + f] + acc * inv;
}

// ---------------------------------------------------------------------------
// Combined z/s projection, half z output: zh = half(h@Wn) ; s = h@Ws + b.
template <int DIN, int DOUT, int NV>
__global__ void k_zsH(const float* __restrict__ h, const float* __restrict__ Wn,
                      const float* __restrict__ Ws, const float* __restrict__ bias,
                      __half* __restrict__ zh, float* __restrict__ s) {
    constexpr int OG = DOUT / 4;
    long long t = (long long)blockIdx.x * blockDim.x + threadIdx.x;
    int oq = (int)(t % OG);
    long long ng = t / OG;
    int n0 = (int)(ng * NV);
    if (n0 >= NN) return;

    float4 b4 = __ldg(reinterpret_cast<const float4*>(bias) + oq);
    float4 az[NV], as[NV];
#pragma unroll
    for (int i = 0; i < NV; i++) {
        az[i] = make_float4(0.f, 0.f, 0.f, 0.f);
        as[i] = b4;
    }

#pragma unroll
    for (int k = 0; k < DIN; k += 4) {
        float4 n0w = __ldg(reinterpret_cast<const float4*>(Wn + (size_t)(k + 0) * DOUT) + oq);
        float4 n1w = __ldg(reinterpret_cast<const float4*>(Wn + (size_t)(k + 1) * DOUT) + oq);
        float4 n2w = __ldg(reinterpret_cast<const float4*>(Wn + (size_t)(k + 2) * DOUT) + oq);
        float4 n3w = __ldg(reinterpret_cast<const float4*>(Wn + (size_t)(k + 3) * DOUT) + oq);
        float4 s0w = __ldg(reinterpret_cast<const float4*>(Ws + (size_t)(k + 0) * DOUT) + oq);
        float4 s1w = __ldg(reinterpret_cast<const float4*>(Ws + (size_t)(k + 1) * DOUT) + oq);
        float4 s2w = __ldg(reinterpret_cast<const float4*>(Ws + (size_t)(k + 2) * DOUT) + oq);
        float4 s3w = __ldg(reinterpret_cast<const float4*>(Ws + (size_t)(k + 3) * DOUT) + oq);
#pragma unroll
        for (int i = 0; i < NV; i++) {
            int node = min(n0 + i, NN - 1);
            float4 hv = __ldg(reinterpret_cast<const float4*>(h + (size_t)node * DIN) + (k >> 2));
            az[i].x = fmaf(hv.x, n0w.x, fmaf(hv.y, n1w.x, fmaf(hv.z, n2w.x, fmaf(hv.w, n3w.x, az[i].x))));
            az[i].y = fmaf(hv.x, n0w.y, fmaf(hv.y, n1w.y, fmaf(hv.z, n2w.y, fmaf(hv.w, n3w.y, az[i].y))));
            az[i].z = fmaf(hv.x, n0w.z, fmaf(hv.y, n1w.z, fmaf(hv.z, n2w.z, fmaf(hv.w, n3w.z, az[i].z))));
            az[i].w = fmaf(hv.x, n0w.w, fmaf(hv.y, n1w.w, fmaf(hv.z, n2w.w, fmaf(hv.w, n3w.w, az[i].w))));
            as[i].x = fmaf(hv.x, s0w.x, fmaf(hv.y, s1w.x, fmaf(hv.z, s2w.x, fmaf(hv.w, s3w.x, as[i].x))));
            as[i].y = fmaf(hv.x, s0w.y, fmaf(hv.y, s1w.y, fmaf(hv.z, s2w.y, fmaf(hv.w, s3w.y, as[i].y))));
            as[i].z = fmaf(hv.x, s0w.z, fmaf(hv.y, s1w.z, fmaf(hv.z, s2w.z, fmaf(hv.w, s3w.z, as[i].z))));
            as[i].w = fmaf(hv.x, s0w.w, fmaf(hv.y, s1w.w, fmaf(hv.z, s2w.w, fmaf(hv.w, s3w.w, as[i].w))));
        }
    }

#pragma unroll
    for (int i = 0; i < NV; i++) {
        if (n0 + i < NN) {
            __half2 h01 = __floats2half2_rn(az[i].x, az[i].y);
            __half2 h23 = __floats2half2_rn(az[i].z, az[i].w);
            reinterpret_cast<uint2*>(zh + (size_t)(n0 + i) * DOUT)[oq] =
                make_uint2(*reinterpret_cast<unsigned*>(&h01), *reinterpret_cast<unsigned*>(&h23));
            reinterpret_cast<float4*>(s + (size_t)(n0 + i) * DOUT)[oq] = as[i];
        }
    }
}

// scalar combined z/s for DOUT=5 (layer 3, fp32)
template <int DIN, int DOUT>
__global__ void k_zsS(const float* __restrict__ h, const float* __restrict__ Wn,
                      const float* __restrict__ Ws, const float* __restrict__ bias,
                      float* __restrict__ z, float* __restrict__ s) {
    long long idx = (long long)blockIdx.x * blockDim.x + threadIdx.x;
    if (idx >= (long long)NN * DOUT) return;
    int v = (int)(idx / DOUT);
    int o = (int)(idx % DOUT);
    const float* hrow = h + (size_t)v * DIN;
    float accz = 0.0f;
    float accs = bias[o];
#pragma unroll
    for (int k = 0; k < DIN; k++) {
        float hv = hrow[k];
        accz = fmaf(hv, Wn[k * DOUT + o], accz);
        accs = fmaf(hv, Ws[k * DOUT + o], accs);
    }
    z[idx] = accz;
    s[idx] = accs;
}

// Fused layer-0: out = relu( feat@Ws + agg@Wn + b ), DIN=32, DOUT=128
template <int NV>
__global__ void k_sage0(const float* __restrict__ feat, const float* __restrict__ agg,
                        const float* __restrict__ Ws, const float* __restrict__ Wn,
                        const float* __restrict__ bias, float* __restrict__ out) {
    constexpr int DIN = 32, DOUT = 128, OG = 32;
    long long t = (long long)blockIdx.x * blockDim.x + threadIdx.x;
    int oq = (int)(t % OG);
    long long ng = t / OG;
    int n0 = (int)(ng * NV);
    if (n0 >= NN) return;

    float4 b4 = __ldg(reinterpret_cast<const float4*>(bias) + oq);
    float4 acc[NV];
#pragma unroll
    for (int i = 0; i < NV; i++) acc[i] = b4;

#pragma unroll
    for (int k = 0; k < DIN; k += 4) {
        float4 ws0 = __ldg(reinterpret_cast<const float4*>(Ws + (size_t)(k + 0) * DOUT) + oq);
        float4 ws1 = __ldg(reinterpret_cast<const float4*>(Ws + (size_t)(k + 1) * DOUT) + oq);
        float4 ws2 = __ldg(reinterpret_cast<const float4*>(Ws + (size_t)(k + 2) * DOUT) + oq);
        float4 ws3 = __ldg(reinterpret_cast<const float4*>(Ws + (size_t)(k + 3) * DOUT) + oq);
        float4 wn0 = __ldg(reinterpret_cast<const float4*>(Wn + (size_t)(k + 0) * DOUT) + oq);
        float4 wn1 = __ldg(reinterpret_cast<const float4*>(Wn + (size_t)(k + 1) * DOUT) + oq);
        float4 wn2 = __ldg(reinterpret_cast<const float4*>(Wn + (size_t)(k + 2) * DOUT) + oq);
        float4 wn3 = __ldg(reinterpret_cast<const float4*>(Wn + (size_t)(k + 3) * DOUT) + oq);
#pragma unroll
        for (int i = 0; i < NV; i++) {
            int node = min(n0 + i, NN - 1);
            float4 hv = __ldg(reinterpret_cast<const float4*>(feat + (size_t)node * DIN) + (k >> 2));
            float4 av = __ldg(reinterpret_cast<const float4*>(agg + (size_t)node * DIN) + (k >> 2));
            acc[i].x = fmaf(hv.x, ws0.x, fmaf(hv.y, ws1.x, fmaf(hv.z, ws2.x, fmaf(hv.w, ws3.x, acc[i].x))));
            acc[i].y = fmaf(hv.x, ws0.y, fmaf(hv.y, ws1.y, fmaf(hv.z, ws2.y, fmaf(hv.w, ws3.y, acc[i].y))));
            acc[i].z = fmaf(hv.x, ws0.z, fmaf(hv.y, ws1.z, fmaf(hv.z, ws2.z, fmaf(hv.w, ws3.z, acc[i].z))));
            acc[i].w = fmaf(hv.x, ws0.w, fmaf(hv.y, ws1.w, fmaf(hv.z, ws2.w, fmaf(hv.w, ws3.w, acc[i].w))));
            acc[i].x = fmaf(av.x, wn0.x, fmaf(av.y, wn1.x, fmaf(av.z, wn2.x, fmaf(av.w, wn3.x, acc[i].x))));
            acc[i].y = fmaf(av.x, wn0.y, fmaf(av.y, wn1.y, fmaf(av.z, wn2.y, fmaf(av.w, wn3.y, acc[i].y))));
            acc[i].z = fmaf(av.x, wn0.z, fmaf(av.y, wn1.z, fmaf(av.z, wn2.z, fmaf(av.w, wn3.z, acc[i].z))));
            acc[i].w = fmaf(av.x, wn0.w, fmaf(av.y, wn1.w, fmaf(av.z, wn2.w, fmaf(av.w, wn3.w, acc[i].w))));
        }
    }

#pragma unroll
    for (int i = 0; i < NV; i++) {
        if (n0 + i < NN) {
            float4 r = acc[i];
            r.x = fmaxf(r.x, 0.f); r.y = fmaxf(r.y, 0.f);
            r.z = fmaxf(r.z, 0.f); r.w = fmaxf(r.w, 0.f);
            reinterpret_cast<float4*>(out + (size_t)(n0 + i) * DOUT)[oq] = r;
        }
    }
}

// ---------------------------------------------------------------------------
// warp-aggregated readout (gid sorted -> warps mostly single-graph)
__global__ void k_readout(const float* __restrict__ h, const int* __restrict__ gid,
                          float* __restrict__ out) {
    int v = blockIdx.x * blockDim.x + threadIdx.x;
    bool ok = (v < NN);
    int g = ok ? gid[v] : -1;
    float c = ok ? 1.0f : 0.0f;
    float f0 = 0, f1 = 0, f2 = 0, f3 = 0, f4 = 0;
    if (ok) {
        const float* hr = h + (size_t)v * 5;
        f0 = hr[0]; f1 = hr[1]; f2 = hr[2]; f3 = hr[3]; f4 = hr[4];
    }
    int g0 = __shfl_sync(0xFFFFFFFFu, ok ? g : __shfl_sync(0xFFFFFFFFu, g, 0), 0);
    bool uniform = __all_sync(0xFFFFFFFFu, !ok || g == g0);
    if (uniform) {
#pragma unroll
        for (int m = 16; m > 0; m >>= 1) {
            c  += __shfl_xor_sync(0xFFFFFFFFu, c, m);
            f0 += __shfl_xor_sync(0xFFFFFFFFu, f0, m);
            f1 += __shfl_xor_sync(0xFFFFFFFFu, f1, m);
            f2 += __shfl_xor_sync(0xFFFFFFFFu, f2, m);
            f3 += __shfl_xor_sync(0xFFFFFFFFu, f3, m);
            f4 += __shfl_xor_sync(0xFFFFFFFFu, f4, m);
        }
        if ((threadIdx.x & 31) == 0 && c > 0.0f) {
            atomicAdd(&g_cnt[g0], c);
            atomicAdd(&out[g0 * 5 + 0], f0);
            atomicAdd(&out[g0 * 5 + 1], f1);
            atomicAdd(&out[g0 * 5 + 2], f2);
            atomicAdd(&out[g0 * 5 + 3], f3);
            atomicAdd(&out[g0 * 5 + 4], f4);
        }
    } else if (ok) {
        atomicAdd(&g_cnt[g], 1.0f);
        atomicAdd(&out[g * 5 + 0], f0);
        atomicAdd(&out[g * 5 + 1], f1);
        atomicAdd(&out[g * 5 + 2], f2);
        atomicAdd(&out[g * 5 + 3], f3);
        atomicAdd(&out[g * 5 + 4], f4);
    }
}

__global__ void k_final(float* __restrict__ out) {
    int i = blockIdx.x * blockDim.x + threadIdx.x;
    if (i < NG * 5) out[i] /= fmaxf(g_cnt[i / 5], 1.0f);
}

// ---------------------------------------------------------------------------
static inline int blks(long long n, int t) { return (int)((n + t - 1) / t); }

extern "C" void kernel_launch(void* const* d_in, const int* in_sizes, int n_in,
                              void* d_out, int out_size) {
    const float* feat = (const float*)d_in[0];
    const int* src = (const int*)d_in[1];
    const int* dst = (const int*)d_in[2];
    const int* gid = (const int*)d_in[3];
    const float* Ws0 = (const float*)d_in[4];
    const float* Wn0 = (const float*)d_in[5];
    const float* b0  = (const float*)d_in[6];
    const float* Ws1 = (const float*)d_in[7];
    const float* Wn1 = (const float*)d_in[8];
    const float* b1  = (const float*)d_in[9];
    const float* Ws2 = (const float*)d_in[10];
    const float* Wn2 = (const float*)d_in[11];
    const float* b2  = (const float*)d_in[12];
    const float* Ws3 = (const float*)d_in[13];
    const float* Wn3 = (const float*)d_in[14];
    const float* b3  = (const float*)d_in[15];
    float* out = (float*)d_out;

    float *bufA, *bufB, *z, *s, *agg, *cnt;
    __half *feath, *zh;
    int *degi;
    cudaGetSymbolAddress((void**)&bufA, g_bufA);
    cudaGetSymbolAddress((void**)&bufB, g_bufB);
    cudaGetSymbolAddress((void**)&z, g_z);
    cudaGetSymbolAddress((void**)&s, g_s);
    cudaGetSymbolAddress((void**)&agg, g_agg);
    cudaGetSymbolAddress((void**)&cnt, g_cnt);
    cudaGetSymbolAddress((void**)&degi, g_degi);
    cudaGetSymbolAddress((void**)&feath, g_feath);
    cudaGetSymbolAddress((void**)&zh, g_zh);

    const int T = 256;

    // ---- CSR build (single atomic pass + atomic-free fill) ----
    cudaMemsetAsync(degi, 0, NN * sizeof(int));
    k_degrank<<<blks(NE, T), T>>>(dst);
    k_scan1<<<NB, 1024>>>();
    k_scan2<<<1, 256>>>();
    k_scan3<<<NB, 1024>>>();
    k_build<<<blks(NE, T), T>>>(src, dst);

    // ---- feat -> fp16 copy (gather operand) ----
    k_cvtfeat<<<blks((long long)NN * 8, T), T>>>(feat, feath);

    // ---- layer 0: 32 -> 128, relu ----
    k_gatherH<32, 8, false, false><<<blks((long long)NN * 32, T), T>>>(feath, nullptr, agg);
    {
        long long th = (long long)((NN + 3) / 4) * 32;
        k_sage0<4><<<blks(th, T), T>>>(feat, agg, Ws0, Wn0, b0, bufA);
    }

    // ---- layer 1: 128 -> 48, relu (zs with half z + fused gather) ----
    {
        long long th = (long long)((NN + 3) / 4) * 12;
        k_zsH<128, 48, 4><<<blks(th, T), T>>>(bufA, Wn1, Ws1, b1, zh, s);
    }
    k_gatherH<48, 4, true, true><<<blks((long long)NN * 32, T), T>>>(zh, s, bufB);

    // ---- layer 2: 48 -> 28, relu ----
    {
        long long th = (long long)((NN + 3) / 4) * 7;
        k_zsH<48, 28, 4><<<blks(th, T), T>>>(bufB, Wn2, Ws2, b2, zh, s);
    }
    k_gatherH2<28, 4, true><<<blks((long long)NN * 32, T), T>>>(zh, s, bufA);

    // ---- layer 3: 28 -> 5, linear (fp32) ----
    k_zsS<28, 5><<<blks((long long)NN * 5, T), T>>>(bufA, Wn3, Ws3, b3, z, s);
    k_gatherF5<<<blks((long long)NN * 32, T), T>>>(z, s, bufB);

    // ---- readout ----
    cudaMemsetAsync(out, 0, NG * 5 * sizeof(float));
    cudaMemsetAsync(cnt, 0, NG * sizeof(float));
    k_readout<<<blks(NN, T), T>>>(bufB, gid, out);
    k_final<<<blks(NG * 5, T), T>>>(out);
}

// round 13
// speedup vs baseline: 1.6831x; 1.2186x over previous
#include <cuda_runtime.h>
#include <cuda_bf16.h>
#include <cuda_fp16.h>

static const int NN = 200000;
static const int NE = 3200000;
static const int NG = 400;
static const int NB = (NN + 1023) / 1024;  // 196 scan blocks

// Scratch (device globals; no runtime allocation allowed)
__device__ int    g_degi[NN];
__device__ int    g_off[NN + 1];
__device__ int    g_rank[NE];
__device__ int    g_csr[NE];
__device__ int    g_bsum[256];
__device__ __half g_bufAh[(size_t)NN * 128];  // layer0 output (fp16, mma operand)
__device__ float  g_bufB[(size_t)NN * 48];    // layer1 output (fp32)
__device__ float  g_bufC[(size_t)NN * 28];    // layer2 output (fp32)
__device__ __half g_feath[(size_t)NN * 32];   // fp16 copy of feat
__device__ __half g_aggh[(size_t)NN * 32];    // fp16 layer-0 aggregate
__device__ __half g_zh[(size_t)NN * 48];      // fp16 projected neighbor features
__device__ float  g_z[(size_t)NN * 48];       // fp32 z for layer 3
__device__ float  g_s[(size_t)NN * 48];       // self-projection + bias
__device__ __half g_WsT0[128 * 32];           // transposed fp16 weights [N][K]
__device__ __half g_WnT0[128 * 32];
__device__ __half g_WsT1[48 * 128];
__device__ __half g_WnT1[48 * 128];
__device__ float  g_cnt[NG];

// ---------------------------------------------------------------------------
__global__ void k_degrank(const int* __restrict__ dst) {
    int e = blockIdx.x * blockDim.x + threadIdx.x;
    if (e < NE) g_rank[e] = atomicAdd(&g_degi[dst[e]], 1);
}

__global__ void k_scan1() {
    __shared__ int sh[1024];
    int t = threadIdx.x;
    int j = blockIdx.x * 1024 + t;
    sh[t] = (j < NN) ? g_degi[j] : 0;
    __syncthreads();
    for (int d = 512; d > 0; d >>= 1) {
        if (t < d) sh[t] += sh[t + d];
        __syncthreads();
    }
    if (t == 0) g_bsum[blockIdx.x] = sh[0];
}

__global__ void k_scan2() {
    __shared__ int sh[256];
    int t = threadIdx.x;
    int v = (t < NB) ? g_bsum[t] : 0;
    sh[t] = v;
    __syncthreads();
    for (int d = 1; d < 256; d <<= 1) {
        int x = (t >= d) ? sh[t - d] : 0;
        __syncthreads();
        sh[t] += x;
        __syncthreads();
    }
    g_bsum[t] = sh[t] - v;
}

__global__ void k_scan3() {
    __shared__ int sh[1024];
    int t = threadIdx.x;
    int j = blockIdx.x * 1024 + t;
    int v = (j < NN) ? g_degi[j] : 0;
    sh[t] = v;
    __syncthreads();
    for (int d = 1; d < 1024; d <<= 1) {
        int x = (t >= d) ? sh[t - d] : 0;
        __syncthreads();
        sh[t] += x;
        __syncthreads();
    }
    int excl = sh[t] - v + g_bsum[blockIdx.x];
    if (j < NN) g_off[j] = excl;
    if (j == NN - 1) g_off[NN] = excl + v;
}

__global__ void k_build(const int* __restrict__ src, const int* __restrict__ dst) {
    int e = blockIdx.x * blockDim.x + threadIdx.x;
    if (e >= NE) return;
    int d = dst[e];
    g_csr[g_off[d] + g_rank[e]] = src[e];
}

// feat fp32 -> fp16
__global__ void k_cvtfeat(const float* __restrict__ f, __half* __restrict__ fh) {
    int i = blockIdx.x * blockDim.x + threadIdx.x;
    if (i >= NN * 32 / 4) return;
    float4 v = reinterpret_cast<const float4*>(f)[i];
    __half2 a = __floats2half2_rn(v.x, v.y);
    __half2 b = __floats2half2_rn(v.z, v.w);
    reinterpret_cast<uint2*>(fh)[i] =
        make_uint2(*reinterpret_cast<unsigned*>(&a), *reinterpret_cast<unsigned*>(&b));
}

// weight [K][N] fp32 -> transposed fp16 [N][K]
template <int DIN, int DOUT>
__global__ void k_cvtWT(const float* __restrict__ W, __half* __restrict__ WT) {
    int i = blockIdx.x * blockDim.x + threadIdx.x;
    if (i >= DIN * DOUT) return;
    int k = i / DOUT;
    int o = i % DOUT;
    WT[o * DIN + k] = __float2half(W[i]);
}

// ---------------------------------------------------------------------------
// fp16 gather for layer 0 (DIM=32, 8 slots), fp16 output (mma operand)
__global__ void k_gather32H(const __half* __restrict__ zh, __half* __restrict__ aggh) {
    constexpr int DIM = 32, SLOTS = 8;
    constexpr int NCH = DIM / 8;      // 4 uint4 chunks
    constexpr int F4L = 32 / SLOTS;   // 4 lanes per slot
    int gt = blockIdx.x * blockDim.x + threadIdx.x;
    int v = gt >> 5;
    if (v >= NN) return;
    int lane = gt & 31;
    int slot = lane / F4L;
    int f4 = lane % F4L;
    bool act = (f4 < NCH);

    int beg = g_off[v];
    int end = g_off[v + 1];
    float4 a0 = make_float4(0.f, 0.f, 0.f, 0.f);
    float4 a1 = make_float4(0.f, 0.f, 0.f, 0.f);

    int e = beg;
    for (; e + 2 * SLOTS <= end; e += 2 * SLOTS) {
        int s0 = g_csr[e + slot];
        int s1 = g_csr[e + SLOTS + slot];
        if (act) {
            uint4 t0 = __ldg(reinterpret_cast<const uint4*>(zh + (size_t)s0 * DIM) + f4);
            uint4 t1 = __ldg(reinterpret_cast<const uint4*>(zh + (size_t)s1 * DIM) + f4);
            __half2 p0 = __hadd2(*reinterpret_cast<__half2*>(&t0.x), *reinterpret_cast<__half2*>(&t1.x));
            __half2 p1 = __hadd2(*reinterpret_cast<__half2*>(&t0.y), *reinterpret_cast<__half2*>(&t1.y));
            __half2 p2 = __hadd2(*reinterpret_cast<__half2*>(&t0.z), *reinterpret_cast<__half2*>(&t1.z));
            __half2 p3 = __hadd2(*reinterpret_cast<__half2*>(&t0.w), *reinterpret_cast<__half2*>(&t1.w));
            float2 f0 = __half22float2(p0), f1 = __half22float2(p1);
            float2 f2 = __half22float2(p2), f3 = __half22float2(p3);
            a0.x += f0.x; a0.y += f0.y; a0.z += f1.x; a0.w += f1.y;
            a1.x += f2.x; a1.y += f2.y; a1.z += f3.x; a1.w += f3.y;
        }
    }
    for (; e < end; e += SLOTS) {
        int myE = e + slot;
        if (myE < end && act) {
            uint4 t0 = __ldg(reinterpret_cast<const uint4*>(zh + (size_t)g_csr[myE] * DIM) + f4);
            float2 f0 = __half22float2(*reinterpret_cast<__half2*>(&t0.x));
            float2 f1 = __half22float2(*reinterpret_cast<__half2*>(&t0.y));
            float2 f2 = __half22float2(*reinterpret_cast<__half2*>(&t0.z));
            float2 f3 = __half22float2(*reinterpret_cast<__half2*>(&t0.w));
            a0.x += f0.x; a0.y += f0.y; a0.z += f1.x; a0.w += f1.y;
            a1.x += f2.x; a1.y += f2.y; a1.z += f3.x; a1.w += f3.y;
        }
    }
#pragma unroll
    for (int m = F4L; m < 32; m <<= 1) {
        a0.x += __shfl_xor_sync(0xFFFFFFFFu, a0.x, m);
        a0.y += __shfl_xor_sync(0xFFFFFFFFu, a0.y, m);
        a0.z += __shfl_xor_sync(0xFFFFFFFFu, a0.z, m);
        a0.w += __shfl_xor_sync(0xFFFFFFFFu, a0.w, m);
        a1.x += __shfl_xor_sync(0xFFFFFFFFu, a1.x, m);
        a1.y += __shfl_xor_sync(0xFFFFFFFFu, a1.y, m);
        a1.z += __shfl_xor_sync(0xFFFFFFFFu, a1.z, m);
        a1.w += __shfl_xor_sync(0xFFFFFFFFu, a1.w, m);
    }
    float inv = 1.0f / fmaxf((float)(end - beg), 1.0f);
    if (slot == 0 && act) {
        __half2 h0 = __floats2half2_rn(a0.x * inv, a0.y * inv);
        __half2 h1 = __floats2half2_rn(a0.z * inv, a0.w * inv);
        __half2 h2 = __floats2half2_rn(a1.x * inv, a1.y * inv);
        __half2 h3 = __floats2half2_rn(a1.z * inv, a1.w * inv);
        reinterpret_cast<uint4*>(aggh + (size_t)v * DIM)[f4] =
            make_uint4(*reinterpret_cast<unsigned*>(&h0), *reinterpret_cast<unsigned*>(&h1),
                       *reinterpret_cast<unsigned*>(&h2), *reinterpret_cast<unsigned*>(&h3));
    }
}

// fp16 gather, uint4 chunks, fused fp32 epilogue (layer 1, DIM=48)
template <int DIM, int SLOTS, bool RELU>
__global__ void k_gatherH(const __half* __restrict__ zh, const float* __restrict__ s,
                          float* __restrict__ out) {
    constexpr int NCH = DIM / 8;
    constexpr int F4L = 32 / SLOTS;
    int gt = blockIdx.x * blockDim.x + threadIdx.x;
    int v = gt >> 5;
    if (v >= NN) return;
    int lane = gt & 31;
    int slot = lane / F4L;
    int f4 = lane % F4L;
    bool act = (f4 < NCH);

    int beg = g_off[v];
    int end = g_off[v + 1];
    float4 a0 = make_float4(0.f, 0.f, 0.f, 0.f);
    float4 a1 = make_float4(0.f, 0.f, 0.f, 0.f);

    int e = beg;
    for (; e + 2 * SLOTS <= end; e += 2 * SLOTS) {
        int s0 = g_csr[e + slot];
        int s1 = g_csr[e + SLOTS + slot];
        if (act) {
            uint4 t0 = __ldg(reinterpret_cast<const uint4*>(zh + (size_t)s0 * DIM) + f4);
            uint4 t1 = __ldg(reinterpret_cast<const uint4*>(zh + (size_t)s1 * DIM) + f4);
            __half2 p0 = __hadd2(*reinterpret_cast<__half2*>(&t0.x), *reinterpret_cast<__half2*>(&t1.x));
            __half2 p1 = __hadd2(*reinterpret_cast<__half2*>(&t0.y), *reinterpret_cast<__half2*>(&t1.y));
            __half2 p2 = __hadd2(*reinterpret_cast<__half2*>(&t0.z), *reinterpret_cast<__half2*>(&t1.z));
            __half2 p3 = __hadd2(*reinterpret_cast<__half2*>(&t0.w), *reinterpret_cast<__half2*>(&t1.w));
            float2 f0 = __half22float2(p0), f1 = __half22float2(p1);
            float2 f2 = __half22float2(p2), f3 = __half22float2(p3);
            a0.x += f0.x; a0.y += f0.y; a0.z += f1.x; a0.w += f1.y;
            a1.x += f2.x; a1.y += f2.y; a1.z += f3.x; a1.w += f3.y;
        }
    }
    for (; e < end; e += SLOTS) {
        int myE = e + slot;
        if (myE < end && act) {
            uint4 t0 = __ldg(reinterpret_cast<const uint4*>(zh + (size_t)g_csr[myE] * DIM) + f4);
            float2 f0 = __half22float2(*reinterpret_cast<__half2*>(&t0.x));
            float2 f1 = __half22float2(*reinterpret_cast<__half2*>(&t0.y));
            float2 f2 = __half22float2(*reinterpret_cast<__half2*>(&t0.z));
            float2 f3 = __half22float2(*reinterpret_cast<__half2*>(&t0.w));
            a0.x += f0.x; a0.y += f0.y; a0.z += f1.x; a0.w += f1.y;
            a1.x += f2.x; a1.y += f2.y; a1.z += f3.x; a1.w += f3.y;
        }
    }
#pragma unroll
    for (int m = F4L; m < 32; m <<= 1) {
        a0.x += __shfl_xor_sync(0xFFFFFFFFu, a0.x, m);
        a0.y += __shfl_xor_sync(0xFFFFFFFFu, a0.y, m);
        a0.z += __shfl_xor_sync(0xFFFFFFFFu, a0.z, m);
        a0.w += __shfl_xor_sync(0xFFFFFFFFu, a0.w, m);
        a1.x += __shfl_xor_sync(0xFFFFFFFFu, a1.x, m);
        a1.y += __shfl_xor_sync(0xFFFFFFFFu, a1.y, m);
        a1.z += __shfl_xor_sync(0xFFFFFFFFu, a1.z, m);
        a1.w += __shfl_xor_sync(0xFFFFFFFFu, a1.w, m);
    }
    float inv = 1.0f / fmaxf((float)(end - beg), 1.0f);
    if (slot == 0 && act) {
        float* dst = out + (size_t)v * DIM + f4 * 8;
        const float* sp = s + (size_t)v * DIM + f4 * 8;
        float4 s0v = *reinterpret_cast<const float4*>(sp);
        float4 s1v = *reinterpret_cast<const float4*>(sp + 4);
        float4 r0 = make_float4(s0v.x + a0.x * inv, s0v.y + a0.y * inv,
                                s0v.z + a0.z * inv, s0v.w + a0.w * inv);
        float4 r1 = make_float4(s1v.x + a1.x * inv, s1v.y + a1.y * inv,
                                s1v.z + a1.z * inv, s1v.w + a1.w * inv);
        if (RELU) {
            r0.x = fmaxf(r0.x, 0.f); r0.y = fmaxf(r0.y, 0.f);
            r0.z = fmaxf(r0.z, 0.f); r0.w = fmaxf(r0.w, 0.f);
            r1.x = fmaxf(r1.x, 0.f); r1.y = fmaxf(r1.y, 0.f);
            r1.z = fmaxf(r1.z, 0.f); r1.w = fmaxf(r1.w, 0.f);
        }
        *reinterpret_cast<float4*>(dst) = r0;
        *reinterpret_cast<float4*>(dst + 4) = r1;
    }
}

// fp16 gather, uint2 chunks (layer 2, DIM=28), fused epilogue
template <int DIM, int SLOTS, bool RELU>
__global__ void k_gatherH2(const __half* __restrict__ zh, const float* __restrict__ s,
                           float* __restrict__ out) {
    constexpr int NCH = DIM / 4;
    constexpr int F4L = 32 / SLOTS;
    int gt = blockIdx.x * blockDim.x + threadIdx.x;
    int v = gt >> 5;
    if (v >= NN) return;
    int lane = gt & 31;
    int slot = lane / F4L;
    int f4 = lane % F4L;
    bool act = (f4 < NCH);

    int beg = g_off[v];
    int end = g_off[v + 1];
    float4 a0 = make_float4(0.f, 0.f, 0.f, 0.f);

    int e = beg;
    for (; e + 2 * SLOTS <= end; e += 2 * SLOTS) {
        int s0 = g_csr[e + slot];
        int s1 = g_csr[e + SLOTS + slot];
        if (act) {
            uint2 t0 = __ldg(reinterpret_cast<const uint2*>(zh + (size_t)s0 * DIM) + f4);
            uint2 t1 = __ldg(reinterpret_cast<const uint2*>(zh + (size_t)s1 * DIM) + f4);
            __half2 p0 = __hadd2(*reinterpret_cast<__half2*>(&t0.x), *reinterpret_cast<__half2*>(&t1.x));
            __half2 p1 = __hadd2(*reinterpret_cast<__half2*>(&t0.y), *reinterpret_cast<__half2*>(&t1.y));
            float2 f0 = __half22float2(p0), f1 = __half22float2(p1);
            a0.x += f0.x; a0.y += f0.y; a0.z += f1.x; a0.w += f1.y;
        }
    }
    for (; e < end; e += SLOTS) {
        int myE = e + slot;
        if (myE < end && act) {
            uint2 t0 = __ldg(reinterpret_cast<const uint2*>(zh + (size_t)g_csr[myE] * DIM) + f4);
            float2 f0 = __half22float2(*reinterpret_cast<__half2*>(&t0.x));
            float2 f1 = __half22float2(*reinterpret_cast<__half2*>(&t0.y));
            a0.x += f0.x; a0.y += f0.y; a0.z += f1.x; a0.w += f1.y;
        }
    }
#pragma unroll
    for (int m = F4L; m < 32; m <<= 1) {
        a0.x += __shfl_xor_sync(0xFFFFFFFFu, a0.x, m);
        a0.y += __shfl_xor_sync(0xFFFFFFFFu, a0.y, m);
        a0.z += __shfl_xor_sync(0xFFFFFFFFu, a0.z, m);
        a0.w += __shfl_xor_sync(0xFFFFFFFFu, a0.w, m);
    }
    float inv = 1.0f / fmaxf((float)(end - beg), 1.0f);
    if (slot == 0 && act) {
        const float* sp = s + (size_t)v * DIM + f4 * 4;
        float4 sv = *reinterpret_cast<const float4*>(sp);
        float4 r = make_float4(sv.x + a0.x * inv, sv.y + a0.y * inv,
                               sv.z + a0.z * inv, sv.w + a0.w * inv);
        if (RELU) {
            r.x = fmaxf(r.x, 0.f); r.y = fmaxf(r.y, 0.f);
            r.z = fmaxf(r.z, 0.f); r.w = fmaxf(r.w, 0.f);
        }
        *reinterpret_cast<float4*>(out + (size_t)v * DIM + f4 * 4) = r;
    }
}

// fused scalar gather for DIM=5 (layer 3, fp32 z, no relu)
__global__ void k_gatherF5(const float* __restrict__ z, const float* __restrict__ s,
                           float* __restrict__ out) {
    constexpr int DIM = 5;
    int gt = blockIdx.x * blockDim.x + threadIdx.x;
    int v = gt >> 5;
    if (v >= NN) return;
    int lane = gt & 31;
    int slot = lane >> 3;
    int f = lane & 7;
    bool act = (f < DIM);

    int beg = g_off[v];
    int end = g_off[v + 1];
    float acc = 0.0f;
    int e = beg;
    for (; e + 8 <= end; e += 8) {
        int s0 = g_csr[e + slot];
        int s1 = g_csr[e + 4 + slot];
        if (act) acc += z[(size_t)s0 * DIM + f] + z[(size_t)s1 * DIM + f];
    }
    for (; e < end; e += 4) {
        int myE = e + slot;
        if (myE < end && act) acc += z[(size_t)g_csr[myE] * DIM + f];
    }
#pragma unroll
    for (int m = 8; m < 32; m <<= 1) acc += __shfl_xor_sync(0xFFFFFFFFu, acc, m);
    float inv = 1.0f / fmaxf((float)(end - beg), 1.0f);
    if (slot == 0 && act)
        out[(size_t)v * DIM + f] = s[(size_t)v * DIM + f] + acc * inv;
}

// ---------------------------------------------------------------------------
// mma.sync m16n8k16 fp16 helpers
__device__ __forceinline__ void mma16816(float c[4], unsigned a0, unsigned a1,
                                         unsigned a2, unsigned a3,
                                         unsigned b0, unsigned b1) {
    asm volatile(
        "mma.sync.aligned.m16n8k16.row.col.f32.f16.f16.f32 "
        "{%0,%1,%2,%3}, {%4,%5,%6,%7}, {%8,%9}, {%0,%1,%2,%3};"
        : "+f"(c[0]), "+f"(c[1]), "+f"(c[2]), "+f"(c[3])
        : "r"(a0), "r"(a1), "r"(a2), "r"(a3), "r"(b0), "r"(b1));
}

__device__ __forceinline__ unsigned ldu(const __half* p) {
    return *reinterpret_cast<const unsigned*>(p);
}

// Layer-0 MMA: bufAh = relu( feat_h@Ws0 + agg_h@Wn0 + b0 ), warp = 16 nodes.
// K=32 (2 ksteps), N=128 (16 ntiles), fp16 operands, fp32 accumulate.
__global__ void __launch_bounds__(256) k_mma_sage0(
    const __half* __restrict__ fh, const __half* __restrict__ ah,
    const __half* __restrict__ WsT, const __half* __restrict__ WnT,  // [128][32]
    const float* __restrict__ bias, __half* __restrict__ outh) {
    int w = (blockIdx.x * blockDim.x + threadIdx.x) >> 5;
    int lane = threadIdx.x & 31;
    int base = w * 16;
    if (base >= NN) return;
    int r = lane >> 2, q = lane & 3;

    float c[16][4];
#pragma unroll
    for (int nt = 0; nt < 16; nt++)
#pragma unroll
        for (int j = 0; j < 4; j++) c[nt][j] = 0.f;

#pragma unroll
    for (int ks = 0; ks < 2; ks++) {
        int k0 = ks * 16;
        unsigned fa0 = ldu(fh + (size_t)(base + r) * 32 + k0 + 2 * q);
        unsigned fa1 = ldu(fh + (size_t)(base + r + 8) * 32 + k0 + 2 * q);
        unsigned fa2 = ldu(fh + (size_t)(base + r) * 32 + k0 + 2 * q + 8);
        unsigned fa3 = ldu(fh + (size_t)(base + r + 8) * 32 + k0 + 2 * q + 8);
        unsigned ga0 = ldu(ah + (size_t)(base + r) * 32 + k0 + 2 * q);
        unsigned ga1 = ldu(ah + (size_t)(base + r + 8) * 32 + k0 + 2 * q);
        unsigned ga2 = ldu(ah + (size_t)(base + r) * 32 + k0 + 2 * q + 8);
        unsigned ga3 = ldu(ah + (size_t)(base + r + 8) * 32 + k0 + 2 * q + 8);
#pragma unroll
        for (int nt = 0; nt < 16; nt++) {
            int n = nt * 8 + r;
            unsigned bs0 = ldu(WsT + n * 32 + k0 + 2 * q);
            unsigned bs1 = ldu(WsT + n * 32 + k0 + 2 * q + 8);
            mma16816(c[nt], fa0, fa1, fa2, fa3, bs0, bs1);
            unsigned bn0 = ldu(WnT + n * 32 + k0 + 2 * q);
            unsigned bn1 = ldu(WnT + n * 32 + k0 + 2 * q + 8);
            mma16816(c[nt], ga0, ga1, ga2, ga3, bn0, bn1);
        }
    }

#pragma unroll
    for (int nt = 0; nt < 16; nt++) {
        int col = nt * 8 + 2 * q;
        float2 bb = *reinterpret_cast<const float2*>(bias + col);
        float v0 = fmaxf(c[nt][0] + bb.x, 0.f);
        float v1 = fmaxf(c[nt][1] + bb.y, 0.f);
        float v2 = fmaxf(c[nt][2] + bb.x, 0.f);
        float v3 = fmaxf(c[nt][3] + bb.y, 0.f);
        __half2 h01 = __floats2half2_rn(v0, v1);
        __half2 h23 = __floats2half2_rn(v2, v3);
        *reinterpret_cast<unsigned*>(outh + (size_t)(base + r) * 128 + col) =
            *reinterpret_cast<unsigned*>(&h01);
        *reinterpret_cast<unsigned*>(outh + (size_t)(base + r + 8) * 128 + col) =
            *reinterpret_cast<unsigned*>(&h23);
    }
}

// Layer-1 MMA: zh = half(h@Wn1), s = h@Ws1 + b1. h = bufAh fp16, warp = 16 nodes.
// K=128 (8 ksteps), N=48 (6 ntiles).
__global__ void __launch_bounds__(256) k_mma_zs1(
    const __half* __restrict__ h,
    const __half* __restrict__ WnT, const __half* __restrict__ WsT,  // [48][128]
    const float* __restrict__ bias,
    __half* __restrict__ zh, float* __restrict__ s) {
    int w = (blockIdx.x * blockDim.x + threadIdx.x) >> 5;
    int lane = threadIdx.x & 31;
    int base = w * 16;
    if (base >= NN) return;
    int r = lane >> 2, q = lane & 3;

    float cz[6][4], cs[6][4];
#pragma unroll
    for (int nt = 0; nt < 6; nt++)
#pragma unroll
        for (int j = 0; j < 4; j++) { cz[nt][j] = 0.f; cs[nt][j] = 0.f; }

#pragma unroll
    for (int ks = 0; ks < 8; ks++) {
        int k0 = ks * 16;
        unsigned a0 = ldu(h + (size_t)(base + r) * 128 + k0 + 2 * q);
        unsigned a1 = ldu(h + (size_t)(base + r + 8) * 128 + k0 + 2 * q);
        unsigned a2 = ldu(h + (size_t)(base + r) * 128 + k0 + 2 * q + 8);
        unsigned a3 = ldu(h + (size_t)(base + r + 8) * 128 + k0 + 2 * q + 8);
#pragma unroll
        for (int nt = 0; nt < 6; nt++) {
            int n = nt * 8 + r;
            unsigned bn0 = ldu(WnT + n * 128 + k0 + 2 * q);
            unsigned bn1 = ldu(WnT + n * 128 + k0 + 2 * q + 8);
            mma16816(cz[nt], a0, a1, a2, a3, bn0, bn1);
            unsigned bs0 = ldu(WsT + n * 128 + k0 + 2 * q);
            unsigned bs1 = ldu(WsT + n * 128 + k0 + 2 * q + 8);
            mma16816(cs[nt], a0, a1, a2, a3, bs0, bs1);
        }
    }

#pragma unroll
    for (int nt = 0; nt < 6; nt++) {
        int col = nt * 8 + 2 * q;
        __half2 z01 = __floats2half2_rn(cz[nt][0], cz[nt][1]);
        __half2 z23 = __floats2half2_rn(cz[nt][2], cz[nt][3]);
        *reinterpret_cast<unsigned*>(zh + (size_t)(base + r) * 48 + col) =
            *reinterpret_cast<unsigned*>(&z01);
        *reinterpret_cast<unsigned*>(zh + (size_t)(base + r + 8) * 48 + col) =
            *reinterpret_cast<unsigned*>(&z23);
        float2 bb = *reinterpret_cast<const float2*>(bias + col);
        float2 s01 = make_float2(cs[nt][0] + bb.x, cs[nt][1] + bb.y);
        float2 s23 = make_float2(cs[nt][2] + bb.x, cs[nt][3] + bb.y);
        *reinterpret_cast<float2*>(s + (size_t)(base + r) * 48 + col) = s01;
        *reinterpret_cast<float2*>(s + (size_t)(base + r + 8) * 48 + col) = s23;
    }
}

// ---------------------------------------------------------------------------
// scalar combined z/s (layer 2: 48->28, half z out; layer 3: 28->5 fp32)
template <int DIN, int DOUT, int NV>
__global__ void k_zsH(const float* __restrict__ h, const float* __restrict__ Wn,
                      const float* __restrict__ Ws, const float* __restrict__ bias,
                      __half* __restrict__ zh, float* __restrict__ s) {
    constexpr int OG = DOUT / 4;
    long long t = (long long)blockIdx.x * blockDim.x + threadIdx.x;
    int oq = (int)(t % OG);
    long long ng = t / OG;
    int n0 = (int)(ng * NV);
    if (n0 >= NN) return;

    float4 b4 = __ldg(reinterpret_cast<const float4*>(bias) + oq);
    float4 az[NV], as[NV];
#pragma unroll
    for (int i = 0; i < NV; i++) {
        az[i] = make_float4(0.f, 0.f, 0.f, 0.f);
        as[i] = b4;
    }

#pragma unroll
    for (int k = 0; k < DIN; k += 4) {
        float4 n0w = __ldg(reinterpret_cast<const float4*>(Wn + (size_t)(k + 0) * DOUT) + oq);
        float4 n1w = __ldg(reinterpret_cast<const float4*>(Wn + (size_t)(k + 1) * DOUT) + oq);
        float4 n2w = __ldg(reinterpret_cast<const float4*>(Wn + (size_t)(k + 2) * DOUT) + oq);
        float4 n3w = __ldg(reinterpret_cast<const float4*>(Wn + (size_t)(k + 3) * DOUT) + oq);
        float4 s0w = __ldg(reinterpret_cast<const float4*>(Ws + (size_t)(k + 0) * DOUT) + oq);
        float4 s1w = __ldg(reinterpret_cast<const float4*>(Ws + (size_t)(k + 1) * DOUT) + oq);
        float4 s2w = __ldg(reinterpret_cast<const float4*>(Ws + (size_t)(k + 2) * DOUT) + oq);
        float4 s3w = __ldg(reinterpret_cast<const float4*>(Ws + (size_t)(k + 3) * DOUT) + oq);
#pragma unroll
        for (int i = 0; i < NV; i++) {
            int node = min(n0 + i, NN - 1);
            float4 hv = __ldg(reinterpret_cast<const float4*>(h + (size_t)node * DIN) + (k >> 2));
            az[i].x = fmaf(hv.x, n0w.x, fmaf(hv.y, n1w.x, fmaf(hv.z, n2w.x, fmaf(hv.w, n3w.x, az[i].x))));
            az[i].y = fmaf(hv.x, n0w.y, fmaf(hv.y, n1w.y, fmaf(hv.z, n2w.y, fmaf(hv.w, n3w.y, az[i].y))));
            az[i].z = fmaf(hv.x, n0w.z, fmaf(hv.y, n1w.z, fmaf(hv.z, n2w.z, fmaf(hv.w, n3w.z, az[i].z))));
            az[i].w = fmaf(hv.x, n0w.w, fmaf(hv.y, n1w.w, fmaf(hv.z, n2w.w, fmaf(hv.w, n3w.w, az[i].w))));
            as[i].x = fmaf(hv.x, s0w.x, fmaf(hv.y, s1w.x, fmaf(hv.z, s2w.x, fmaf(hv.w, s3w.x, as[i].x))));
            as[i].y = fmaf(hv.x, s0w.y, fmaf(hv.y, s1w.y, fmaf(hv.z, s2w.y, fmaf(hv.w, s3w.y, as[i].y))));
            as[i].z = fmaf(hv.x, s0w.z, fmaf(hv.y, s1w.z, fmaf(hv.z, s2w.z, fmaf(hv.w, s3w.z, as[i].z))));
            as[i].w = fmaf(hv.x, s0w.w, fmaf(hv.y, s1w.w, fmaf(hv.z, s2w.w, fmaf(hv.w, s3w.w, as[i].w))));
        }
    }

#pragma unroll
    for (int i = 0; i < NV; i++) {
        if (n0 + i < NN) {
            __half2 h01 = __floats2half2_rn(az[i].x, az[i].y);
            __half2 h23 = __floats2half2_rn(az[i].z, az[i].w);
            reinterpret_cast<uint2*>(zh + (size_t)(n0 + i) * DOUT)[oq] =
                make_uint2(*reinterpret_cast<unsigned*>(&h01), *reinterpret_cast<unsigned*>(&h23));
            reinterpret_cast<float4*>(s + (size_t)(n0 + i) * DOUT)[oq] = as[i];
        }
    }
}

template <int DIN, int DOUT>
__global__ void k_zsS(const float* __restrict__ h, const float* __restrict__ Wn,
                      const float* __restrict__ Ws, const float* __restrict__ bias,
                      float* __restrict__ z, float* __restrict__ s) {
    long long idx = (long long)blockIdx.x * blockDim.x + threadIdx.x;
    if (idx >= (long long)NN * DOUT) return;
    int v = (int)(idx / DOUT);
    int o = (int)(idx % DOUT);
    const float* hrow = h + (size_t)v * DIN;
    float accz = 0.0f;
    float accs = bias[o];
#pragma unroll
    for (int k = 0; k < DIN; k++) {
        float hv = hrow[k];
        accz = fmaf(hv, Wn[k * DOUT + o], accz);
        accs = fmaf(hv, Ws[k * DOUT + o], accs);
    }
    z[idx] = accz;
    s[idx] = accs;
}

// ---------------------------------------------------------------------------
__global__ void k_readout(const float* __restrict__ h, const int* __restrict__ gid,
                          float* __restrict__ out) {
    int v = blockIdx.x * blockDim.x + threadIdx.x;
    bool ok = (v < NN);
    int g = ok ? gid[v] : -1;
    float c = ok ? 1.0f : 0.0f;
    float f0 = 0, f1 = 0, f2 = 0, f3 = 0, f4 = 0;
    if (ok) {
        const float* hr = h + (size_t)v * 5;
        f0 = hr[0]; f1 = hr[1]; f2 = hr[2]; f3 = hr[3]; f4 = hr[4];
    }
    int g0 = __shfl_sync(0xFFFFFFFFu, ok ? g : __shfl_sync(0xFFFFFFFFu, g, 0), 0);
    bool uniform = __all_sync(0xFFFFFFFFu, !ok || g == g0);
    if (uniform) {
#pragma unroll
        for (int m = 16; m > 0; m >>= 1) {
            c  += __shfl_xor_sync(0xFFFFFFFFu, c, m);
            f0 += __shfl_xor_sync(0xFFFFFFFFu, f0, m);
            f1 += __shfl_xor_sync(0xFFFFFFFFu, f1, m);
            f2 += __shfl_xor_sync(0xFFFFFFFFu, f2, m);
            f3 += __shfl_xor_sync(0xFFFFFFFFu, f3, m);
            f4 += __shfl_xor_sync(0xFFFFFFFFu, f4, m);
        }
        if ((threadIdx.x & 31) == 0 && c > 0.0f) {
            atomicAdd(&g_cnt[g0], c);
            atomicAdd(&out[g0 * 5 + 0], f0);
            atomicAdd(&out[g0 * 5 + 1], f1);
            atomicAdd(&out[g0 * 5 + 2], f2);
            atomicAdd(&out[g0 * 5 + 3], f3);
            atomicAdd(&out[g0 * 5 + 4], f4);
        }
    } else if (ok) {
        atomicAdd(&g_cnt[g], 1.0f);
        atomicAdd(&out[g * 5 + 0], f0);
        atomicAdd(&out[g * 5 + 1], f1);
        atomicAdd(&out[g * 5 + 2], f2);
        atomicAdd(&out[g * 5 + 3], f3);
        atomicAdd(&out[g * 5 + 4], f4);
    }
}

__global__ void k_final(float* __restrict__ out) {
    int i = blockIdx.x * blockDim.x + threadIdx.x;
    if (i < NG * 5) out[i] /= fmaxf(g_cnt[i / 5], 1.0f);
}

// ---------------------------------------------------------------------------
static inline int blks(long long n, int t) { return (int)((n + t - 1) / t); }

extern "C" void kernel_launch(void* const* d_in, const int* in_sizes, int n_in,
                              void* d_out, int out_size) {
    const float* feat = (const float*)d_in[0];
    const int* src = (const int*)d_in[1];
    const int* dst = (const int*)d_in[2];
    const int* gid = (const int*)d_in[3];
    const float* Ws0 = (const float*)d_in[4];
    const float* Wn0 = (const float*)d_in[5];
    const float* b0  = (const float*)d_in[6];
    const float* Ws1 = (const float*)d_in[7];
    const float* Wn1 = (const float*)d_in[8];
    const float* b1  = (const float*)d_in[9];
    const float* Ws2 = (const float*)d_in[10];
    const float* Wn2 = (const float*)d_in[11];
    const float* b2  = (const float*)d_in[12];
    const float* Ws3 = (const float*)d_in[13];
    const float* Wn3 = (const float*)d_in[14];
    const float* b3  = (const float*)d_in[15];
    float* out = (float*)d_out;

    float *bufB, *bufC, *z, *s, *cnt;
    __half *bufAh, *feath, *aggh, *zh, *WsT0, *WnT0, *WsT1, *WnT1;
    int *degi;
    cudaGetSymbolAddress((void**)&bufAh, g_bufAh);
    cudaGetSymbolAddress((void**)&bufB, g_bufB);
    cudaGetSymbolAddress((void**)&bufC, g_bufC);
    cudaGetSymbolAddress((void**)&z, g_z);
    cudaGetSymbolAddress((void**)&s, g_s);
    cudaGetSymbolAddress((void**)&cnt, g_cnt);
    cudaGetSymbolAddress((void**)&degi, g_degi);
    cudaGetSymbolAddress((void**)&feath, g_feath);
    cudaGetSymbolAddress((void**)&aggh, g_aggh);
    cudaGetSymbolAddress((void**)&zh, g_zh);
    cudaGetSymbolAddress((void**)&WsT0, g_WsT0);
    cudaGetSymbolAddress((void**)&WnT0, g_WnT0);
    cudaGetSymbolAddress((void**)&WsT1, g_WsT1);
    cudaGetSymbolAddress((void**)&WnT1, g_WnT1);

    const int T = 256;

    // ---- input conversions (independent of CSR) ----
    k_cvtfeat<<<blks((long long)NN * 8, T), T>>>(feat, feath);
    k_cvtWT<32, 128><<<blks(32 * 128, T), T>>>(Ws0, WsT0);
    k_cvtWT<32, 128><<<blks(32 * 128, T), T>>>(Wn0, WnT0);
    k_cvtWT<128, 48><<<blks(128 * 48, T), T>>>(Ws1, WsT1);
    k_cvtWT<128, 48><<<blks(128 * 48, T), T>>>(Wn1, WnT1);

    // ---- CSR build (single atomic pass + atomic-free fill) ----
    cudaMemsetAsync(degi, 0, NN * sizeof(int));
    k_degrank<<<blks(NE, T), T>>>(dst);
    k_scan1<<<NB, 1024>>>();
    k_scan2<<<1, 256>>>();
    k_scan3<<<NB, 1024>>>();
    k_build<<<blks(NE, T), T>>>(src, dst);

    // ---- layer 0: gather (fp16 out) + tensor-core dual projection ----
    k_gather32H<<<blks((long long)NN * 32, T), T>>>(feath, aggh);
    k_mma_sage0<<<blks((long long)(NN / 16) * 32, T), T>>>(feath, aggh, WsT0, WnT0, b0, bufAh);

    // ---- layer 1: tensor-core zs + fused gather ----
    k_mma_zs1<<<blks((long long)(NN / 16) * 32, T), T>>>(bufAh, WnT1, WsT1, b1, zh, s);
    k_gatherH<48, 4, true><<<blks((long long)NN * 32, T), T>>>(zh, s, bufB);

    // ---- layer 2: 48 -> 28, relu (scalar zs + fused gather) ----
    {
        long long th = (long long)((NN + 3) / 4) * 7;
        k_zsH<48, 28, 4><<<blks(th, T), T>>>(bufB, Wn2, Ws2, b2, zh, s);
    }
    k_gatherH2<28, 4, true><<<blks((long long)NN * 32, T), T>>>(zh, s, bufC);

    // ---- layer 3: 28 -> 5, linear (fp32) ----
    k_zsS<28, 5><<<blks((long long)NN * 5, T), T>>>(bufC, Wn3, Ws3, b3, z, s);
    k_gatherF5<<<blks((long long)NN * 32, T), T>>>(z, s, bufB);

    // ---- readout ----
    cudaMemsetAsync(out, 0, NG * 5 * sizeof(float));
    cudaMemsetAsync(cnt, 0, NG * sizeof(float));
    k_readout<<<blks(NN, T), T>>>(bufB, gid, out);
    k_final<<<blks(NG * 5, T), T>>>(out);
}

// round 14
// speedup vs baseline: 1.8001x; 1.0695x over previous
#include <cuda_runtime.h>
#include <cuda_bf16.h>
#include <cuda_fp16.h>

static const int NN = 200000;
static const int NE = 3200000;
static const int NG = 400;
static const int NB = (NN + 1023) / 1024;  // 196 scan blocks

// Scratch (device globals; no runtime allocation allowed)
__device__ int    g_degi[NN];
__device__ int    g_off[NN + 1];
__device__ int    g_rank[NE];
__device__ int    g_csr[NE];
__device__ int    g_bsum[256];
__device__ __half g_bufAh[(size_t)NN * 128];  // layer0 output (fp16, mma operand)
__device__ __half g_bufBh[(size_t)NN * 48];   // layer1 output (fp16, mma operand)
__device__ float  g_bufC[(size_t)NN * 28];    // layer2 output (fp32)
__device__ float  g_bufD[(size_t)NN * 5];     // layer3 output (fp32)
__device__ __half g_feath[(size_t)NN * 32];   // fp16 copy of feat
__device__ __half g_aggh[(size_t)NN * 32];    // fp16 layer-0 aggregate
__device__ __half g_zh[(size_t)NN * 48];      // fp16 projected neighbor features
__device__ float  g_z[(size_t)NN * 48];       // fp32 z for layer 3
__device__ float  g_s[(size_t)NN * 48];       // self-projection + bias
__device__ __half g_WsT0[128 * 32];           // transposed fp16 weights [N][K]
__device__ __half g_WnT0[128 * 32];
__device__ __half g_WsT1[48 * 128];
__device__ __half g_WnT1[48 * 128];
__device__ __half g_WsT2[32 * 48];            // padded N: 28 -> 32 (zero rows)
__device__ __half g_WnT2[32 * 48];
__device__ float  g_cnt[NG];

// ---------------------------------------------------------------------------
__global__ void k_degrank(const int* __restrict__ dst) {
    int e = blockIdx.x * blockDim.x + threadIdx.x;
    if (e < NE) g_rank[e] = atomicAdd(&g_degi[dst[e]], 1);
}

__global__ void k_scan1() {
    __shared__ int sh[1024];
    int t = threadIdx.x;
    int j = blockIdx.x * 1024 + t;
    sh[t] = (j < NN) ? g_degi[j] : 0;
    __syncthreads();
    for (int d = 512; d > 0; d >>= 1) {
        if (t < d) sh[t] += sh[t + d];
        __syncthreads();
    }
    if (t == 0) g_bsum[blockIdx.x] = sh[0];
}

__global__ void k_scan2() {
    __shared__ int sh[256];
    int t = threadIdx.x;
    int v = (t < NB) ? g_bsum[t] : 0;
    sh[t] = v;
    __syncthreads();
    for (int d = 1; d < 256; d <<= 1) {
        int x = (t >= d) ? sh[t - d] : 0;
        __syncthreads();
        sh[t] += x;
        __syncthreads();
    }
    g_bsum[t] = sh[t] - v;
}

__global__ void k_scan3() {
    __shared__ int sh[1024];
    int t = threadIdx.x;
    int j = blockIdx.x * 1024 + t;
    int v = (j < NN) ? g_degi[j] : 0;
    sh[t] = v;
    __syncthreads();
    for (int d = 1; d < 1024; d <<= 1) {
        int x = (t >= d) ? sh[t - d] : 0;
        __syncthreads();
        sh[t] += x;
        __syncthreads();
    }
    int excl = sh[t] - v + g_bsum[blockIdx.x];
    if (j < NN) g_off[j] = excl;
    if (j == NN - 1) g_off[NN] = excl + v;
}

__global__ void k_build(const int* __restrict__ src, const int* __restrict__ dst) {
    int e = blockIdx.x * blockDim.x + threadIdx.x;
    if (e >= NE) return;
    int d = dst[e];
    g_csr[g_off[d] + g_rank[e]] = src[e];
}

// feat fp32 -> fp16
__global__ void k_cvtfeat(const float* __restrict__ f, __half* __restrict__ fh) {
    int i = blockIdx.x * blockDim.x + threadIdx.x;
    if (i >= NN * 32 / 4) return;
    float4 v = reinterpret_cast<const float4*>(f)[i];
    __half2 a = __floats2half2_rn(v.x, v.y);
    __half2 b = __floats2half2_rn(v.z, v.w);
    reinterpret_cast<uint2*>(fh)[i] =
        make_uint2(*reinterpret_cast<unsigned*>(&a), *reinterpret_cast<unsigned*>(&b));
}

// all weight transposes fused: [K][N] fp32 -> [N][K] fp16 (layer2 N padded to 32)
__global__ void k_cvtAllW(const float* Ws0, const float* Wn0,
                          const float* Ws1, const float* Wn1,
                          const float* Ws2, const float* Wn2) {
    int i = blockIdx.x * blockDim.x + threadIdx.x;
    const int S0 = 128 * 32, S1 = 48 * 128, S2 = 32 * 48;
    if (i < S0) {
        int o = i / 32, k = i % 32;
        g_WsT0[i] = __float2half(Ws0[k * 128 + o]);
    } else if (i < 2 * S0) {
        int j = i - S0;
        int o = j / 32, k = j % 32;
        g_WnT0[j] = __float2half(Wn0[k * 128 + o]);
    } else if (i < 2 * S0 + S1) {
        int j = i - 2 * S0;
        int o = j / 128, k = j % 128;
        g_WsT1[j] = __float2half(Ws1[k * 48 + o]);
    } else if (i < 2 * S0 + 2 * S1) {
        int j = i - 2 * S0 - S1;
        int o = j / 128, k = j % 128;
        g_WnT1[j] = __float2half(Wn1[k * 48 + o]);
    } else if (i < 2 * S0 + 2 * S1 + S2) {
        int j = i - 2 * S0 - 2 * S1;
        int o = j / 48, k = j % 48;
        g_WsT2[j] = (o < 28) ? __float2half(Ws2[k * 28 + o]) : __float2half(0.0f);
    } else if (i < 2 * S0 + 2 * S1 + 2 * S2) {
        int j = i - 2 * S0 - 2 * S1 - S2;
        int o = j / 48, k = j % 48;
        g_WnT2[j] = (o < 28) ? __float2half(Wn2[k * 28 + o]) : __float2half(0.0f);
    }
}

// ---------------------------------------------------------------------------
// fp16 gather for layer 0 (DIM=32, 8 slots), fp16 output (mma operand)
__global__ void k_gather32H(const __half* __restrict__ zh, __half* __restrict__ aggh) {
    constexpr int DIM = 32, SLOTS = 8;
    constexpr int NCH = DIM / 8;
    constexpr int F4L = 32 / SLOTS;
    int gt = blockIdx.x * blockDim.x + threadIdx.x;
    int v = gt >> 5;
    if (v >= NN) return;
    int lane = gt & 31;
    int slot = lane / F4L;
    int f4 = lane % F4L;
    bool act = (f4 < NCH);

    int beg = g_off[v];
    int end = g_off[v + 1];
    float4 a0 = make_float4(0.f, 0.f, 0.f, 0.f);
    float4 a1 = make_float4(0.f, 0.f, 0.f, 0.f);

    int e = beg;
    for (; e + 2 * SLOTS <= end; e += 2 * SLOTS) {
        int s0 = g_csr[e + slot];
        int s1 = g_csr[e + SLOTS + slot];
        if (act) {
            uint4 t0 = __ldg(reinterpret_cast<const uint4*>(zh + (size_t)s0 * DIM) + f4);
            uint4 t1 = __ldg(reinterpret_cast<const uint4*>(zh + (size_t)s1 * DIM) + f4);
            __half2 p0 = __hadd2(*reinterpret_cast<__half2*>(&t0.x), *reinterpret_cast<__half2*>(&t1.x));
            __half2 p1 = __hadd2(*reinterpret_cast<__half2*>(&t0.y), *reinterpret_cast<__half2*>(&t1.y));
            __half2 p2 = __hadd2(*reinterpret_cast<__half2*>(&t0.z), *reinterpret_cast<__half2*>(&t1.z));
            __half2 p3 = __hadd2(*reinterpret_cast<__half2*>(&t0.w), *reinterpret_cast<__half2*>(&t1.w));
            float2 f0 = __half22float2(p0), f1 = __half22float2(p1);
            float2 f2 = __half22float2(p2), f3 = __half22float2(p3);
            a0.x += f0.x; a0.y += f0.y; a0.z += f1.x; a0.w += f1.y;
            a1.x += f2.x; a1.y += f2.y; a1.z += f3.x; a1.w += f3.y;
        }
    }
    for (; e < end; e += SLOTS) {
        int myE = e + slot;
        if (myE < end && act) {
            uint4 t0 = __ldg(reinterpret_cast<const uint4*>(zh + (size_t)g_csr[myE] * DIM) + f4);
            float2 f0 = __half22float2(*reinterpret_cast<__half2*>(&t0.x));
            float2 f1 = __half22float2(*reinterpret_cast<__half2*>(&t0.y));
            float2 f2 = __half22float2(*reinterpret_cast<__half2*>(&t0.z));
            float2 f3 = __half22float2(*reinterpret_cast<__half2*>(&t0.w));
            a0.x += f0.x; a0.y += f0.y; a0.z += f1.x; a0.w += f1.y;
            a1.x += f2.x; a1.y += f2.y; a1.z += f3.x; a1.w += f3.y;
        }
    }
#pragma unroll
    for (int m = F4L; m < 32; m <<= 1) {
        a0.x += __shfl_xor_sync(0xFFFFFFFFu, a0.x, m);
        a0.y += __shfl_xor_sync(0xFFFFFFFFu, a0.y, m);
        a0.z += __shfl_xor_sync(0xFFFFFFFFu, a0.z, m);
        a0.w += __shfl_xor_sync(0xFFFFFFFFu, a0.w, m);
        a1.x += __shfl_xor_sync(0xFFFFFFFFu, a1.x, m);
        a1.y += __shfl_xor_sync(0xFFFFFFFFu, a1.y, m);
        a1.z += __shfl_xor_sync(0xFFFFFFFFu, a1.z, m);
        a1.w += __shfl_xor_sync(0xFFFFFFFFu, a1.w, m);
    }
    float inv = 1.0f / fmaxf((float)(end - beg), 1.0f);
    if (slot == 0 && act) {
        __half2 h0 = __floats2half2_rn(a0.x * inv, a0.y * inv);
        __half2 h1 = __floats2half2_rn(a0.z * inv, a0.w * inv);
        __half2 h2 = __floats2half2_rn(a1.x * inv, a1.y * inv);
        __half2 h3 = __floats2half2_rn(a1.z * inv, a1.w * inv);
        reinterpret_cast<uint4*>(aggh + (size_t)v * DIM)[f4] =
            make_uint4(*reinterpret_cast<unsigned*>(&h0), *reinterpret_cast<unsigned*>(&h1),
                       *reinterpret_cast<unsigned*>(&h2), *reinterpret_cast<unsigned*>(&h3));
    }
}

// fp16 gather, uint4 chunks, fused epilogue, fp16 output (layer 1, DIM=48)
template <int DIM, int SLOTS, bool RELU>
__global__ void k_gatherHh(const __half* __restrict__ zh, const float* __restrict__ s,
                           __half* __restrict__ outh) {
    constexpr int NCH = DIM / 8;
    constexpr int F4L = 32 / SLOTS;
    int gt = blockIdx.x * blockDim.x + threadIdx.x;
    int v = gt >> 5;
    if (v >= NN) return;
    int lane = gt & 31;
    int slot = lane / F4L;
    int f4 = lane % F4L;
    bool act = (f4 < NCH);

    int beg = g_off[v];
    int end = g_off[v + 1];
    float4 a0 = make_float4(0.f, 0.f, 0.f, 0.f);
    float4 a1 = make_float4(0.f, 0.f, 0.f, 0.f);

    int e = beg;
    for (; e + 2 * SLOTS <= end; e += 2 * SLOTS) {
        int s0 = g_csr[e + slot];
        int s1 = g_csr[e + SLOTS + slot];
        if (act) {
            uint4 t0 = __ldg(reinterpret_cast<const uint4*>(zh + (size_t)s0 * DIM) + f4);
            uint4 t1 = __ldg(reinterpret_cast<const uint4*>(zh + (size_t)s1 * DIM) + f4);
            __half2 p0 = __hadd2(*reinterpret_cast<__half2*>(&t0.x), *reinterpret_cast<__half2*>(&t1.x));
            __half2 p1 = __hadd2(*reinterpret_cast<__half2*>(&t0.y), *reinterpret_cast<__half2*>(&t1.y));
            __half2 p2 = __hadd2(*reinterpret_cast<__half2*>(&t0.z), *reinterpret_cast<__half2*>(&t1.z));
            __half2 p3 = __hadd2(*reinterpret_cast<__half2*>(&t0.w), *reinterpret_cast<__half2*>(&t1.w));
            float2 f0 = __half22float2(p0), f1 = __half22float2(p1);
            float2 f2 = __half22float2(p2), f3 = __half22float2(p3);
            a0.x += f0.x; a0.y += f0.y; a0.z += f1.x; a0.w += f1.y;
            a1.x += f2.x; a1.y += f2.y; a1.z += f3.x; a1.w += f3.y;
        }
    }
    for (; e < end; e += SLOTS) {
        int myE = e + slot;
        if (myE < end && act) {
            uint4 t0 = __ldg(reinterpret_cast<const uint4*>(zh + (size_t)g_csr[myE] * DIM) + f4);
            float2 f0 = __half22float2(*reinterpret_cast<__half2*>(&t0.x));
            float2 f1 = __half22float2(*reinterpret_cast<__half2*>(&t0.y));
            float2 f2 = __half22float2(*reinterpret_cast<__half2*>(&t0.z));
            float2 f3 = __half22float2(*reinterpret_cast<__half2*>(&t0.w));
            a0.x += f0.x; a0.y += f0.y; a0.z += f1.x; a0.w += f1.y;
            a1.x += f2.x; a1.y += f2.y; a1.z += f3.x; a1.w += f3.y;
        }
    }
#pragma unroll
    for (int m = F4L; m < 32; m <<= 1) {
        a0.x += __shfl_xor_sync(0xFFFFFFFFu, a0.x, m);
        a0.y += __shfl_xor_sync(0xFFFFFFFFu, a0.y, m);
        a0.z += __shfl_xor_sync(0xFFFFFFFFu, a0.z, m);
        a0.w += __shfl_xor_sync(0xFFFFFFFFu, a0.w, m);
        a1.x += __shfl_xor_sync(0xFFFFFFFFu, a1.x, m);
        a1.y += __shfl_xor_sync(0xFFFFFFFFu, a1.y, m);
        a1.z += __shfl_xor_sync(0xFFFFFFFFu, a1.z, m);
        a1.w += __shfl_xor_sync(0xFFFFFFFFu, a1.w, m);
    }
    float inv = 1.0f / fmaxf((float)(end - beg), 1.0f);
    if (slot == 0 && act) {
        const float* sp = s + (size_t)v * DIM + f4 * 8;
        float4 s0v = *reinterpret_cast<const float4*>(sp);
        float4 s1v = *reinterpret_cast<const float4*>(sp + 4);
        float r0 = s0v.x + a0.x * inv, r1 = s0v.y + a0.y * inv;
        float r2 = s0v.z + a0.z * inv, r3 = s0v.w + a0.w * inv;
        float r4 = s1v.x + a1.x * inv, r5 = s1v.y + a1.y * inv;
        float r6 = s1v.z + a1.z * inv, r7 = s1v.w + a1.w * inv;
        if (RELU) {
            r0 = fmaxf(r0, 0.f); r1 = fmaxf(r1, 0.f); r2 = fmaxf(r2, 0.f); r3 = fmaxf(r3, 0.f);
            r4 = fmaxf(r4, 0.f); r5 = fmaxf(r5, 0.f); r6 = fmaxf(r6, 0.f); r7 = fmaxf(r7, 0.f);
        }
        __half2 h0 = __floats2half2_rn(r0, r1);
        __half2 h1 = __floats2half2_rn(r2, r3);
        __half2 h2 = __floats2half2_rn(r4, r5);
        __half2 h3 = __floats2half2_rn(r6, r7);
        reinterpret_cast<uint4*>(outh + (size_t)v * DIM)[f4] =
            make_uint4(*reinterpret_cast<unsigned*>(&h0), *reinterpret_cast<unsigned*>(&h1),
                       *reinterpret_cast<unsigned*>(&h2), *reinterpret_cast<unsigned*>(&h3));
    }
}

// fp16 gather, uint2 chunks (layer 2, DIM=28), fused fp32 epilogue
template <int DIM, int SLOTS, bool RELU>
__global__ void k_gatherH2(const __half* __restrict__ zh, const float* __restrict__ s,
                           float* __restrict__ out) {
    constexpr int NCH = DIM / 4;
    constexpr int F4L = 32 / SLOTS;
    int gt = blockIdx.x * blockDim.x + threadIdx.x;
    int v = gt >> 5;
    if (v >= NN) return;
    int lane = gt & 31;
    int slot = lane / F4L;
    int f4 = lane % F4L;
    bool act = (f4 < NCH);

    int beg = g_off[v];
    int end = g_off[v + 1];
    float4 a0 = make_float4(0.f, 0.f, 0.f, 0.f);

    int e = beg;
    for (; e + 2 * SLOTS <= end; e += 2 * SLOTS) {
        int s0 = g_csr[e + slot];
        int s1 = g_csr[e + SLOTS + slot];
        if (act) {
            uint2 t0 = __ldg(reinterpret_cast<const uint2*>(zh + (size_t)s0 * DIM) + f4);
            uint2 t1 = __ldg(reinterpret_cast<const uint2*>(zh + (size_t)s1 * DIM) + f4);
            __half2 p0 = __hadd2(*reinterpret_cast<__half2*>(&t0.x), *reinterpret_cast<__half2*>(&t1.x));
            __half2 p1 = __hadd2(*reinterpret_cast<__half2*>(&t0.y), *reinterpret_cast<__half2*>(&t1.y));
            float2 f0 = __half22float2(p0), f1 = __half22float2(p1);
            a0.x += f0.x; a0.y += f0.y; a0.z += f1.x; a0.w += f1.y;
        }
    }
    for (; e < end; e += SLOTS) {
        int myE = e + slot;
        if (myE < end && act) {
            uint2 t0 = __ldg(reinterpret_cast<const uint2*>(zh + (size_t)g_csr[myE] * DIM) + f4);
            float2 f0 = __half22float2(*reinterpret_cast<__half2*>(&t0.x));
            float2 f1 = __half22float2(*reinterpret_cast<__half2*>(&t0.y));
            a0.x += f0.x; a0.y += f0.y; a0.z += f1.x; a0.w += f1.y;
        }
    }
#pragma unroll
    for (int m = F4L; m < 32; m <<= 1) {
        a0.x += __shfl_xor_sync(0xFFFFFFFFu, a0.x, m);
        a0.y += __shfl_xor_sync(0xFFFFFFFFu, a0.y, m);
        a0.z += __shfl_xor_sync(0xFFFFFFFFu, a0.z, m);
        a0.w += __shfl_xor_sync(0xFFFFFFFFu, a0.w, m);
    }
    float inv = 1.0f / fmaxf((float)(end - beg), 1.0f);
    if (slot == 0 && act) {
        const float* sp = s + (size_t)v * DIM + f4 * 4;
        float4 sv = *reinterpret_cast<const float4*>(sp);
        float4 r = make_float4(sv.x + a0.x * inv, sv.y + a0.y * inv,
                               sv.z + a0.z * inv, sv.w + a0.w * inv);
        if (RELU) {
            r.x = fmaxf(r.x, 0.f); r.y = fmaxf(r.y, 0.f);
            r.z = fmaxf(r.z, 0.f); r.w = fmaxf(r.w, 0.f);
        }
        *reinterpret_cast<float4*>(out + (size_t)v * DIM + f4 * 4) = r;
    }
}

// fused scalar gather for DIM=5 (layer 3, fp32 z, no relu)
__global__ void k_gatherF5(const float* __restrict__ z, const float* __restrict__ s,
                           float* __restrict__ out) {
    constexpr int DIM = 5;
    int gt = blockIdx.x * blockDim.x + threadIdx.x;
    int v = gt >> 5;
    if (v >= NN) return;
    int lane = gt & 31;
    int slot = lane >> 3;
    int f = lane & 7;
    bool act = (f < DIM);

    int beg = g_off[v];
    int end = g_off[v + 1];
    float acc = 0.0f;
    int e = beg;
    for (; e + 8 <= end; e += 8) {
        int s0 = g_csr[e + slot];
        int s1 = g_csr[e + 4 + slot];
        if (act) acc += z[(size_t)s0 * DIM + f] + z[(size_t)s1 * DIM + f];
    }
    for (; e < end; e += 4) {
        int myE = e + slot;
        if (myE < end && act) acc += z[(size_t)g_csr[myE] * DIM + f];
    }
#pragma unroll
    for (int m = 8; m < 32; m <<= 1) acc += __shfl_xor_sync(0xFFFFFFFFu, acc, m);
    float inv = 1.0f / fmaxf((float)(end - beg), 1.0f);
    if (slot == 0 && act)
        out[(size_t)v * DIM + f] = s[(size_t)v * DIM + f] + acc * inv;
}

// ---------------------------------------------------------------------------
__device__ __forceinline__ void mma16816(float c[4], unsigned a0, unsigned a1,
                                         unsigned a2, unsigned a3,
                                         unsigned b0, unsigned b1) {
    asm volatile(
        "mma.sync.aligned.m16n8k16.row.col.f32.f16.f16.f32 "
        "{%0,%1,%2,%3}, {%4,%5,%6,%7}, {%8,%9}, {%0,%1,%2,%3};"
        : "+f"(c[0]), "+f"(c[1]), "+f"(c[2]), "+f"(c[3])
        : "r"(a0), "r"(a1), "r"(a2), "r"(a3), "r"(b0), "r"(b1));
}

__device__ __forceinline__ unsigned ldu(const __half* p) {
    return *reinterpret_cast<const unsigned*>(p);
}

// Layer-0 MMA: bufAh = relu( feat_h@Ws0 + agg_h@Wn0 + b0 ), warp = 16 nodes.
__global__ void __launch_bounds__(256) k_mma_sage0(
    const __half* __restrict__ fh, const __half* __restrict__ ah,
    const __half* __restrict__ WsT, const __half* __restrict__ WnT,  // [128][32]
    const float* __restrict__ bias, __half* __restrict__ outh) {
    int w = (blockIdx.x * blockDim.x + threadIdx.x) >> 5;
    int lane = threadIdx.x & 31;
    int base = w * 16;
    if (base >= NN) return;
    int r = lane >> 2, q = lane & 3;

    float c[16][4];
#pragma unroll
    for (int nt = 0; nt < 16; nt++)
#pragma unroll
        for (int j = 0; j < 4; j++) c[nt][j] = 0.f;

#pragma unroll
    for (int ks = 0; ks < 2; ks++) {
        int k0 = ks * 16;
        unsigned fa0 = ldu(fh + (size_t)(base + r) * 32 + k0 + 2 * q);
        unsigned fa1 = ldu(fh + (size_t)(base + r + 8) * 32 + k0 + 2 * q);
        unsigned fa2 = ldu(fh + (size_t)(base + r) * 32 + k0 + 2 * q + 8);
        unsigned fa3 = ldu(fh + (size_t)(base + r + 8) * 32 + k0 + 2 * q + 8);
        unsigned ga0 = ldu(ah + (size_t)(base + r) * 32 + k0 + 2 * q);
        unsigned ga1 = ldu(ah + (size_t)(base + r + 8) * 32 + k0 + 2 * q);
        unsigned ga2 = ldu(ah + (size_t)(base + r) * 32 + k0 + 2 * q + 8);
        unsigned ga3 = ldu(ah + (size_t)(base + r + 8) * 32 + k0 + 2 * q + 8);
#pragma unroll
        for (int nt = 0; nt < 16; nt++) {
            int n = nt * 8 + r;
            unsigned bs0 = ldu(WsT + n * 32 + k0 + 2 * q);
            unsigned bs1 = ldu(WsT + n * 32 + k0 + 2 * q + 8);
            mma16816(c[nt], fa0, fa1, fa2, fa3, bs0, bs1);
            unsigned bn0 = ldu(WnT + n * 32 + k0 + 2 * q);
            unsigned bn1 = ldu(WnT + n * 32 + k0 + 2 * q + 8);
            mma16816(c[nt], ga0, ga1, ga2, ga3, bn0, bn1);
        }
    }

#pragma unroll
    for (int nt = 0; nt < 16; nt++) {
        int col = nt * 8 + 2 * q;
        float2 bb = *reinterpret_cast<const float2*>(bias + col);
        float v0 = fmaxf(c[nt][0] + bb.x, 0.f);
        float v1 = fmaxf(c[nt][1] + bb.y, 0.f);
        float v2 = fmaxf(c[nt][2] + bb.x, 0.f);
        float v3 = fmaxf(c[nt][3] + bb.y, 0.f);
        __half2 h01 = __floats2half2_rn(v0, v1);
        __half2 h23 = __floats2half2_rn(v2, v3);
        *reinterpret_cast<unsigned*>(outh + (size_t)(base + r) * 128 + col) =
            *reinterpret_cast<unsigned*>(&h01);
        *reinterpret_cast<unsigned*>(outh + (size_t)(base + r + 8) * 128 + col) =
            *reinterpret_cast<unsigned*>(&h23);
    }
}

// Layer-1 MMA: zh = half(h@Wn1), s = h@Ws1 + b1. K=128, N=48.
__global__ void __launch_bounds__(256) k_mma_zs1(
    const __half* __restrict__ h,
    const __half* __restrict__ WnT, const __half* __restrict__ WsT,  // [48][128]
    const float* __restrict__ bias,
    __half* __restrict__ zh, float* __restrict__ s) {
    int w = (blockIdx.x * blockDim.x + threadIdx.x) >> 5;
    int lane = threadIdx.x & 31;
    int base = w * 16;
    if (base >= NN) return;
    int r = lane >> 2, q = lane & 3;

    float cz[6][4], cs[6][4];
#pragma unroll
    for (int nt = 0; nt < 6; nt++)
#pragma unroll
        for (int j = 0; j < 4; j++) { cz[nt][j] = 0.f; cs[nt][j] = 0.f; }

#pragma unroll
    for (int ks = 0; ks < 8; ks++) {
        int k0 = ks * 16;
        unsigned a0 = ldu(h + (size_t)(base + r) * 128 + k0 + 2 * q);
        unsigned a1 = ldu(h + (size_t)(base + r + 8) * 128 + k0 + 2 * q);
        unsigned a2 = ldu(h + (size_t)(base + r) * 128 + k0 + 2 * q + 8);
        unsigned a3 = ldu(h + (size_t)(base + r + 8) * 128 + k0 + 2 * q + 8);
#pragma unroll
        for (int nt = 0; nt < 6; nt++) {
            int n = nt * 8 + r;
            unsigned bn0 = ldu(WnT + n * 128 + k0 + 2 * q);
            unsigned bn1 = ldu(WnT + n * 128 + k0 + 2 * q + 8);
            mma16816(cz[nt], a0, a1, a2, a3, bn0, bn1);
            unsigned bs0 = ldu(WsT + n * 128 + k0 + 2 * q);
            unsigned bs1 = ldu(WsT + n * 128 + k0 + 2 * q + 8);
            mma16816(cs[nt], a0, a1, a2, a3, bs0, bs1);
        }
    }

#pragma unroll
    for (int nt = 0; nt < 6; nt++) {
        int col = nt * 8 + 2 * q;
        __half2 z01 = __floats2half2_rn(cz[nt][0], cz[nt][1]);
        __half2 z23 = __floats2half2_rn(cz[nt][2], cz[nt][3]);
        *reinterpret_cast<unsigned*>(zh + (size_t)(base + r) * 48 + col) =
            *reinterpret_cast<unsigned*>(&z01);
        *reinterpret_cast<unsigned*>(zh + (size_t)(base + r + 8) * 48 + col) =
            *reinterpret_cast<unsigned*>(&z23);
        float2 bb = *reinterpret_cast<const float2*>(bias + col);
        float2 s01 = make_float2(cs[nt][0] + bb.x, cs[nt][1] + bb.y);
        float2 s23 = make_float2(cs[nt][2] + bb.x, cs[nt][3] + bb.y);
        *reinterpret_cast<float2*>(s + (size_t)(base + r) * 48 + col) = s01;
        *reinterpret_cast<float2*>(s + (size_t)(base + r + 8) * 48 + col) = s23;
    }
}

// Layer-2 MMA: zh = half(h@Wn2), s = h@Ws2 + b2. K=48 (3 ksteps), N=28 pad 32.
__global__ void __launch_bounds__(256) k_mma_zs2(
    const __half* __restrict__ h,                                    // [NN][48]
    const __half* __restrict__ WnT, const __half* __restrict__ WsT,  // [32][48]
    const float* __restrict__ bias,
    __half* __restrict__ zh, float* __restrict__ s) {                // [NN][28]
    int w = (blockIdx.x * blockDim.x + threadIdx.x) >> 5;
    int lane = threadIdx.x & 31;
    int base = w * 16;
    if (base >= NN) return;
    int r = lane >> 2, q = lane & 3;

    float cz[4][4], cs[4][4];
#pragma unroll
    for (int nt = 0; nt < 4; nt++)
#pragma unroll
        for (int j = 0; j < 4; j++) { cz[nt][j] = 0.f; cs[nt][j] = 0.f; }

#pragma unroll
    for (int ks = 0; ks < 3; ks++) {
        int k0 = ks * 16;
        unsigned a0 = ldu(h + (size_t)(base + r) * 48 + k0 + 2 * q);
        unsigned a1 = ldu(h + (size_t)(base + r + 8) * 48 + k0 + 2 * q);
        unsigned a2 = ldu(h + (size_t)(base + r) * 48 + k0 + 2 * q + 8);
        unsigned a3 = ldu(h + (size_t)(base + r + 8) * 48 + k0 + 2 * q + 8);
#pragma unroll
        for (int nt = 0; nt < 4; nt++) {
            int n = nt * 8 + r;
            unsigned bn0 = ldu(WnT + n * 48 + k0 + 2 * q);
            unsigned bn1 = ldu(WnT + n * 48 + k0 + 2 * q + 8);
            mma16816(cz[nt], a0, a1, a2, a3, bn0, bn1);
            unsigned bs0 = ldu(WsT + n * 48 + k0 + 2 * q);
            unsigned bs1 = ldu(WsT + n * 48 + k0 + 2 * q + 8);
            mma16816(cs[nt], a0, a1, a2, a3, bs0, bs1);
        }
    }

#pragma unroll
    for (int nt = 0; nt < 4; nt++) {
        int col = nt * 8 + 2 * q;
        if (col < 28) {
            __half2 z01 = __floats2half2_rn(cz[nt][0], cz[nt][1]);
            __half2 z23 = __floats2half2_rn(cz[nt][2], cz[nt][3]);
            *reinterpret_cast<unsigned*>(zh + (size_t)(base + r) * 28 + col) =
                *reinterpret_cast<unsigned*>(&z01);
            *reinterpret_cast<unsigned*>(zh + (size_t)(base + r + 8) * 28 + col) =
                *reinterpret_cast<unsigned*>(&z23);
            float2 bb = *reinterpret_cast<const float2*>(bias + col);
            float2 s01 = make_float2(cs[nt][0] + bb.x, cs[nt][1] + bb.y);
            float2 s23 = make_float2(cs[nt][2] + bb.x, cs[nt][3] + bb.y);
            *reinterpret_cast<float2*>(s + (size_t)(base + r) * 28 + col) = s01;
            *reinterpret_cast<float2*>(s + (size_t)(base + r + 8) * 28 + col) = s23;
        }
    }
}

// scalar combined z/s for DOUT=5 (layer 3, fp32)
template <int DIN, int DOUT>
__global__ void k_zsS(const float* __restrict__ h, const float* __restrict__ Wn,
                      const float* __restrict__ Ws, const float* __restrict__ bias,
                      float* __restrict__ z, float* __restrict__ s) {
    long long idx = (long long)blockIdx.x * blockDim.x + threadIdx.x;
    if (idx >= (long long)NN * DOUT) return;
    int v = (int)(idx / DOUT);
    int o = (int)(idx % DOUT);
    const float* hrow = h + (size_t)v * DIN;
    float accz = 0.0f;
    float accs = bias[o];
#pragma unroll
    for (int k = 0; k < DIN; k++) {
        float hv = hrow[k];
        accz = fmaf(hv, Wn[k * DOUT + o], accz);
        accs = fmaf(hv, Ws[k * DOUT + o], accs);
    }
    z[idx] = accz;
    s[idx] = accs;
}

// ---------------------------------------------------------------------------
__global__ void k_readout(const float* __restrict__ h, const int* __restrict__ gid,
                          float* __restrict__ out) {
    int v = blockIdx.x * blockDim.x + threadIdx.x;
    bool ok = (v < NN);
    int g = ok ? gid[v] : -1;
    float c = ok ? 1.0f : 0.0f;
    float f0 = 0, f1 = 0, f2 = 0, f3 = 0, f4 = 0;
    if (ok) {
        const float* hr = h + (size_t)v * 5;
        f0 = hr[0]; f1 = hr[1]; f2 = hr[2]; f3 = hr[3]; f4 = hr[4];
    }
    int g0 = __shfl_sync(0xFFFFFFFFu, ok ? g : __shfl_sync(0xFFFFFFFFu, g, 0), 0);
    bool uniform = __all_sync(0xFFFFFFFFu, !ok || g == g0);
    if (uniform) {
#pragma unroll
        for (int m = 16; m > 0; m >>= 1) {
            c  += __shfl_xor_sync(0xFFFFFFFFu, c, m);
            f0 += __shfl_xor_sync(0xFFFFFFFFu, f0, m);
            f1 += __shfl_xor_sync(0xFFFFFFFFu, f1, m);
            f2 += __shfl_xor_sync(0xFFFFFFFFu, f2, m);
            f3 += __shfl_xor_sync(0xFFFFFFFFu, f3, m);
            f4 += __shfl_xor_sync(0xFFFFFFFFu, f4, m);
        }
        if ((threadIdx.x & 31) == 0 && c > 0.0f) {
            atomicAdd(&g_cnt[g0], c);
            atomicAdd(&out[g0 * 5 + 0], f0);
            atomicAdd(&out[g0 * 5 + 1], f1);
            atomicAdd(&out[g0 * 5 + 2], f2);
            atomicAdd(&out[g0 * 5 + 3], f3);
            atomicAdd(&out[g0 * 5 + 4], f4);
        }
    } else if (ok) {
        atomicAdd(&g_cnt[g], 1.0f);
        atomicAdd(&out[g * 5 + 0], f0);
        atomicAdd(&out[g * 5 + 1], f1);
        atomicAdd(&out[g * 5 + 2], f2);
        atomicAdd(&out[g * 5 + 3], f3);
        atomicAdd(&out[g * 5 + 4], f4);
    }
}

__global__ void k_final(float* __restrict__ out) {
    int i = blockIdx.x * blockDim.x + threadIdx.x;
    if (i < NG * 5) out[i] /= fmaxf(g_cnt[i / 5], 1.0f);
}

// ---------------------------------------------------------------------------
static inline int blks(long long n, int t) { return (int)((n + t - 1) / t); }

extern "C" void kernel_launch(void* const* d_in, const int* in_sizes, int n_in,
                              void* d_out, int out_size) {
    const float* feat = (const float*)d_in[0];
    const int* src = (const int*)d_in[1];
    const int* dst = (const int*)d_in[2];
    const int* gid = (const int*)d_in[3];
    const float* Ws0 = (const float*)d_in[4];
    const float* Wn0 = (const float*)d_in[5];
    const float* b0  = (const float*)d_in[6];
    const float* Ws1 = (const float*)d_in[7];
    const float* Wn1 = (const float*)d_in[8];
    const float* b1  = (const float*)d_in[9];
    const float* Ws2 = (const float*)d_in[10];
    const float* Wn2 = (const float*)d_in[11];
    const float* b2  = (const float*)d_in[12];
    const float* Ws3 = (const float*)d_in[13];
    const float* Wn3 = (const float*)d_in[14];
    const float* b3  = (const float*)d_in[15];
    float* out = (float*)d_out;

    float *bufC, *bufD, *z, *s, *cnt;
    __half *bufAh, *bufBh, *feath, *aggh, *zh;
    __half *WsT0, *WnT0, *WsT1, *WnT1, *WsT2, *WnT2;
    int *degi;
    cudaGetSymbolAddress((void**)&bufAh, g_bufAh);
    cudaGetSymbolAddress((void**)&bufBh, g_bufBh);
    cudaGetSymbolAddress((void**)&bufC, g_bufC);
    cudaGetSymbolAddress((void**)&bufD, g_bufD);
    cudaGetSymbolAddress((void**)&z, g_z);
    cudaGetSymbolAddress((void**)&s, g_s);
    cudaGetSymbolAddress((void**)&cnt, g_cnt);
    cudaGetSymbolAddress((void**)&degi, g_degi);
    cudaGetSymbolAddress((void**)&feath, g_feath);
    cudaGetSymbolAddress((void**)&aggh, g_aggh);
    cudaGetSymbolAddress((void**)&zh, g_zh);
    cudaGetSymbolAddress((void**)&WsT0, g_WsT0);
    cudaGetSymbolAddress((void**)&WnT0, g_WnT0);
    cudaGetSymbolAddress((void**)&WsT1, g_WsT1);
    cudaGetSymbolAddress((void**)&WnT1, g_WnT1);
    cudaGetSymbolAddress((void**)&WsT2, g_WsT2);
    cudaGetSymbolAddress((void**)&WnT2, g_WnT2);

    const int T = 256;

    // ---- input conversions (independent of CSR) ----
    k_cvtfeat<<<blks((long long)NN * 8, T), T>>>(feat, feath);
    {
        int totW = 2 * (128 * 32) + 2 * (48 * 128) + 2 * (32 * 48);
        k_cvtAllW<<<blks(totW, T), T>>>(Ws0, Wn0, Ws1, Wn1, Ws2, Wn2);
    }

    // ---- CSR build (single atomic pass + atomic-free fill) ----
    cudaMemsetAsync(degi, 0, NN * sizeof(int));
    k_degrank<<<blks(NE, T), T>>>(dst);
    k_scan1<<<NB, 1024>>>();
    k_scan2<<<1, 256>>>();
    k_scan3<<<NB, 1024>>>();
    k_build<<<blks(NE, T), T>>>(src, dst);

    // ---- layer 0: gather (fp16 out) + tensor-core dual projection ----
    k_gather32H<<<blks((long long)NN * 32, T), T>>>(feath, aggh);
    k_mma_sage0<<<blks((long long)(NN / 16) * 32, T), T>>>(feath, aggh, WsT0, WnT0, b0, bufAh);

    // ---- layer 1: tensor-core zs + fused gather (fp16 out) ----
    k_mma_zs1<<<blks((long long)(NN / 16) * 32, T), T>>>(bufAh, WnT1, WsT1, b1, zh, s);
    k_gatherHh<48, 4, true><<<blks((long long)NN * 32, T), T>>>(zh, s, bufBh);

    // ---- layer 2: tensor-core zs (48->28, padded) + fused gather ----
    k_mma_zs2<<<blks((long long)(NN / 16) * 32, T), T>>>(bufBh, WnT2, WsT2, b2, zh, s);
    k_gatherH2<28, 4, true><<<blks((long long)NN * 32, T), T>>>(zh, s, bufC);

    // ---- layer 3: 28 -> 5, linear (fp32) ----
    k_zsS<28, 5><<<blks((long long)NN * 5, T), T>>>(bufC, Wn3, Ws3, b3, z, s);
    k_gatherF5<<<blks((long long)NN * 32, T), T>>>(z, s, bufD);

    // ---- readout ----
    cudaMemsetAsync(out, 0, NG * 5 * sizeof(float));
    cudaMemsetAsync(cnt, 0, NG * sizeof(float));
    k_readout<<<blks(NN, T), T>>>(bufD, gid, out);
    k_final<<<blks(NG * 5, T), T>>>(out);
}

// round 15
// speedup vs baseline: 1.8454x; 1.0252x over previous
#include <cuda_runtime.h>
#include <cuda_bf16.h>
#include <cuda_fp16.h>

static const int NN = 200000;
static const int NE = 3200000;
static const int NG = 400;
static const int NB = (NN + 1023) / 1024;  // 196 scan blocks

// Scratch (device globals; no runtime allocation allowed)
__device__ int    g_degi[NN];
__device__ int    g_off[NN + 1];
__device__ int    g_rank[NE];
__device__ int    g_csr[NE];
__device__ int    g_bsum[256];
__device__ __half g_bufAh[(size_t)NN * 128];  // layer0 output (fp16, mma operand)
__device__ __half g_bufBh[(size_t)NN * 48];   // layer1 output (fp16, mma operand)
__device__ float  g_bufC[(size_t)NN * 28];    // layer2 output (fp32)
__device__ float  g_bufD[(size_t)NN * 5];     // layer3 output (fp32)
__device__ __half g_feath[(size_t)NN * 32];   // fp16 copy of feat
__device__ __half g_aggh[(size_t)NN * 32];    // fp16 layer-0 aggregate
__device__ __half g_zh[(size_t)NN * 48];      // fp16 projected neighbor features
__device__ float  g_z[(size_t)NN * 48];       // fp32 z for layer 3
__device__ float  g_s[(size_t)NN * 48];       // self-projection + bias
__device__ __half g_WsT0[128 * 32];           // transposed fp16 weights [N][K]
__device__ __half g_WnT0[128 * 32];
__device__ __half g_WsT1[48 * 128];
__device__ __half g_WnT1[48 * 128];
__device__ __half g_WsT2[32 * 48];            // padded N: 28 -> 32 (zero rows)
__device__ __half g_WnT2[32 * 48];
__device__ float  g_cnt[NG];

// ---------------------------------------------------------------------------
__global__ void k_degrank(const int* __restrict__ dst) {
    int e = blockIdx.x * blockDim.x + threadIdx.x;
    if (e < NE) g_rank[e] = atomicAdd(&g_degi[dst[e]], 1);
}

__global__ void k_scan1() {
    __shared__ int sh[1024];
    int t = threadIdx.x;
    int j = blockIdx.x * 1024 + t;
    sh[t] = (j < NN) ? g_degi[j] : 0;
    __syncthreads();
    for (int d = 512; d > 0; d >>= 1) {
        if (t < d) sh[t] += sh[t + d];
        __syncthreads();
    }
    if (t == 0) g_bsum[blockIdx.x] = sh[0];
}

__global__ void k_scan2() {
    __shared__ int sh[256];
    int t = threadIdx.x;
    int v = (t < NB) ? g_bsum[t] : 0;
    sh[t] = v;
    __syncthreads();
    for (int d = 1; d < 256; d <<= 1) {
        int x = (t >= d) ? sh[t - d] : 0;
        __syncthreads();
        sh[t] += x;
        __syncthreads();
    }
    g_bsum[t] = sh[t] - v;
}

__global__ void k_scan3() {
    __shared__ int sh[1024];
    int t = threadIdx.x;
    int j = blockIdx.x * 1024 + t;
    int v = (j < NN) ? g_degi[j] : 0;
    sh[t] = v;
    __syncthreads();
    for (int d = 1; d < 1024; d <<= 1) {
        int x = (t >= d) ? sh[t - d] : 0;
        __syncthreads();
        sh[t] += x;
        __syncthreads();
    }
    int excl = sh[t] - v + g_bsum[blockIdx.x];
    if (j < NN) g_off[j] = excl;
    if (j == NN - 1) g_off[NN] = excl + v;
}

__global__ void k_build(const int* __restrict__ src, const int* __restrict__ dst) {
    int e = blockIdx.x * blockDim.x + threadIdx.x;
    if (e >= NE) return;
    int d = dst[e];
    g_csr[g_off[d] + g_rank[e]] = src[e];
}

// feat fp32 -> fp16
__global__ void k_cvtfeat(const float* __restrict__ f, __half* __restrict__ fh) {
    int i = blockIdx.x * blockDim.x + threadIdx.x;
    if (i >= NN * 32 / 4) return;
    float4 v = reinterpret_cast<const float4*>(f)[i];
    __half2 a = __floats2half2_rn(v.x, v.y);
    __half2 b = __floats2half2_rn(v.z, v.w);
    reinterpret_cast<uint2*>(fh)[i] =
        make_uint2(*reinterpret_cast<unsigned*>(&a), *reinterpret_cast<unsigned*>(&b));
}

// all weight transposes fused: [K][N] fp32 -> [N][K] fp16 (layer2 N padded to 32)
__global__ void k_cvtAllW(const float* Ws0, const float* Wn0,
                          const float* Ws1, const float* Wn1,
                          const float* Ws2, const float* Wn2) {
    int i = blockIdx.x * blockDim.x + threadIdx.x;
    const int S0 = 128 * 32, S1 = 48 * 128, S2 = 32 * 48;
    if (i < S0) {
        int o = i / 32, k = i % 32;
        g_WsT0[i] = __float2half(Ws0[k * 128 + o]);
    } else if (i < 2 * S0) {
        int j = i - S0;
        int o = j / 32, k = j % 32;
        g_WnT0[j] = __float2half(Wn0[k * 128 + o]);
    } else if (i < 2 * S0 + S1) {
        int j = i - 2 * S0;
        int o = j / 128, k = j % 128;
        g_WsT1[j] = __float2half(Ws1[k * 48 + o]);
    } else if (i < 2 * S0 + 2 * S1) {
        int j = i - 2 * S0 - S1;
        int o = j / 128, k = j % 128;
        g_WnT1[j] = __float2half(Wn1[k * 48 + o]);
    } else if (i < 2 * S0 + 2 * S1 + S2) {
        int j = i - 2 * S0 - 2 * S1;
        int o = j / 48, k = j % 48;
        g_WsT2[j] = (o < 28) ? __float2half(Ws2[k * 28 + o]) : __float2half(0.0f);
    } else if (i < 2 * S0 + 2 * S1 + 2 * S2) {
        int j = i - 2 * S0 - 2 * S1 - S2;
        int o = j / 48, k = j % 48;
        g_WnT2[j] = (o < 28) ? __float2half(Wn2[k * 28 + o]) : __float2half(0.0f);
    }
}

// ---------------------------------------------------------------------------
__device__ __forceinline__ void acc8(float4& a0, float4& a1, const uint4& t) {
    float2 f0 = __half22float2(*reinterpret_cast<const __half2*>(&t.x));
    float2 f1 = __half22float2(*reinterpret_cast<const __half2*>(&t.y));
    float2 f2 = __half22float2(*reinterpret_cast<const __half2*>(&t.z));
    float2 f3 = __half22float2(*reinterpret_cast<const __half2*>(&t.w));
    a0.x += f0.x; a0.y += f0.y; a0.z += f1.x; a0.w += f1.y;
    a1.x += f2.x; a1.y += f2.y; a1.z += f3.x; a1.w += f3.y;
}

__device__ __forceinline__ void acc8p(float4& a0, float4& a1, const uint4& ta, const uint4& tb) {
    __half2 p0 = __hadd2(*reinterpret_cast<const __half2*>(&ta.x), *reinterpret_cast<const __half2*>(&tb.x));
    __half2 p1 = __hadd2(*reinterpret_cast<const __half2*>(&ta.y), *reinterpret_cast<const __half2*>(&tb.y));
    __half2 p2 = __hadd2(*reinterpret_cast<const __half2*>(&ta.z), *reinterpret_cast<const __half2*>(&tb.z));
    __half2 p3 = __hadd2(*reinterpret_cast<const __half2*>(&ta.w), *reinterpret_cast<const __half2*>(&tb.w));
    float2 f0 = __half22float2(p0), f1 = __half22float2(p1);
    float2 f2 = __half22float2(p2), f3 = __half22float2(p3);
    a0.x += f0.x; a0.y += f0.y; a0.z += f1.x; a0.w += f1.y;
    a1.x += f2.x; a1.y += f2.y; a1.z += f3.x; a1.w += f3.y;
}

__device__ __forceinline__ void acc4p(float4& a0, const uint2& ta, const uint2& tb) {
    __half2 p0 = __hadd2(*reinterpret_cast<const __half2*>(&ta.x), *reinterpret_cast<const __half2*>(&tb.x));
    __half2 p1 = __hadd2(*reinterpret_cast<const __half2*>(&ta.y), *reinterpret_cast<const __half2*>(&tb.y));
    float2 f0 = __half22float2(p0), f1 = __half22float2(p1);
    a0.x += f0.x; a0.y += f0.y; a0.z += f1.x; a0.w += f1.y;
}

__device__ __forceinline__ void acc4(float4& a0, const uint2& t) {
    float2 f0 = __half22float2(*reinterpret_cast<const __half2*>(&t.x));
    float2 f1 = __half22float2(*reinterpret_cast<const __half2*>(&t.y));
    a0.x += f0.x; a0.y += f0.y; a0.z += f1.x; a0.w += f1.y;
}

// fp16 gather for layer 0 (DIM=32, 8 slots, 4-deep unroll), fp16 output
__global__ void k_gather32H(const __half* __restrict__ zh, __half* __restrict__ aggh) {
    constexpr int DIM = 32, SLOTS = 8;
    constexpr int NCH = DIM / 8;
    constexpr int F4L = 32 / SLOTS;
    int gt = blockIdx.x * blockDim.x + threadIdx.x;
    int v = gt >> 5;
    if (v >= NN) return;
    int lane = gt & 31;
    int slot = lane / F4L;
    int f4 = lane % F4L;
    bool act = (f4 < NCH);

    int beg = g_off[v];
    int end = g_off[v + 1];
    float4 a0 = make_float4(0.f, 0.f, 0.f, 0.f);
    float4 a1 = make_float4(0.f, 0.f, 0.f, 0.f);

    int e = beg;
    for (; e + 4 * SLOTS <= end; e += 4 * SLOTS) {
        int s0 = g_csr[e + slot];
        int s1 = g_csr[e + SLOTS + slot];
        int s2 = g_csr[e + 2 * SLOTS + slot];
        int s3 = g_csr[e + 3 * SLOTS + slot];
        if (act) {
            uint4 t0 = __ldg(reinterpret_cast<const uint4*>(zh + (size_t)s0 * DIM) + f4);
            uint4 t1 = __ldg(reinterpret_cast<const uint4*>(zh + (size_t)s1 * DIM) + f4);
            uint4 t2 = __ldg(reinterpret_cast<const uint4*>(zh + (size_t)s2 * DIM) + f4);
            uint4 t3 = __ldg(reinterpret_cast<const uint4*>(zh + (size_t)s3 * DIM) + f4);
            acc8p(a0, a1, t0, t1);
            acc8p(a0, a1, t2, t3);
        }
    }
    for (; e < end; e += SLOTS) {
        int myE = e + slot;
        if (myE < end && act) {
            uint4 t0 = __ldg(reinterpret_cast<const uint4*>(zh + (size_t)g_csr[myE] * DIM) + f4);
            acc8(a0, a1, t0);
        }
    }
#pragma unroll
    for (int m = F4L; m < 32; m <<= 1) {
        a0.x += __shfl_xor_sync(0xFFFFFFFFu, a0.x, m);
        a0.y += __shfl_xor_sync(0xFFFFFFFFu, a0.y, m);
        a0.z += __shfl_xor_sync(0xFFFFFFFFu, a0.z, m);
        a0.w += __shfl_xor_sync(0xFFFFFFFFu, a0.w, m);
        a1.x += __shfl_xor_sync(0xFFFFFFFFu, a1.x, m);
        a1.y += __shfl_xor_sync(0xFFFFFFFFu, a1.y, m);
        a1.z += __shfl_xor_sync(0xFFFFFFFFu, a1.z, m);
        a1.w += __shfl_xor_sync(0xFFFFFFFFu, a1.w, m);
    }
    float inv = 1.0f / fmaxf((float)(end - beg), 1.0f);
    if (slot == 0 && act) {
        __half2 h0 = __floats2half2_rn(a0.x * inv, a0.y * inv);
        __half2 h1 = __floats2half2_rn(a0.z * inv, a0.w * inv);
        __half2 h2 = __floats2half2_rn(a1.x * inv, a1.y * inv);
        __half2 h3 = __floats2half2_rn(a1.z * inv, a1.w * inv);
        reinterpret_cast<uint4*>(aggh + (size_t)v * DIM)[f4] =
            make_uint4(*reinterpret_cast<unsigned*>(&h0), *reinterpret_cast<unsigned*>(&h1),
                       *reinterpret_cast<unsigned*>(&h2), *reinterpret_cast<unsigned*>(&h3));
    }
}

// fp16 gather, uint4 chunks, 4-deep unroll, fused epilogue, fp16 out (layer 1)
template <int DIM, int SLOTS, bool RELU>
__global__ void k_gatherHh(const __half* __restrict__ zh, const float* __restrict__ s,
                           __half* __restrict__ outh) {
    constexpr int NCH = DIM / 8;
    constexpr int F4L = 32 / SLOTS;
    int gt = blockIdx.x * blockDim.x + threadIdx.x;
    int v = gt >> 5;
    if (v >= NN) return;
    int lane = gt & 31;
    int slot = lane / F4L;
    int f4 = lane % F4L;
    bool act = (f4 < NCH);

    int beg = g_off[v];
    int end = g_off[v + 1];
    float4 a0 = make_float4(0.f, 0.f, 0.f, 0.f);
    float4 a1 = make_float4(0.f, 0.f, 0.f, 0.f);

    int e = beg;
    for (; e + 4 * SLOTS <= end; e += 4 * SLOTS) {
        int s0 = g_csr[e + slot];
        int s1 = g_csr[e + SLOTS + slot];
        int s2 = g_csr[e + 2 * SLOTS + slot];
        int s3 = g_csr[e + 3 * SLOTS + slot];
        if (act) {
            uint4 t0 = __ldg(reinterpret_cast<const uint4*>(zh + (size_t)s0 * DIM) + f4);
            uint4 t1 = __ldg(reinterpret_cast<const uint4*>(zh + (size_t)s1 * DIM) + f4);
            uint4 t2 = __ldg(reinterpret_cast<const uint4*>(zh + (size_t)s2 * DIM) + f4);
            uint4 t3 = __ldg(reinterpret_cast<const uint4*>(zh + (size_t)s3 * DIM) + f4);
            acc8p(a0, a1, t0, t1);
            acc8p(a0, a1, t2, t3);
        }
    }
    for (; e < end; e += SLOTS) {
        int myE = e + slot;
        if (myE < end && act) {
            uint4 t0 = __ldg(reinterpret_cast<const uint4*>(zh + (size_t)g_csr[myE] * DIM) + f4);
            acc8(a0, a1, t0);
        }
    }
#pragma unroll
    for (int m = F4L; m < 32; m <<= 1) {
        a0.x += __shfl_xor_sync(0xFFFFFFFFu, a0.x, m);
        a0.y += __shfl_xor_sync(0xFFFFFFFFu, a0.y, m);
        a0.z += __shfl_xor_sync(0xFFFFFFFFu, a0.z, m);
        a0.w += __shfl_xor_sync(0xFFFFFFFFu, a0.w, m);
        a1.x += __shfl_xor_sync(0xFFFFFFFFu, a1.x, m);
        a1.y += __shfl_xor_sync(0xFFFFFFFFu, a1.y, m);
        a1.z += __shfl_xor_sync(0xFFFFFFFFu, a1.z, m);
        a1.w += __shfl_xor_sync(0xFFFFFFFFu, a1.w, m);
    }
    float inv = 1.0f / fmaxf((float)(end - beg), 1.0f);
    if (slot == 0 && act) {
        const float* sp = s + (size_t)v * DIM + f4 * 8;
        float4 s0v = *reinterpret_cast<const float4*>(sp);
        float4 s1v = *reinterpret_cast<const float4*>(sp + 4);
        float r0 = s0v.x + a0.x * inv, r1 = s0v.y + a0.y * inv;
        float r2 = s0v.z + a0.z * inv, r3 = s0v.w + a0.w * inv;
        float r4 = s1v.x + a1.x * inv, r5 = s1v.y + a1.y * inv;
        float r6 = s1v.z + a1.z * inv, r7 = s1v.w + a1.w * inv;
        if (RELU) {
            r0 = fmaxf(r0, 0.f); r1 = fmaxf(r1, 0.f); r2 = fmaxf(r2, 0.f); r3 = fmaxf(r3, 0.f);
            r4 = fmaxf(r4, 0.f); r5 = fmaxf(r5, 0.f); r6 = fmaxf(r6, 0.f); r7 = fmaxf(r7, 0.f);
        }
        __half2 h0 = __floats2half2_rn(r0, r1);
        __half2 h1 = __floats2half2_rn(r2, r3);
        __half2 h2 = __floats2half2_rn(r4, r5);
        __half2 h3 = __floats2half2_rn(r6, r7);
        reinterpret_cast<uint4*>(outh + (size_t)v * DIM)[f4] =
            make_uint4(*reinterpret_cast<unsigned*>(&h0), *reinterpret_cast<unsigned*>(&h1),
                       *reinterpret_cast<unsigned*>(&h2), *reinterpret_cast<unsigned*>(&h3));
    }
}

// fp16 gather, uint2 chunks, 4-deep unroll (layer 2, DIM=28), fused fp32 epilogue
template <int DIM, int SLOTS, bool RELU>
__global__ void k_gatherH2(const __half* __restrict__ zh, const float* __restrict__ s,
                           float* __restrict__ out) {
    constexpr int NCH = DIM / 4;
    constexpr int F4L = 32 / SLOTS;
    int gt = blockIdx.x * blockDim.x + threadIdx.x;
    int v = gt >> 5;
    if (v >= NN) return;
    int lane = gt & 31;
    int slot = lane / F4L;
    int f4 = lane % F4L;
    bool act = (f4 < NCH);

    int beg = g_off[v];
    int end = g_off[v + 1];
    float4 a0 = make_float4(0.f, 0.f, 0.f, 0.f);

    int e = beg;
    for (; e + 4 * SLOTS <= end; e += 4 * SLOTS) {
        int s0 = g_csr[e + slot];
        int s1 = g_csr[e + SLOTS + slot];
        int s2 = g_csr[e + 2 * SLOTS + slot];
        int s3 = g_csr[e + 3 * SLOTS + slot];
        if (act) {
            uint2 t0 = __ldg(reinterpret_cast<const uint2*>(zh + (size_t)s0 * DIM) + f4);
            uint2 t1 = __ldg(reinterpret_cast<const uint2*>(zh + (size_t)s1 * DIM) + f4);
            uint2 t2 = __ldg(reinterpret_cast<const uint2*>(zh + (size_t)s2 * DIM) + f4);
            uint2 t3 = __ldg(reinterpret_cast<const uint2*>(zh + (size_t)s3 * DIM) + f4);
            acc4p(a0, t0, t1);
            acc4p(a0, t2, t3);
        }
    }
    for (; e < end; e += SLOTS) {
        int myE = e + slot;
        if (myE < end && act) {
            uint2 t0 = __ldg(reinterpret_cast<const uint2*>(zh + (size_t)g_csr[myE] * DIM) + f4);
            acc4(a0, t0);
        }
    }
#pragma unroll
    for (int m = F4L; m < 32; m <<= 1) {
        a0.x += __shfl_xor_sync(0xFFFFFFFFu, a0.x, m);
        a0.y += __shfl_xor_sync(0xFFFFFFFFu, a0.y, m);
        a0.z += __shfl_xor_sync(0xFFFFFFFFu, a0.z, m);
        a0.w += __shfl_xor_sync(0xFFFFFFFFu, a0.w, m);
    }
    float inv = 1.0f / fmaxf((float)(end - beg), 1.0f);
    if (slot == 0 && act) {
        const float* sp = s + (size_t)v * DIM + f4 * 4;
        float4 sv = *reinterpret_cast<const float4*>(sp);
        float4 r = make_float4(sv.x + a0.x * inv, sv.y + a0.y * inv,
                               sv.z + a0.z * inv, sv.w + a0.w * inv);
        if (RELU) {
            r.x = fmaxf(r.x, 0.f); r.y = fmaxf(r.y, 0.f);
            r.z = fmaxf(r.z, 0.f); r.w = fmaxf(r.w, 0.f);
        }
        *reinterpret_cast<float4*>(out + (size_t)v * DIM + f4 * 4) = r;
    }
}

// fused scalar gather for DIM=5 (layer 3, fp32 z, no relu)
__global__ void k_gatherF5(const float* __restrict__ z, const float* __restrict__ s,
                           float* __restrict__ out) {
    constexpr int DIM = 5;
    int gt = blockIdx.x * blockDim.x + threadIdx.x;
    int v = gt >> 5;
    if (v >= NN) return;
    int lane = gt & 31;
    int slot = lane >> 3;
    int f = lane & 7;
    bool act = (f < DIM);

    int beg = g_off[v];
    int end = g_off[v + 1];
    float acc = 0.0f;
    int e = beg;
    for (; e + 16 <= end; e += 16) {
        int s0 = g_csr[e + slot];
        int s1 = g_csr[e + 4 + slot];
        int s2 = g_csr[e + 8 + slot];
        int s3 = g_csr[e + 12 + slot];
        if (act) {
            acc += (z[(size_t)s0 * DIM + f] + z[(size_t)s1 * DIM + f]) +
                   (z[(size_t)s2 * DIM + f] + z[(size_t)s3 * DIM + f]);
        }
    }
    for (; e < end; e += 4) {
        int myE = e + slot;
        if (myE < end && act) acc += z[(size_t)g_csr[myE] * DIM + f];
    }
#pragma unroll
    for (int m = 8; m < 32; m <<= 1) acc += __shfl_xor_sync(0xFFFFFFFFu, acc, m);
    float inv = 1.0f / fmaxf((float)(end - beg), 1.0f);
    if (slot == 0 && act)
        out[(size_t)v * DIM + f] = s[(size_t)v * DIM + f] + acc * inv;
}

// ---------------------------------------------------------------------------
__device__ __forceinline__ void mma16816(float c[4], unsigned a0, unsigned a1,
                                         unsigned a2, unsigned a3,
                                         unsigned b0, unsigned b1) {
    asm volatile(
        "mma.sync.aligned.m16n8k16.row.col.f32.f16.f16.f32 "
        "{%0,%1,%2,%3}, {%4,%5,%6,%7}, {%8,%9}, {%0,%1,%2,%3};"
        : "+f"(c[0]), "+f"(c[1]), "+f"(c[2]), "+f"(c[3])
        : "r"(a0), "r"(a1), "r"(a2), "r"(a3), "r"(b0), "r"(b1));
}

__device__ __forceinline__ unsigned ldu(const __half* p) {
    return *reinterpret_cast<const unsigned*>(p);
}

// Layer-0 MMA: bufAh = relu( feat_h@Ws0 + agg_h@Wn0 + b0 ), warp = 16 nodes.
__global__ void __launch_bounds__(256) k_mma_sage0(
    const __half* __restrict__ fh, const __half* __restrict__ ah,
    const __half* __restrict__ WsT, const __half* __restrict__ WnT,  // [128][32]
    const float* __restrict__ bias, __half* __restrict__ outh) {
    int w = (blockIdx.x * blockDim.x + threadIdx.x) >> 5;
    int lane = threadIdx.x & 31;
    int base = w * 16;
    if (base >= NN) return;
    int r = lane >> 2, q = lane & 3;

    float c[16][4];
#pragma unroll
    for (int nt = 0; nt < 16; nt++)
#pragma unroll
        for (int j = 0; j < 4; j++) c[nt][j] = 0.f;

#pragma unroll
    for (int ks = 0; ks < 2; ks++) {
        int k0 = ks * 16;
        unsigned fa0 = ldu(fh + (size_t)(base + r) * 32 + k0 + 2 * q);
        unsigned fa1 = ldu(fh + (size_t)(base + r + 8) * 32 + k0 + 2 * q);
        unsigned fa2 = ldu(fh + (size_t)(base + r) * 32 + k0 + 2 * q + 8);
        unsigned fa3 = ldu(fh + (size_t)(base + r + 8) * 32 + k0 + 2 * q + 8);
        unsigned ga0 = ldu(ah + (size_t)(base + r) * 32 + k0 + 2 * q);
        unsigned ga1 = ldu(ah + (size_t)(base + r + 8) * 32 + k0 + 2 * q);
        unsigned ga2 = ldu(ah + (size_t)(base + r) * 32 + k0 + 2 * q + 8);
        unsigned ga3 = ldu(ah + (size_t)(base + r + 8) * 32 + k0 + 2 * q + 8);
#pragma unroll
        for (int nt = 0; nt < 16; nt++) {
            int n = nt * 8 + r;
            unsigned bs0 = ldu(WsT + n * 32 + k0 + 2 * q);
            unsigned bs1 = ldu(WsT + n * 32 + k0 + 2 * q + 8);
            mma16816(c[nt], fa0, fa1, fa2, fa3, bs0, bs1);
            unsigned bn0 = ldu(WnT + n * 32 + k0 + 2 * q);
            unsigned bn1 = ldu(WnT + n * 32 + k0 + 2 * q + 8);
            mma16816(c[nt], ga0, ga1, ga2, ga3, bn0, bn1);
        }
    }

#pragma unroll
    for (int nt = 0; nt < 16; nt++) {
        int col = nt * 8 + 2 * q;
        float2 bb = *reinterpret_cast<const float2*>(bias + col);
        float v0 = fmaxf(c[nt][0] + bb.x, 0.f);
        float v1 = fmaxf(c[nt][1] + bb.y, 0.f);
        float v2 = fmaxf(c[nt][2] + bb.x, 0.f);
        float v3 = fmaxf(c[nt][3] + bb.y, 0.f);
        __half2 h01 = __floats2half2_rn(v0, v1);
        __half2 h23 = __floats2half2_rn(v2, v3);
        *reinterpret_cast<unsigned*>(outh + (size_t)(base + r) * 128 + col) =
            *reinterpret_cast<unsigned*>(&h01);
        *reinterpret_cast<unsigned*>(outh + (size_t)(base + r + 8) * 128 + col) =
            *reinterpret_cast<unsigned*>(&h23);
    }
}

// Layer-1 MMA: zh = half(h@Wn1), s = h@Ws1 + b1. K=128, N=48.
__global__ void __launch_bounds__(256) k_mma_zs1(
    const __half* __restrict__ h,
    const __half* __restrict__ WnT, const __half* __restrict__ WsT,  // [48][128]
    const float* __restrict__ bias,
    __half* __restrict__ zh, float* __restrict__ s) {
    int w = (blockIdx.x * blockDim.x + threadIdx.x) >> 5;
    int lane = threadIdx.x & 31;
    int base = w * 16;
    if (base >= NN) return;
    int r = lane >> 2, q = lane & 3;

    float cz[6][4], cs[6][4];
#pragma unroll
    for (int nt = 0; nt < 6; nt++)
#pragma unroll
        for (int j = 0; j < 4; j++) { cz[nt][j] = 0.f; cs[nt][j] = 0.f; }

#pragma unroll
    for (int ks = 0; ks < 8; ks++) {
        int k0 = ks * 16;
        unsigned a0 = ldu(h + (size_t)(base + r) * 128 + k0 + 2 * q);
        unsigned a1 = ldu(h + (size_t)(base + r + 8) * 128 + k0 + 2 * q);
        unsigned a2 = ldu(h + (size_t)(base + r) * 128 + k0 + 2 * q + 8);
        unsigned a3 = ldu(h + (size_t)(base + r + 8) * 128 + k0 + 2 * q + 8);
#pragma unroll
        for (int nt = 0; nt < 6; nt++) {
            int n = nt * 8 + r;
            unsigned bn0 = ldu(WnT + n * 128 + k0 + 2 * q);
            unsigned bn1 = ldu(WnT + n * 128 + k0 + 2 * q + 8);
            mma16816(cz[nt], a0, a1, a2, a3, bn0, bn1);
            unsigned bs0 = ldu(WsT + n * 128 + k0 + 2 * q);
            unsigned bs1 = ldu(WsT + n * 128 + k0 + 2 * q + 8);
            mma16816(cs[nt], a0, a1, a2, a3, bs0, bs1);
        }
    }

#pragma unroll
    for (int nt = 0; nt < 6; nt++) {
        int col = nt * 8 + 2 * q;
        __half2 z01 = __floats2half2_rn(cz[nt][0], cz[nt][1]);
        __half2 z23 = __floats2half2_rn(cz[nt][2], cz[nt][3]);
        *reinterpret_cast<unsigned*>(zh + (size_t)(base + r) * 48 + col) =
            *reinterpret_cast<unsigned*>(&z01);
        *reinterpret_cast<unsigned*>(zh + (size_t)(base + r + 8) * 48 + col) =
            *reinterpret_cast<unsigned*>(&z23);
        float2 bb = *reinterpret_cast<const float2*>(bias + col);
        float2 s01 = make_float2(cs[nt][0] + bb.x, cs[nt][1] + bb.y);
        float2 s23 = make_float2(cs[nt][2] + bb.x, cs[nt][3] + bb.y);
        *reinterpret_cast<float2*>(s + (size_t)(base + r) * 48 + col) = s01;
        *reinterpret_cast<float2*>(s + (size_t)(base + r + 8) * 48 + col) = s23;
    }
}

// Layer-2 MMA: zh = half(h@Wn2), s = h@Ws2 + b2. K=48 (3 ksteps), N=28 pad 32.
__global__ void __launch_bounds__(256) k_mma_zs2(
    const __half* __restrict__ h,                                    // [NN][48]
    const __half* __restrict__ WnT, const __half* __restrict__ WsT,  // [32][48]
    const float* __restrict__ bias,
    __half* __restrict__ zh, float* __restrict__ s) {                // [NN][28]
    int w = (blockIdx.x * blockDim.x + threadIdx.x) >> 5;
    int lane = threadIdx.x & 31;
    int base = w * 16;
    if (base >= NN) return;
    int r = lane >> 2, q = lane & 3;

    float cz[4][4], cs[4][4];
#pragma unroll
    for (int nt = 0; nt < 4; nt++)
#pragma unroll
        for (int j = 0; j < 4; j++) { cz[nt][j] = 0.f; cs[nt][j] = 0.f; }

#pragma unroll
    for (int ks = 0; ks < 3; ks++) {
        int k0 = ks * 16;
        unsigned a0 = ldu(h + (size_t)(base + r) * 48 + k0 + 2 * q);
        unsigned a1 = ldu(h + (size_t)(base + r + 8) * 48 + k0 + 2 * q);
        unsigned a2 = ldu(h + (size_t)(base + r) * 48 + k0 + 2 * q + 8);
        unsigned a3 = ldu(h + (size_t)(base + r + 8) * 48 + k0 + 2 * q + 8);
#pragma unroll
        for (int nt = 0; nt < 4; nt++) {
            int n = nt * 8 + r;
            unsigned bn0 = ldu(WnT + n * 48 + k0 + 2 * q);
            unsigned bn1 = ldu(WnT + n * 48 + k0 + 2 * q + 8);
            mma16816(cz[nt], a0, a1, a2, a3, bn0, bn1);
            unsigned bs0 = ldu(WsT + n * 48 + k0 + 2 * q);
            unsigned bs1 = ldu(WsT + n * 48 + k0 + 2 * q + 8);
            mma16816(cs[nt], a0, a1, a2, a3, bs0, bs1);
        }
    }

#pragma unroll
    for (int nt = 0; nt < 4; nt++) {
        int col = nt * 8 + 2 * q;
        if (col < 28) {
            __half2 z01 = __floats2half2_rn(cz[nt][0], cz[nt][1]);
            __half2 z23 = __floats2half2_rn(cz[nt][2], cz[nt][3]);
            *reinterpret_cast<unsigned*>(zh + (size_t)(base + r) * 28 + col) =
                *reinterpret_cast<unsigned*>(&z01);
            *reinterpret_cast<unsigned*>(zh + (size_t)(base + r + 8) * 28 + col) =
                *reinterpret_cast<unsigned*>(&z23);
            float2 bb = *reinterpret_cast<const float2*>(bias + col);
            float2 s01 = make_float2(cs[nt][0] + bb.x, cs[nt][1] + bb.y);
            float2 s23 = make_float2(cs[nt][2] + bb.x, cs[nt][3] + bb.y);
            *reinterpret_cast<float2*>(s + (size_t)(base + r) * 28 + col) = s01;
            *reinterpret_cast<float2*>(s + (size_t)(base + r + 8) * 28 + col) = s23;
        }
    }
}

// scalar combined z/s for DOUT=5 (layer 3, fp32)
template <int DIN, int DOUT>
__global__ void k_zsS(const float* __restrict__ h, const float* __restrict__ Wn,
                      const float* __restrict__ Ws, const float* __restrict__ bias,
                      float* __restrict__ z, float* __restrict__ s) {
    long long idx = (long long)blockIdx.x * blockDim.x + threadIdx.x;
    if (idx >= (long long)NN * DOUT) return;
    int v = (int)(idx / DOUT);
    int o = (int)(idx % DOUT);
    const float* hrow = h + (size_t)v * DIN;
    float accz = 0.0f;
    float accs = bias[o];
#pragma unroll
    for (int k = 0; k < DIN; k++) {
        float hv = hrow[k];
        accz = fmaf(hv, Wn[k * DOUT + o], accz);
        accs = fmaf(hv, Ws[k * DOUT + o], accs);
    }
    z[idx] = accz;
    s[idx] = accs;
}

// ---------------------------------------------------------------------------
__global__ void k_readout(const float* __restrict__ h, const int* __restrict__ gid,
                          float* __restrict__ out) {
    int v = blockIdx.x * blockDim.x + threadIdx.x;
    bool ok = (v < NN);
    int g = ok ? gid[v] : -1;
    float c = ok ? 1.0f : 0.0f;
    float f0 = 0, f1 = 0, f2 = 0, f3 = 0, f4 = 0;
    if (ok) {
        const float* hr = h + (size_t)v * 5;
        f0 = hr[0]; f1 = hr[1]; f2 = hr[2]; f3 = hr[3]; f4 = hr[4];
    }
    int g0 = __shfl_sync(0xFFFFFFFFu, ok ? g : __shfl_sync(0xFFFFFFFFu, g, 0), 0);
    bool uniform = __all_sync(0xFFFFFFFFu, !ok || g == g0);
    if (uniform) {
#pragma unroll
        for (int m = 16; m > 0; m >>= 1) {
            c  += __shfl_xor_sync(0xFFFFFFFFu, c, m);
            f0 += __shfl_xor_sync(0xFFFFFFFFu, f0, m);
            f1 += __shfl_xor_sync(0xFFFFFFFFu, f1, m);
            f2 += __shfl_xor_sync(0xFFFFFFFFu, f2, m);
            f3 += __shfl_xor_sync(0xFFFFFFFFu, f3, m);
            f4 += __shfl_xor_sync(0xFFFFFFFFu, f4, m);
        }
        if ((threadIdx.x & 31) == 0 && c > 0.0f) {
            atomicAdd(&g_cnt[g0], c);
            atomicAdd(&out[g0 * 5 + 0], f0);
            atomicAdd(&out[g0 * 5 + 1], f1);
            atomicAdd(&out[g0 * 5 + 2], f2);
            atomicAdd(&out[g0 * 5 + 3], f3);
            atomicAdd(&out[g0 * 5 + 4], f4);
        }
    } else if (ok) {
        atomicAdd(&g_cnt[g], 1.0f);
        atomicAdd(&out[g * 5 + 0], f0);
        atomicAdd(&out[g * 5 + 1], f1);
        atomicAdd(&out[g * 5 + 2], f2);
        atomicAdd(&out[g * 5 + 3], f3);
        atomicAdd(&out[g * 5 + 4], f4);
    }
}

__global__ void k_final(float* __restrict__ out) {
    int i = blockIdx.x * blockDim.x + threadIdx.x;
    if (i < NG * 5) out[i] /= fmaxf(g_cnt[i / 5], 1.0f);
}

// ---------------------------------------------------------------------------
static inline int blks(long long n, int t) { return (int)((n + t - 1) / t); }

extern "C" void kernel_launch(void* const* d_in, const int* in_sizes, int n_in,
                              void* d_out, int out_size) {
    const float* feat = (const float*)d_in[0];
    const int* src = (const int*)d_in[1];
    const int* dst = (const int*)d_in[2];
    const int* gid = (const int*)d_in[3];
    const float* Ws0 = (const float*)d_in[4];
    const float* Wn0 = (const float*)d_in[5];
    const float* b0  = (const float*)d_in[6];
    const float* Ws1 = (const float*)d_in[7];
    const float* Wn1 = (const float*)d_in[8];
    const float* b1  = (const float*)d_in[9];
    const float* Ws2 = (const float*)d_in[10];
    const float* Wn2 = (const float*)d_in[11];
    const float* b2  = (const float*)d_in[12];
    const float* Ws3 = (const float*)d_in[13];
    const float* Wn3 = (const float*)d_in[14];
    const float* b3  = (const float*)d_in[15];
    float* out = (float*)d_out;

    float *bufC, *bufD, *z, *s, *cnt;
    __half *bufAh, *bufBh, *feath, *aggh, *zh;
    __half *WsT0, *WnT0, *WsT1, *WnT1, *WsT2, *WnT2;
    int *degi;
    cudaGetSymbolAddress((void**)&bufAh, g_bufAh);
    cudaGetSymbolAddress((void**)&bufBh, g_bufBh);
    cudaGetSymbolAddress((void**)&bufC, g_bufC);
    cudaGetSymbolAddress((void**)&bufD, g_bufD);
    cudaGetSymbolAddress((void**)&z, g_z);
    cudaGetSymbolAddress((void**)&s, g_s);
    cudaGetSymbolAddress((void**)&cnt, g_cnt);
    cudaGetSymbolAddress((void**)&degi, g_degi);
    cudaGetSymbolAddress((void**)&feath, g_feath);
    cudaGetSymbolAddress((void**)&aggh, g_aggh);
    cudaGetSymbolAddress((void**)&zh, g_zh);
    cudaGetSymbolAddress((void**)&WsT0, g_WsT0);
    cudaGetSymbolAddress((void**)&WnT0, g_WnT0);
    cudaGetSymbolAddress((void**)&WsT1, g_WsT1);
    cudaGetSymbolAddress((void**)&WnT1, g_WnT1);
    cudaGetSymbolAddress((void**)&WsT2, g_WsT2);
    cudaGetSymbolAddress((void**)&WnT2, g_WnT2);

    const int T = 256;

    // ---- input conversions (independent of CSR) ----
    k_cvtfeat<<<blks((long long)NN * 8, T), T>>>(feat, feath);
    {
        int totW = 2 * (128 * 32) + 2 * (48 * 128) + 2 * (32 * 48);
        k_cvtAllW<<<blks(totW, T), T>>>(Ws0, Wn0, Ws1, Wn1, Ws2, Wn2);
    }

    // ---- CSR build (single atomic pass + atomic-free fill) ----
    cudaMemsetAsync(degi, 0, NN * sizeof(int));
    k_degrank<<<blks(NE, T), T>>>(dst);
    k_scan1<<<NB, 1024>>>();
    k_scan2<<<1, 256>>>();
    k_scan3<<<NB, 1024>>>();
    k_build<<<blks(NE, T), T>>>(src, dst);

    // ---- layer 0: gather (fp16 out) + tensor-core dual projection ----
    k_gather32H<<<blks((long long)NN * 32, T), T>>>(feath, aggh);
    k_mma_sage0<<<blks((long long)(NN / 16) * 32, T), T>>>(feath, aggh, WsT0, WnT0, b0, bufAh);

    // ---- layer 1: tensor-core zs + fused gather (fp16 out) ----
    k_mma_zs1<<<blks((long long)(NN / 16) * 32, T), T>>>(bufAh, WnT1, WsT1, b1, zh, s);
    k_gatherHh<48, 4, true><<<blks((long long)NN * 32, T), T>>>(zh, s, bufBh);

    // ---- layer 2: tensor-core zs (48->28, padded) + fused gather ----
    k_mma_zs2<<<blks((long long)(NN / 16) * 32, T), T>>>(bufBh, WnT2, WsT2, b2, zh, s);
    k_gatherH2<28, 4, true><<<blks((long long)NN * 32, T), T>>>(zh, s, bufC);

    // ---- layer 3: 28 -> 5, linear (fp32) ----
    k_zsS<28, 5><<<blks((long long)NN * 5, T), T>>>(bufC, Wn3, Ws3, b3, z, s);
    k_gatherF5<<<blks((long long)NN * 32, T), T>>>(z, s, bufD);

    // ---- readout ----
    cudaMemsetAsync(out, 0, NG * 5 * sizeof(float));
    cudaMemsetAsync(cnt, 0, NG * sizeof(float));
    k_readout<<<blks(NN, T), T>>>(bufD, gid, out);
    k_final<<<blks(NG * 5, T), T>>>(out);
}